// round 2
// baseline (speedup 1.0000x reference)
#include <cuda_runtime.h>
#include <cuda_bf16.h>

// ---------------- problem constants ----------------
// B=4, S=2048, D=4096, T=256, W=32, H=8, DH=512
#define DB   4
#define DS   2048
#define DD   4096
#define DT   256
#define DW   32
#define DH_  512
#define NH   8
#define NTOK (DB*DS)            // 8192
#define NQ   (DB*DT)            // 1024
#define SCL  0.044194173824159216f  // 1/sqrt(512)

// ---------------- device scratch (no allocations allowed) ----------------
__device__ float g_qkv [ (long)NTOK * 3 * DD ];   // 8192 x 12288
__device__ float g_attnl[ (long)NTOK * DD ];      // 8192 x 4096
__device__ float g_y   [ (long)NTOK * DD ];
__device__ float g_ln  [ (long)NTOK * DD ];
__device__ float g_lf  [ (long)NTOK * DD ];
__device__ float g_qg  [ (long)DT * DD ];         // 256 x 4096 (batch-invariant)
__device__ float g_kvg [ (long)NTOK * 2 * DD ];   // 8192 x 8192
__device__ float g_sc  [ (long)DB * NH * DT * DS ]; // 32 x 256 x 2048
__device__ float g_ag  [ (long)NQ * DD ];         // 1024 x 4096
__device__ float g_yg  [ (long)NQ * DD ];
__device__ float g_lng [ (long)NQ * DD ];

// ---------------- reductions ----------------
__device__ __forceinline__ float blockSum(float val) {
    __shared__ float sh[32];
    int lane = threadIdx.x & 31, w = threadIdx.x >> 5;
    #pragma unroll
    for (int o = 16; o; o >>= 1) val += __shfl_xor_sync(0xffffffffu, val, o);
    __syncthreads();                    // protect sh reuse across calls
    if (lane == 0) sh[w] = val;
    __syncthreads();
    val = (lane < 8) ? sh[lane] : 0.f;  // 8 warps / block
    #pragma unroll
    for (int o = 4; o; o >>= 1) val += __shfl_xor_sync(0xffffffffu, val, o);
    return __shfl_sync(0xffffffffu, val, 0);
}

__device__ __forceinline__ float blockMax(float val) {
    __shared__ float sh[32];
    int lane = threadIdx.x & 31, w = threadIdx.x >> 5;
    #pragma unroll
    for (int o = 16; o; o >>= 1) val = fmaxf(val, __shfl_xor_sync(0xffffffffu, val, o));
    __syncthreads();
    if (lane == 0) sh[w] = val;
    __syncthreads();
    val = (lane < 8) ? sh[lane] : -3.4e38f;
    #pragma unroll
    for (int o = 4; o; o >>= 1) val = fmaxf(val, __shfl_xor_sync(0xffffffffu, val, o));
    return __shfl_sync(0xffffffffu, val, 0);
}

// ---------------- SGEMM: C = scale * (A @ B^T) [+bias] [+residual] ----------------
// A: (M,K) rows stride lda ; B: (N,K) rows stride ldb ; C: (M,N) stride ldc.
// Batched via blockIdx.z: z -> (zi = z % zInner, zo = z / zInner), pointer offsets.
// All M,N divisible by 128; K divisible by 16 (holds for every call here).
__global__ __launch_bounds__(256) void gemm_abt(
    const float* __restrict__ A, int lda,
    const float* __restrict__ B, int ldb,
    float*       __restrict__ C, int ldc,
    const float* __restrict__ bias,
    const float* __restrict__ res, int resMod, int resLd,
    int K, float scale,
    int zInner, long aIn, long aOut, long bIn, long bOut, long cIn, long cOut)
{
    const int z = blockIdx.z;
    const int zi = z % zInner, zo = z / zInner;
    A += (long)zi * aIn + (long)zo * aOut;
    B += (long)zi * bIn + (long)zo * bOut;
    C += (long)zi * cIn + (long)zo * cOut;

    const int bm = blockIdx.y * 128;
    const int bn = blockIdx.x * 128;
    __shared__ float As[16][132];
    __shared__ float Bs[16][132];
    const int tid = threadIdx.x;
    const int tm = (tid >> 4) * 8;
    const int tn = (tid & 15) * 8;
    float acc[8][8] = {};

    for (int k0 = 0; k0 < K; k0 += 16) {
        #pragma unroll
        for (int i = 0; i < 2; i++) {
            int l = tid + i * 256;            // 0..511
            int r = l >> 2;                   // row 0..127
            int c = (l & 3) * 4;              // k 0,4,8,12
            float4 va = *(const float4*)(A + (long)(bm + r) * lda + k0 + c);
            As[c+0][r] = va.x; As[c+1][r] = va.y; As[c+2][r] = va.z; As[c+3][r] = va.w;
            float4 vb = *(const float4*)(B + (long)(bn + r) * ldb + k0 + c);
            Bs[c+0][r] = vb.x; Bs[c+1][r] = vb.y; Bs[c+2][r] = vb.z; Bs[c+3][r] = vb.w;
        }
        __syncthreads();
        #pragma unroll
        for (int k = 0; k < 16; k++) {
            float4 a0 = *(const float4*)&As[k][tm];
            float4 a1 = *(const float4*)&As[k][tm + 4];
            float4 b0 = *(const float4*)&Bs[k][tn];
            float4 b1 = *(const float4*)&Bs[k][tn + 4];
            float a[8] = {a0.x,a0.y,a0.z,a0.w,a1.x,a1.y,a1.z,a1.w};
            float b[8] = {b0.x,b0.y,b0.z,b0.w,b1.x,b1.y,b1.z,b1.w};
            #pragma unroll
            for (int i = 0; i < 8; i++)
                #pragma unroll
                for (int j = 0; j < 8; j++)
                    acc[i][j] += a[i] * b[j];
        }
        __syncthreads();
    }

    #pragma unroll
    for (int i = 0; i < 8; i++) {
        const int row = bm + tm + i;
        #pragma unroll
        for (int j = 0; j < 8; j++) {
            const int col = bn + tn + j;
            float v = acc[i][j] * scale;
            if (bias) v += bias[col];
            if (res)  v += res[(long)(row % resMod) * resLd + col];
            C[(long)row * ldc + col] = v;
        }
    }
}

// ---------------- SGEMM: C = A @ B  (B is (K,N) row-major, stride ldb) ----------------
__global__ __launch_bounds__(256) void gemm_ab(
    const float* __restrict__ A, int lda,
    const float* __restrict__ B, int ldb,
    float*       __restrict__ C, int ldc,
    int K,
    int zInner, long aIn, long aOut, long bIn, long bOut, long cIn, long cOut)
{
    const int z = blockIdx.z;
    const int zi = z % zInner, zo = z / zInner;
    A += (long)zi * aIn + (long)zo * aOut;
    B += (long)zi * bIn + (long)zo * bOut;
    C += (long)zi * cIn + (long)zo * cOut;

    const int bm = blockIdx.y * 128;
    const int bn = blockIdx.x * 128;
    __shared__ float As[16][132];
    __shared__ float Bs[16][132];
    const int tid = threadIdx.x;
    const int tm = (tid >> 4) * 8;
    const int tn = (tid & 15) * 8;
    float acc[8][8] = {};

    for (int k0 = 0; k0 < K; k0 += 16) {
        #pragma unroll
        for (int i = 0; i < 2; i++) {
            int l = tid + i * 256;
            int r = l >> 2;
            int c = (l & 3) * 4;
            float4 va = *(const float4*)(A + (long)(bm + r) * lda + k0 + c);
            As[c+0][r] = va.x; As[c+1][r] = va.y; As[c+2][r] = va.z; As[c+3][r] = va.w;
            int kk = l >> 5;                 // 0..15
            int n4 = (l & 31) * 4;           // 0..124
            float4 vb = *(const float4*)(B + (long)(k0 + kk) * ldb + bn + n4);
            Bs[kk][n4+0] = vb.x; Bs[kk][n4+1] = vb.y; Bs[kk][n4+2] = vb.z; Bs[kk][n4+3] = vb.w;
        }
        __syncthreads();
        #pragma unroll
        for (int k = 0; k < 16; k++) {
            float4 a0 = *(const float4*)&As[k][tm];
            float4 a1 = *(const float4*)&As[k][tm + 4];
            float4 b0 = *(const float4*)&Bs[k][tn];
            float4 b1 = *(const float4*)&Bs[k][tn + 4];
            float a[8] = {a0.x,a0.y,a0.z,a0.w,a1.x,a1.y,a1.z,a1.w};
            float b[8] = {b0.x,b0.y,b0.z,b0.w,b1.x,b1.y,b1.z,b1.w};
            #pragma unroll
            for (int i = 0; i < 8; i++)
                #pragma unroll
                for (int j = 0; j < 8; j++)
                    acc[i][j] += a[i] * b[j];
        }
        __syncthreads();
    }

    #pragma unroll
    for (int i = 0; i < 8; i++)
        #pragma unroll
        for (int j = 0; j < 8; j++)
            C[(long)(bm + tm + i) * ldc + bn + tn + j] = acc[i][j];
}

// ---------------- local windowed attention (one block per (window, head)) ----------------
// qkv: (8192, 12288) = [q | k | v]. out: (8192, 4096), head-major within row.
// mask passed as int32 (bool converted by harness); nonzero bits == valid (also
// correct if it arrives as float32 1.0/0.0).
__global__ __launch_bounds__(256) void local_attn(
    const float* __restrict__ qkv, const int* __restrict__ mask,
    float* __restrict__ out)
{
    const int  bw   = blockIdx.x;          // 0..255 window (batch-flattened)
    const int  h    = blockIdx.y;          // 0..7 head
    const long tok0 = (long)bw * DW;
    const int  LD   = 3 * DD;              // 12288
    const float* qb = qkv + tok0 * LD + h * DH_;
    const float* kb = qkv + tok0 * LD + DD + h * DH_;
    const float* vb = qkv + tok0 * LD + 2 * DD + h * DH_;

    __shared__ float s[DW][DW + 1];
    __shared__ float msk[DW];
    const int tid = threadIdx.x;

    if (tid < DW) msk[tid] = (mask[tok0 + tid] != 0) ? 0.f : -1e9f;

    // scores: 1024 (i,j) dots of length 512
    #pragma unroll
    for (int p = tid; p < DW * DW; p += 256) {
        int i = p >> 5, j = p & 31;
        const float4* qp = (const float4*)(qb + (long)i * LD);
        const float4* kp = (const float4*)(kb + (long)j * LD);
        float acc = 0.f;
        #pragma unroll 8
        for (int d = 0; d < DH_ / 4; d++) {
            float4 a = qp[d], c = kp[d];
            acc += a.x * c.x + a.y * c.y + a.z * c.z + a.w * c.w;
        }
        s[i][j] = acc;
    }
    __syncthreads();

    // softmax rows (thread i < 32 owns row i) — replicates ref: s*scale + bias, exp(x-max)
    if (tid < DW) {
        const int i = tid;
        const float mi = msk[i];
        float r[DW];
        float mx = -3.4e38f;
        #pragma unroll
        for (int j = 0; j < DW; j++) {
            float bias = (mi + msk[j] < -0.5f) ? -1e9f : 0.f;
            r[j] = s[i][j] * SCL + bias;
            mx = fmaxf(mx, r[j]);
        }
        float sum = 0.f;
        #pragma unroll
        for (int j = 0; j < DW; j++) { r[j] = expf(r[j] - mx); sum += r[j]; }
        const float inv = 1.f / sum;
        #pragma unroll
        for (int j = 0; j < DW; j++) s[i][j] = r[j] * inv;
    }
    __syncthreads();

    // out[i, d] = sum_j s[i][j] * v[j][d]; each thread owns 2 d-columns, v read once
    float2 acc[DW];
    #pragma unroll
    for (int i = 0; i < DW; i++) acc[i] = make_float2(0.f, 0.f);
    for (int j = 0; j < DW; j++) {
        float2 v2 = *(const float2*)(vb + (long)j * LD + tid * 2);
        #pragma unroll
        for (int i = 0; i < DW; i++) {
            float w = s[i][j];
            acc[i].x += w * v2.x;
            acc[i].y += w * v2.y;
        }
    }
    float* ob = out + tok0 * DD + h * DH_ + tid * 2;
    #pragma unroll
    for (int i = 0; i < DW; i++)
        *(float2*)(ob + (long)i * DD) = acc[i];
}

// ---------------- LayerNorm over rows of 4096 ----------------
__global__ __launch_bounds__(256) void layernorm_k(
    const float* __restrict__ X, const float* __restrict__ g,
    const float* __restrict__ b, float* __restrict__ Y)
{
    const long row = blockIdx.x;
    const float* x = X + row * DD;
    float v[16];
    float s = 0.f;
    #pragma unroll
    for (int i = 0; i < 16; i++) { v[i] = x[threadIdx.x + i * 256]; s += v[i]; }
    const float mean = blockSum(s) * (1.f / DD);
    float d2 = 0.f;
    #pragma unroll
    for (int i = 0; i < 16; i++) { float d = v[i] - mean; d2 += d * d; }
    const float var = blockSum(d2) * (1.f / DD);
    const float rs = rsqrtf(var + 1e-5f);
    #pragma unroll
    for (int i = 0; i < 16; i++) {
        int c = threadIdx.x + i * 256;
        Y[row * DD + c] = (v[i] - mean) * rs * g[c] + b[c];
    }
}

// ---------------- global softmax over S=2048 keys (row per (b,h,t)) ----------------
__global__ __launch_bounds__(256) void softmax_g(
    float* __restrict__ sc, const int* __restrict__ mask)
{
    const long row = blockIdx.x;              // 0..8191, ordered (b,h,t)
    const int  b   = (int)(row >> 11);        // / (H*T)
    float* x = sc + row * DS;
    const int* m = mask + (long)b * DS;
    float v[8];
    float mx = -3.4e38f;
    #pragma unroll
    for (int i = 0; i < 8; i++) {
        int c = threadIdx.x + i * 256;
        float t = x[c] + ((m[c] != 0) ? 0.f : -1e9f);
        v[i] = t;
        mx = fmaxf(mx, t);
    }
    mx = blockMax(mx);
    float s = 0.f;
    #pragma unroll
    for (int i = 0; i < 8; i++) { v[i] = expf(v[i] - mx); s += v[i]; }
    s = blockSum(s);
    const float inv = 1.f / s;
    #pragma unroll
    for (int i = 0; i < 8; i++) x[threadIdx.x + i * 256] = v[i] * inv;
}

// ---------------- launch ----------------
extern "C" void kernel_launch(void* const* d_in, const int* in_sizes, int n_in,
                              void* d_out, int out_size)
{
    const float*         vlm       = (const float*)d_in[0];
    const int*           mask      = (const int*)d_in[1];
    const float*         l_in_w    = (const float*)d_in[2];
    const float*         l_in_b    = (const float*)d_in[3];
    const float*         l_out_w   = (const float*)d_in[4];
    const float*         l_out_b   = (const float*)d_in[5];
    const float*         l_ng      = (const float*)d_in[6];
    const float*         l_nb      = (const float*)d_in[7];
    const float*         l_pw      = (const float*)d_in[8];
    const float*         l_pb      = (const float*)d_in[9];
    const float*         g_in_w    = (const float*)d_in[10];
    const float*         g_in_b    = (const float*)d_in[11];
    const float*         g_out_w   = (const float*)d_in[12];
    const float*         g_out_b   = (const float*)d_in[13];
    const float*         g_ng      = (const float*)d_in[14];
    const float*         g_nb      = (const float*)d_in[15];
    const float*         qtok      = (const float*)d_in[16];
    const float*         o_pw      = (const float*)d_in[17];
    const float*         o_pb      = (const float*)d_in[18];
    float* out = (float*)d_out;

    float *p_qkv, *p_attnl, *p_y, *p_ln, *p_lf, *p_qg, *p_kvg, *p_sc, *p_ag, *p_yg, *p_lng;
    cudaGetSymbolAddress((void**)&p_qkv,   g_qkv);
    cudaGetSymbolAddress((void**)&p_attnl, g_attnl);
    cudaGetSymbolAddress((void**)&p_y,     g_y);
    cudaGetSymbolAddress((void**)&p_ln,    g_ln);
    cudaGetSymbolAddress((void**)&p_lf,    g_lf);
    cudaGetSymbolAddress((void**)&p_qg,    g_qg);
    cudaGetSymbolAddress((void**)&p_kvg,   g_kvg);
    cudaGetSymbolAddress((void**)&p_sc,    g_sc);
    cudaGetSymbolAddress((void**)&p_ag,    g_ag);
    cudaGetSymbolAddress((void**)&p_yg,    g_yg);
    cudaGetSymbolAddress((void**)&p_lng,   g_lng);

    const dim3 T256(256);

    // 1) local QKV: (8192 x 12288) = vlm @ local_in_w^T + b
    gemm_abt<<<dim3(3*DD/128, NTOK/128, 1), T256>>>(
        vlm, DD, l_in_w, DD, p_qkv, 3*DD, l_in_b,
        nullptr, 1, 1, DD, 1.f, 1, 0,0,0,0,0,0);

    // 2) local windowed attention
    local_attn<<<dim3(DB * (DS / DW), NH), T256>>>(p_qkv, mask, p_attnl);

    // 3) local out_proj + residual(vlm)
    gemm_abt<<<dim3(DD/128, NTOK/128, 1), T256>>>(
        p_attnl, DD, l_out_w, DD, p_y, DD, l_out_b,
        vlm, NTOK, DD, DD, 1.f, 1, 0,0,0,0,0,0);

    // 4) LN local
    layernorm_k<<<NTOK, T256>>>(p_y, l_ng, l_nb, p_ln);

    // 5) local_proj -> local_features
    gemm_abt<<<dim3(DD/128, NTOK/128, 1), T256>>>(
        p_ln, DD, l_pw, DD, p_lf, DD, l_pb,
        nullptr, 1, 1, DD, 1.f, 1, 0,0,0,0,0,0);

    // 6) global q (batch-invariant: compute once for 256 query tokens)
    gemm_abt<<<dim3(DD/128, DT/128, 1), T256>>>(
        qtok, DD, g_in_w, DD, p_qg, DD, g_in_b,
        nullptr, 1, 1, DD, 1.f, 1, 0,0,0,0,0,0);

    // 7) global k,v: (8192 x 8192) = lf @ [Wk;Wv]^T
    gemm_abt<<<dim3(2*DD/128, NTOK/128, 1), T256>>>(
        p_lf, DD, g_in_w + (long)DD * DD, DD, p_kvg, 2*DD, g_in_b + DD,
        nullptr, 1, 1, DD, 1.f, 1, 0,0,0,0,0,0);

    // 8) scores (batched 32 = B*H): (256 x 2048 x 512), scaled
    gemm_abt<<<dim3(DS/128, DT/128, DB*NH), T256>>>(
        p_qg, DD, p_kvg, 2*DD, p_sc, DS, nullptr, nullptr, 1, 1,
        DH_, SCL,
        NH, /*aIn*/DH_, /*aOut*/0,
            /*bIn*/DH_, /*bOut*/(long)DS * 2 * DD,
            /*cIn*/(long)DT * DS, /*cOut*/(long)NH * DT * DS);

    // 9) softmax over keys with padding mask
    softmax_g<<<DB * NH * DT, T256>>>(p_sc, mask);

    // 10) AV (batched 32): (256 x 512 x 2048)
    gemm_ab<<<dim3(DH_/128, DT/128, DB*NH), T256>>>(
        p_sc, DS, p_kvg + DD, 2*DD, p_ag, DD,
        DS,
        NH, /*aIn*/(long)DT * DS, /*aOut*/(long)NH * DT * DS,
            /*bIn*/DH_, /*bOut*/(long)DS * 2 * DD,
            /*cIn*/DH_, /*cOut*/(long)DT * DD);

    // 11) global out_proj + residual(query_tokens, broadcast over batch)
    gemm_abt<<<dim3(DD/128, NQ/128, 1), T256>>>(
        p_ag, DD, g_out_w, DD, p_yg, DD, g_out_b,
        qtok, DT, DD, DD, 1.f, 1, 0,0,0,0,0,0);

    // 12) LN global
    layernorm_k<<<NQ, T256>>>(p_yg, g_ng, g_nb, p_lng);

    // 13) output_proj -> d_out
    gemm_abt<<<dim3(DD/128, NQ/128, 1), T256>>>(
        p_lng, DD, o_pw, DD, out, DD, o_pb,
        nullptr, 1, 1, DD, 1.f, 1, 0,0,0,0,0,0);
}

// round 4
// speedup vs baseline: 2.0504x; 2.0504x over previous
#include <cuda_runtime.h>
#include <cuda_bf16.h>
#include <cstdint>

// ---------------- problem constants ----------------
// B=4, S=2048, D=4096, T=256, W=32, H=8, DH=512
#define DB   4
#define DS   2048
#define DD   4096
#define DT   256
#define DW   32
#define DH_  512
#define NH   8
#define NTOK (DB*DS)            // 8192
#define NQ   (DB*DT)            // 1024
#define SCL  0.044194173824159216f  // 1/sqrt(512)

typedef __nv_bfloat16 bf16;

// ---------------- device scratch (no allocations allowed) ----------------
// fp32 intermediates
__device__ float g_qkv  [ (long)NTOK * 3 * DD ];
__device__ float g_attnl[ (long)NTOK * DD ];
__device__ float g_y    [ (long)NTOK * DD ];
__device__ float g_ln   [ (long)NTOK * DD ];
__device__ float g_lf   [ (long)NTOK * DD ];
__device__ float g_qg   [ (long)DT * DD ];
__device__ float g_kvg  [ (long)NTOK * 2 * DD ];
__device__ float g_sc   [ (long)DB * NH * DT * DS ];
__device__ float g_ag   [ (long)NQ * DD ];
__device__ float g_yg   [ (long)NQ * DD ];
__device__ float g_lng  [ (long)NQ * DD ];
// bf16 split operands (hi / lo), 16B-aligned for cp.async
__device__ __align__(16) bf16 b_vlm_h  [(long)NTOK*DD],      b_vlm_l  [(long)NTOK*DD];
__device__ __align__(16) bf16 b_liw_h  [(long)3*DD*DD],      b_liw_l  [(long)3*DD*DD];
__device__ __align__(16) bf16 b_low_h  [(long)DD*DD],        b_low_l  [(long)DD*DD];
__device__ __align__(16) bf16 b_lpw_h  [(long)DD*DD],        b_lpw_l  [(long)DD*DD];
__device__ __align__(16) bf16 b_giw_h  [(long)3*DD*DD],      b_giw_l  [(long)3*DD*DD];
__device__ __align__(16) bf16 b_gow_h  [(long)DD*DD],        b_gow_l  [(long)DD*DD];
__device__ __align__(16) bf16 b_opw_h  [(long)DD*DD],        b_opw_l  [(long)DD*DD];
__device__ __align__(16) bf16 b_attnl_h[(long)NTOK*DD],      b_attnl_l[(long)NTOK*DD];
__device__ __align__(16) bf16 b_ln_h   [(long)NTOK*DD],      b_ln_l   [(long)NTOK*DD];
__device__ __align__(16) bf16 b_lf_h   [(long)NTOK*DD],      b_lf_l   [(long)NTOK*DD];
__device__ __align__(16) bf16 b_qtok_h [(long)DT*DD],        b_qtok_l [(long)DT*DD];
__device__ __align__(16) bf16 b_qg_h   [(long)DT*DD],        b_qg_l   [(long)DT*DD];
__device__ __align__(16) bf16 b_kvk_h  [(long)NTOK*DD],      b_kvk_l  [(long)NTOK*DD];   // K half, ld=4096
__device__ __align__(16) bf16 b_vt_h   [(long)DB*DD*DS],     b_vt_l   [(long)DB*DD*DS];  // V^T: [(b*4096+d)*2048+s]
__device__ __align__(16) bf16 b_sc_h   [(long)DB*NH*DT*DS],  b_sc_l   [(long)DB*NH*DT*DS];
__device__ __align__(16) bf16 b_ag_h   [(long)NQ*DD],        b_ag_l   [(long)NQ*DD];
__device__ __align__(16) bf16 b_lng_h  [(long)NQ*DD],        b_lng_l  [(long)NQ*DD];

// ======================= helpers =======================
__device__ __forceinline__ uint32_t smem_u32(const void* p) {
    uint32_t a;
    asm("{ .reg .u64 t; cvta.to.shared.u64 t, %1; cvt.u32.u64 %0, t; }" : "=r"(a) : "l"(p));
    return a;
}
__device__ __forceinline__ void cp16(uint32_t dst, const void* src) {
    asm volatile("cp.async.cg.shared.global [%0], [%1], 16;" :: "r"(dst), "l"(src));
}
__device__ __forceinline__ void cp_commit() { asm volatile("cp.async.commit_group;" ::: "memory"); }
template <int N> __device__ __forceinline__ void cp_wait() {
    asm volatile("cp.async.wait_group %0;" :: "n"(N) : "memory");
}
__device__ __forceinline__ void ldsm4(uint32_t* r, uint32_t a) {
    asm volatile("ldmatrix.sync.aligned.m8n8.x4.shared.b16 {%0,%1,%2,%3}, [%4];"
        : "=r"(r[0]), "=r"(r[1]), "=r"(r[2]), "=r"(r[3]) : "r"(a));
}
// D += A*B  (m16n8k16, bf16 in, fp32 acc)
__device__ __forceinline__ void mma16816(float* d, const uint32_t* a, const uint32_t* b) {
    asm volatile(
        "mma.sync.aligned.m16n8k16.row.col.f32.bf16.bf16.f32 "
        "{%0,%1,%2,%3}, {%4,%5,%6,%7}, {%8,%9}, {%0,%1,%2,%3};"
        : "+f"(d[0]), "+f"(d[1]), "+f"(d[2]), "+f"(d[3])
        : "r"(a[0]), "r"(a[1]), "r"(a[2]), "r"(a[3]), "r"(b[0]), "r"(b[1]));
}

// ======================= split-bf16 HMMA GEMM =======================
// C(M,N) = scale * (Ah+Al)(Bh+Bl)^T [3-product] + bias + res
// A: (M,K) ld=lda ; B: (N,K) ld=ldb ; 128x128 tile, K-chunk 32, 2-stage cp.async.
// smem/stage (40960B): Ah[128][40] Al Bh[128][40] Bl  (40 bf16 = 80B padded rows)
#define GSTG  40960
#define GSMEM (2*GSTG)

__device__ __forceinline__ void load_chunk(
    uint32_t sb, int stage, long k0, int tid,
    const bf16* __restrict__ Ah, const bf16* __restrict__ Al, long lda, long bm,
    const bf16* __restrict__ Bh, const bf16* __restrict__ Bl, long ldb, long bn)
{
    uint32_t base = sb + (uint32_t)stage * GSTG;
    #pragma unroll
    for (int it = 0; it < 2; it++) {
        int u = tid + it * 256;            // 0..511
        int r = u >> 2, c = u & 3;         // row 0..127, 16B-col 0..3
        uint32_t off = (uint32_t)(r * 80 + c * 16);
        long srcA = (bm + r) * lda + k0 + c * 8;
        cp16(base + off,         Ah + srcA);
        cp16(base + 10240 + off, Al + srcA);
        long srcB = (bn + r) * ldb + k0 + c * 8;
        cp16(base + 20480 + off, Bh + srcB);
        cp16(base + 30720 + off, Bl + srcB);
    }
    cp_commit();
}

__global__ __launch_bounds__(256) void gemm_tc(
    const bf16* __restrict__ Ah, const bf16* __restrict__ Al, long lda,
    const bf16* __restrict__ Bh, const bf16* __restrict__ Bl, long ldb,
    float* __restrict__ C, long ldc,
    const float* __restrict__ bias,
    const float* __restrict__ res, int resMod, long resLd,
    int K, float scale, int nTm, int nTn,
    int zInner, long aIn, long aOut, long bIn, long bOut, long cIn, long cOut)
{
    extern __shared__ __align__(128) char smem[];
    const uint32_t sb = smem_u32(smem);
    const int tid = threadIdx.x;
    const int wid = tid >> 5;
    const int lane = tid & 31;

    const int z = blockIdx.z;
    const int zi = z % zInner, zo = z / zInner;
    Ah += (long)zi * aIn + (long)zo * aOut;  Al += (long)zi * aIn + (long)zo * aOut;
    Bh += (long)zi * bIn + (long)zo * bOut;  Bl += (long)zi * bIn + (long)zo * bOut;
    C  += (long)zi * cIn + (long)zo * cOut;

    // L2-friendly rasterization: bands of 8 N-tiles
    const int idx = blockIdx.x;
    const int per = nTm * 8;
    const int band = idx / per, rem = idx % per;
    const long bm = (long)(rem % nTm) * 128;
    const long bn = (long)(band * 8 + rem / nTm) * 128;

    // warp layout: 4(M) x 2(N); warp tile 32x64
    const int wm = wid & 3;
    const int wn = wid >> 2;

    // ldmatrix base addresses (stage 0)
    // A/B fragment: non-trans x4; lanes 0-15 -> rows, lanes 16-31 -> +8 k-offset
    const uint32_t aBase = sb +
        (uint32_t)((wm * 32 + (lane & 15)) * 80 + ((lane >> 4) * 8) * 2);
    const uint32_t bBase = sb + 20480u +
        (uint32_t)((wn * 64 + (lane & 7) + ((lane >> 4) & 1) * 8) * 80 +
                   (((lane >> 3) & 1) * 8) * 2);

    float acc[2][8][4];
    #pragma unroll
    for (int i = 0; i < 2; i++)
        #pragma unroll
        for (int j = 0; j < 8; j++)
            #pragma unroll
            for (int q = 0; q < 4; q++) acc[i][j][q] = 0.f;

    const int nCh = K >> 5;
    load_chunk(sb, 0, 0,  tid, Ah, Al, lda, bm, Bh, Bl, ldb, bn);
    load_chunk(sb, 1, 32, tid, Ah, Al, lda, bm, Bh, Bl, ldb, bn);

    for (int i = 0; i < nCh; i++) {
        if (i + 1 < nCh) cp_wait<1>(); else cp_wait<0>();
        __syncthreads();
        const uint32_t stg = (uint32_t)(i & 1) * GSTG;
        #pragma unroll
        for (int ks = 0; ks < 2; ks++) {
            uint32_t ah[2][4], al[2][4], bh[4][4], bl[4][4];
            #pragma unroll
            for (int m = 0; m < 2; m++) {
                uint32_t a = aBase + stg + (uint32_t)(m * 1280 + ks * 32);
                ldsm4(ah[m], a);
                ldsm4(al[m], a + 10240);
            }
            #pragma unroll
            for (int p = 0; p < 4; p++) {
                uint32_t a = bBase + stg + (uint32_t)(p * 1280 + ks * 32);
                ldsm4(bh[p], a);
                ldsm4(bl[p], a + 10240);
            }
            #pragma unroll
            for (int m = 0; m < 2; m++)
                #pragma unroll
                for (int nt = 0; nt < 8; nt++) {
                    const uint32_t* BH = &bh[nt >> 1][(nt & 1) * 2];
                    const uint32_t* BL = &bl[nt >> 1][(nt & 1) * 2];
                    mma16816(acc[m][nt], ah[m], BH);
                    mma16816(acc[m][nt], al[m], BH);
                    mma16816(acc[m][nt], ah[m], BL);
                }
        }
        __syncthreads();
        if (i + 2 < nCh)
            load_chunk(sb, i & 1, (long)(i + 2) * 32, tid, Ah, Al, lda, bm, Bh, Bl, ldb, bn);
    }

    // ---- epilogue: direct float2 stores, fused scale/bias/residual ----
    const int r0 = lane >> 2;
    const int c0 = (lane & 3) * 2;
    #pragma unroll
    for (int m = 0; m < 2; m++) {
        #pragma unroll
        for (int half = 0; half < 2; half++) {
            const long grow = bm + wm * 32 + m * 16 + r0 + half * 8;
            const long rrow = (grow % resMod) * resLd;
            #pragma unroll
            for (int nt = 0; nt < 8; nt++) {
                const long gcol = bn + wn * 64 + nt * 8 + c0;
                float vx = acc[m][nt][half * 2]     * scale;
                float vy = acc[m][nt][half * 2 + 1] * scale;
                if (bias) {
                    float2 bb = *(const float2*)&bias[gcol];
                    vx += bb.x; vy += bb.y;
                }
                if (res) {
                    float2 rr = *(const float2*)&res[rrow + gcol];
                    vx += rr.x; vy += rr.y;
                }
                float2 v; v.x = vx; v.y = vy;
                *(float2*)&C[grow * ldc + gcol] = v;
            }
        }
    }
}

// ======================= split / transpose conversions =======================
__global__ __launch_bounds__(256) void split_mat(
    const float* __restrict__ in, long ldIn,
    bf16* __restrict__ oh, bf16* __restrict__ ol, long ldOut,
    int cols4, long total4)
{
    long idx = (long)blockIdx.x * 256 + threadIdx.x;
    if (idx >= total4) return;
    long r = idx / cols4;
    int  c = (int)(idx - r * cols4);
    float4 v = *(const float4*)(in + r * ldIn + c * 4);
    bf16 h0 = __float2bfloat16(v.x), h1 = __float2bfloat16(v.y);
    bf16 h2 = __float2bfloat16(v.z), h3 = __float2bfloat16(v.w);
    bf16 l0 = __float2bfloat16(v.x - __bfloat162float(h0));
    bf16 l1 = __float2bfloat16(v.y - __bfloat162float(h1));
    bf16 l2 = __float2bfloat16(v.z - __bfloat162float(h2));
    bf16 l3 = __float2bfloat16(v.w - __bfloat162float(h3));
    __nv_bfloat162* ph = (__nv_bfloat162*)(oh + r * ldOut + c * 4);
    __nv_bfloat162* pl = (__nv_bfloat162*)(ol + r * ldOut + c * 4);
    __nv_bfloat162 a; a.x = h0; a.y = h1; ph[0] = a;
    a.x = h2; a.y = h3; ph[1] = a;
    a.x = l0; a.y = l1; pl[0] = a;
    a.x = l2; a.y = l3; pl[1] = a;
}

// V part of kvg (cols 4096..8191) -> transposed split: vt[(b*4096+d)*2048 + s]
__global__ __launch_bounds__(256) void vtrans_split(
    const float* __restrict__ kvg, bf16* __restrict__ vh, bf16* __restrict__ vl)
{
    __shared__ float tile[32][33];
    const int s0 = blockIdx.x * 32, d0 = blockIdx.y * 32, b = blockIdx.z;
    const int tx = threadIdx.x & 31, ty = threadIdx.x >> 5;   // (32, 8)
    #pragma unroll
    for (int j = 0; j < 4; j++) {
        int s = s0 + ty + j * 8;
        tile[ty + j * 8][tx] = kvg[((long)b * DS + s) * (2 * DD) + DD + d0 + tx];
    }
    __syncthreads();
    #pragma unroll
    for (int j = 0; j < 4; j++) {
        int d = d0 + ty + j * 8;
        float v = tile[tx][ty + j * 8];
        bf16 h = __float2bfloat16(v);
        bf16 l = __float2bfloat16(v - __bfloat162float(h));
        long o = ((long)b * DD + d) * DS + s0 + tx;
        vh[o] = h; vl[o] = l;
    }
}

// ======================= reductions / small kernels =======================
__device__ __forceinline__ float blockSum(float val) {
    __shared__ float sh[32];
    int lane = threadIdx.x & 31, w = threadIdx.x >> 5;
    #pragma unroll
    for (int o = 16; o; o >>= 1) val += __shfl_xor_sync(0xffffffffu, val, o);
    __syncthreads();
    if (lane == 0) sh[w] = val;
    __syncthreads();
    val = (lane < 8) ? sh[lane] : 0.f;
    #pragma unroll
    for (int o = 4; o; o >>= 1) val += __shfl_xor_sync(0xffffffffu, val, o);
    return __shfl_sync(0xffffffffu, val, 0);
}
__device__ __forceinline__ float blockMax(float val) {
    __shared__ float sh[32];
    int lane = threadIdx.x & 31, w = threadIdx.x >> 5;
    #pragma unroll
    for (int o = 16; o; o >>= 1) val = fmaxf(val, __shfl_xor_sync(0xffffffffu, val, o));
    __syncthreads();
    if (lane == 0) sh[w] = val;
    __syncthreads();
    val = (lane < 8) ? sh[lane] : -3.4e38f;
    #pragma unroll
    for (int o = 4; o; o >>= 1) val = fmaxf(val, __shfl_xor_sync(0xffffffffu, val, o));
    return __shfl_sync(0xffffffffu, val, 0);
}

__global__ __launch_bounds__(256) void local_attn(
    const float* __restrict__ qkv, const int* __restrict__ mask,
    float* __restrict__ out)
{
    const int  bw   = blockIdx.x;
    const int  h    = blockIdx.y;
    const long tok0 = (long)bw * DW;
    const int  LD   = 3 * DD;
    const float* qb = qkv + tok0 * LD + h * DH_;
    const float* kb = qkv + tok0 * LD + DD + h * DH_;
    const float* vb = qkv + tok0 * LD + 2 * DD + h * DH_;

    __shared__ float s[DW][DW + 1];
    __shared__ float msk[DW];
    const int tid = threadIdx.x;
    if (tid < DW) msk[tid] = (mask[tok0 + tid] != 0) ? 0.f : -1e9f;

    #pragma unroll
    for (int p = tid; p < DW * DW; p += 256) {
        int i = p >> 5, j = p & 31;
        const float4* qp = (const float4*)(qb + (long)i * LD);
        const float4* kp = (const float4*)(kb + (long)j * LD);
        float acc = 0.f;
        #pragma unroll 8
        for (int d = 0; d < DH_ / 4; d++) {
            float4 a = qp[d], c = kp[d];
            acc += a.x * c.x + a.y * c.y + a.z * c.z + a.w * c.w;
        }
        s[i][j] = acc;
    }
    __syncthreads();

    if (tid < DW) {
        const int i = tid;
        const float mi = msk[i];
        float r[DW];
        float mx = -3.4e38f;
        #pragma unroll
        for (int j = 0; j < DW; j++) {
            float bias = (mi + msk[j] < -0.5f) ? -1e9f : 0.f;
            r[j] = s[i][j] * SCL + bias;
            mx = fmaxf(mx, r[j]);
        }
        float sum = 0.f;
        #pragma unroll
        for (int j = 0; j < DW; j++) { r[j] = expf(r[j] - mx); sum += r[j]; }
        const float inv = 1.f / sum;
        #pragma unroll
        for (int j = 0; j < DW; j++) s[i][j] = r[j] * inv;
    }
    __syncthreads();

    float2 acc[DW];
    #pragma unroll
    for (int i = 0; i < DW; i++) acc[i] = make_float2(0.f, 0.f);
    for (int j = 0; j < DW; j++) {
        float2 v2 = *(const float2*)(vb + (long)j * LD + tid * 2);
        #pragma unroll
        for (int i = 0; i < DW; i++) {
            float w = s[i][j];
            acc[i].x += w * v2.x;
            acc[i].y += w * v2.y;
        }
    }
    float* ob = out + tok0 * DD + h * DH_ + tid * 2;
    #pragma unroll
    for (int i = 0; i < DW; i++)
        *(float2*)(ob + (long)i * DD) = acc[i];
}

__global__ __launch_bounds__(256) void layernorm_k(
    const float* __restrict__ X, const float* __restrict__ g,
    const float* __restrict__ b, float* __restrict__ Y)
{
    const long row = blockIdx.x;
    const float* x = X + row * DD;
    float v[16];
    float s = 0.f;
    #pragma unroll
    for (int i = 0; i < 16; i++) { v[i] = x[threadIdx.x + i * 256]; s += v[i]; }
    const float mean = blockSum(s) * (1.f / DD);
    float d2 = 0.f;
    #pragma unroll
    for (int i = 0; i < 16; i++) { float d = v[i] - mean; d2 += d * d; }
    const float var = blockSum(d2) * (1.f / DD);
    const float rs = rsqrtf(var + 1e-5f);
    #pragma unroll
    for (int i = 0; i < 16; i++) {
        int c = threadIdx.x + i * 256;
        Y[row * DD + c] = (v[i] - mean) * rs * g[c] + b[c];
    }
}

__global__ __launch_bounds__(256) void softmax_g(
    float* __restrict__ sc, const int* __restrict__ mask)
{
    const long row = blockIdx.x;
    const int  b   = (int)(row >> 11);
    float* x = sc + row * DS;
    const int* m = mask + (long)b * DS;
    float v[8];
    float mx = -3.4e38f;
    #pragma unroll
    for (int i = 0; i < 8; i++) {
        int c = threadIdx.x + i * 256;
        float t = x[c] + ((m[c] != 0) ? 0.f : -1e9f);
        v[i] = t;
        mx = fmaxf(mx, t);
    }
    mx = blockMax(mx);
    float s = 0.f;
    #pragma unroll
    for (int i = 0; i < 8; i++) { v[i] = expf(v[i] - mx); s += v[i]; }
    s = blockSum(s);
    const float inv = 1.f / s;
    #pragma unroll
    for (int i = 0; i < 8; i++) x[threadIdx.x + i * 256] = v[i] * inv;
}

// ======================= launch =======================
static void split_full(const float* in, bf16* oh, bf16* ol, long rows, long cols) {
    long total4 = rows * (cols / 4);
    split_mat<<<(unsigned)((total4 + 255) / 256), 256>>>(in, cols, oh, ol, cols, (int)(cols / 4), total4);
}

extern "C" void kernel_launch(void* const* d_in, const int* in_sizes, int n_in,
                              void* d_out, int out_size)
{
    const float* vlm    = (const float*)d_in[0];
    const int*   mask   = (const int*)d_in[1];
    const float* l_in_w = (const float*)d_in[2];
    const float* l_in_b = (const float*)d_in[3];
    const float* l_out_w= (const float*)d_in[4];
    const float* l_out_b= (const float*)d_in[5];
    const float* l_ng   = (const float*)d_in[6];
    const float* l_nb   = (const float*)d_in[7];
    const float* l_pw   = (const float*)d_in[8];
    const float* l_pb   = (const float*)d_in[9];
    const float* g_in_w = (const float*)d_in[10];
    const float* g_in_b = (const float*)d_in[11];
    const float* g_out_w= (const float*)d_in[12];
    const float* g_out_b= (const float*)d_in[13];
    const float* g_ng   = (const float*)d_in[14];
    const float* g_nb   = (const float*)d_in[15];
    const float* qtok   = (const float*)d_in[16];
    const float* o_pw   = (const float*)d_in[17];
    const float* o_pb   = (const float*)d_in[18];
    float* out = (float*)d_out;

    cudaFuncSetAttribute(gemm_tc, cudaFuncAttributeMaxDynamicSharedMemorySize, GSMEM);

    float *p_qkv, *p_attnl, *p_y, *p_ln, *p_lf, *p_qg, *p_kvg, *p_sc, *p_ag, *p_yg, *p_lng;
    cudaGetSymbolAddress((void**)&p_qkv,   g_qkv);
    cudaGetSymbolAddress((void**)&p_attnl, g_attnl);
    cudaGetSymbolAddress((void**)&p_y,     g_y);
    cudaGetSymbolAddress((void**)&p_ln,    g_ln);
    cudaGetSymbolAddress((void**)&p_lf,    g_lf);
    cudaGetSymbolAddress((void**)&p_qg,    g_qg);
    cudaGetSymbolAddress((void**)&p_kvg,   g_kvg);
    cudaGetSymbolAddress((void**)&p_sc,    g_sc);
    cudaGetSymbolAddress((void**)&p_ag,    g_ag);
    cudaGetSymbolAddress((void**)&p_yg,    g_yg);
    cudaGetSymbolAddress((void**)&p_lng,   g_lng);

    bf16 *vlm_h,*vlm_l,*liw_h,*liw_l,*low_h,*low_l,*lpw_h,*lpw_l,*giw_h,*giw_l,
         *gow_h,*gow_l,*opw_h,*opw_l,*attnl_h,*attnl_l,*ln_h,*ln_l,*lf_h,*lf_l,
         *qtok_h,*qtok_l,*qg_h,*qg_l,*kvk_h,*kvk_l,*vt_h,*vt_l,*sc_h,*sc_l,
         *ag_h,*ag_l,*lng_h,*lng_l;
    cudaGetSymbolAddress((void**)&vlm_h, b_vlm_h);   cudaGetSymbolAddress((void**)&vlm_l, b_vlm_l);
    cudaGetSymbolAddress((void**)&liw_h, b_liw_h);   cudaGetSymbolAddress((void**)&liw_l, b_liw_l);
    cudaGetSymbolAddress((void**)&low_h, b_low_h);   cudaGetSymbolAddress((void**)&low_l, b_low_l);
    cudaGetSymbolAddress((void**)&lpw_h, b_lpw_h);   cudaGetSymbolAddress((void**)&lpw_l, b_lpw_l);
    cudaGetSymbolAddress((void**)&giw_h, b_giw_h);   cudaGetSymbolAddress((void**)&giw_l, b_giw_l);
    cudaGetSymbolAddress((void**)&gow_h, b_gow_h);   cudaGetSymbolAddress((void**)&gow_l, b_gow_l);
    cudaGetSymbolAddress((void**)&opw_h, b_opw_h);   cudaGetSymbolAddress((void**)&opw_l, b_opw_l);
    cudaGetSymbolAddress((void**)&attnl_h, b_attnl_h); cudaGetSymbolAddress((void**)&attnl_l, b_attnl_l);
    cudaGetSymbolAddress((void**)&ln_h,  b_ln_h);    cudaGetSymbolAddress((void**)&ln_l,  b_ln_l);
    cudaGetSymbolAddress((void**)&lf_h,  b_lf_h);    cudaGetSymbolAddress((void**)&lf_l,  b_lf_l);
    cudaGetSymbolAddress((void**)&qtok_h,b_qtok_h);  cudaGetSymbolAddress((void**)&qtok_l,b_qtok_l);
    cudaGetSymbolAddress((void**)&qg_h,  b_qg_h);    cudaGetSymbolAddress((void**)&qg_l,  b_qg_l);
    cudaGetSymbolAddress((void**)&kvk_h, b_kvk_h);   cudaGetSymbolAddress((void**)&kvk_l, b_kvk_l);
    cudaGetSymbolAddress((void**)&vt_h,  b_vt_h);    cudaGetSymbolAddress((void**)&vt_l,  b_vt_l);
    cudaGetSymbolAddress((void**)&sc_h,  b_sc_h);    cudaGetSymbolAddress((void**)&sc_l,  b_sc_l);
    cudaGetSymbolAddress((void**)&ag_h,  b_ag_h);    cudaGetSymbolAddress((void**)&ag_l,  b_ag_l);
    cudaGetSymbolAddress((void**)&lng_h, b_lng_h);   cudaGetSymbolAddress((void**)&lng_l, b_lng_l);

    const dim3 T256(256);
    #define GEMM(Ah,Al,lda,Bh,Bl,ldb,C,ldc,bias,res,resMod,resLd,K,scale,M,N,zTot,zInner,aIn,aOut,bIn,bOut,cIn,cOut) \
        gemm_tc<<<dim3(((M)/128)*((N)/128), 1, zTot), T256, GSMEM>>>( \
            Ah, Al, lda, Bh, Bl, ldb, C, ldc, bias, res, resMod, resLd, \
            K, scale, (M)/128, (N)/128, zInner, aIn, aOut, bIn, bOut, cIn, cOut)

    // weight + input splits
    split_full(vlm,     vlm_h,  vlm_l,  NTOK,   DD);
    split_full(l_in_w,  liw_h,  liw_l,  3*DD,   DD);
    split_full(l_out_w, low_h,  low_l,  DD,     DD);
    split_full(l_pw,    lpw_h,  lpw_l,  DD,     DD);
    split_full(g_in_w,  giw_h,  giw_l,  3*DD,   DD);
    split_full(g_out_w, gow_h,  gow_l,  DD,     DD);
    split_full(o_pw,    opw_h,  opw_l,  DD,     DD);
    split_full(qtok,    qtok_h, qtok_l, DT,     DD);

    // 1) local QKV: (8192 x 12288)
    GEMM(vlm_h, vlm_l, DD, liw_h, liw_l, DD, p_qkv, 3*DD, l_in_b,
         (const float*)nullptr, 1, 1, DD, 1.f, NTOK, 3*DD, 1, 1, 0,0,0,0,0,0);

    // 2) local windowed attention
    local_attn<<<dim3(DB * (DS / DW), NH), T256>>>(p_qkv, mask, p_attnl);
    split_full(p_attnl, attnl_h, attnl_l, NTOK, DD);

    // 3) local out_proj + residual(vlm)
    GEMM(attnl_h, attnl_l, DD, low_h, low_l, DD, p_y, DD, l_out_b,
         vlm, NTOK, DD, DD, 1.f, NTOK, DD, 1, 1, 0,0,0,0,0,0);

    // 4) LN local
    layernorm_k<<<NTOK, T256>>>(p_y, l_ng, l_nb, p_ln);
    split_full(p_ln, ln_h, ln_l, NTOK, DD);

    // 5) local_proj -> local_features
    GEMM(ln_h, ln_l, DD, lpw_h, lpw_l, DD, p_lf, DD, l_pb,
         (const float*)nullptr, 1, 1, DD, 1.f, NTOK, DD, 1, 1, 0,0,0,0,0,0);
    split_full(p_lf, lf_h, lf_l, NTOK, DD);

    // 6) global q (batch-invariant)
    GEMM(qtok_h, qtok_l, DD, giw_h, giw_l, DD, p_qg, DD, g_in_b,
         (const float*)nullptr, 1, 1, DD, 1.f, DT, DD, 1, 1, 0,0,0,0,0,0);
    split_full(p_qg, qg_h, qg_l, DT, DD);

    // 7) global k,v
    GEMM(lf_h, lf_l, DD, giw_h + (long)DD*DD, giw_l + (long)DD*DD, DD,
         p_kvg, 2*DD, g_in_b + DD,
         (const float*)nullptr, 1, 1, DD, 1.f, NTOK, 2*DD, 1, 1, 0,0,0,0,0,0);

    // split K half (compact ld 4096), transpose-split V half
    {
        long total4 = (long)NTOK * (DD / 4);
        split_mat<<<(unsigned)((total4 + 255) / 256), 256>>>(
            p_kvg, 2*DD, kvk_h, kvk_l, DD, DD / 4, total4);
    }
    vtrans_split<<<dim3(DS/32, DD/32, DB), T256>>>(p_kvg, vt_h, vt_l);

    // 8) scores (batched 32): (256 x 2048 x 512), scaled
    GEMM(qg_h, qg_l, DD, kvk_h, kvk_l, DD, p_sc, DS,
         (const float*)nullptr, (const float*)nullptr, 1, 1,
         DH_, SCL, DT, DS, DB*NH, NH,
         /*aIn*/DH_, /*aOut*/0,
         /*bIn*/DH_, /*bOut*/(long)DS * DD,
         /*cIn*/(long)DT * DS, /*cOut*/(long)NH * DT * DS);

    // 9) softmax over keys with padding mask
    softmax_g<<<DB * NH * DT, T256>>>(p_sc, mask);
    split_full(p_sc, sc_h, sc_l, (long)DB*NH*DT, DS);

    // 10) AV (batched 32): (256 x 512 x 2048)
    GEMM(sc_h, sc_l, DS, vt_h, vt_l, DS, p_ag, DD,
         (const float*)nullptr, (const float*)nullptr, 1, 1,
         DS, 1.f, DT, DH_, DB*NH, NH,
         /*aIn*/(long)DT * DS, /*aOut*/(long)NH * DT * DS,
         /*bIn*/(long)DH_ * DS, /*bOut*/(long)DD * DS,
         /*cIn*/DH_, /*cOut*/(long)DT * DD);
    split_full(p_ag, ag_h, ag_l, NQ, DD);

    // 11) global out_proj + residual(query_tokens broadcast)
    GEMM(ag_h, ag_l, DD, gow_h, gow_l, DD, p_yg, DD, g_out_b,
         qtok, DT, DD, DD, 1.f, NQ, DD, 1, 1, 0,0,0,0,0,0);

    // 12) LN global
    layernorm_k<<<NQ, T256>>>(p_yg, g_ng, g_nb, p_lng);
    split_full(p_lng, lng_h, lng_l, NQ, DD);

    // 13) output_proj -> d_out
    GEMM(lng_h, lng_l, DD, opw_h, opw_l, DD, out, DD, o_pb,
         (const float*)nullptr, 1, 1, DD, 1.f, NQ, DD, 1, 1, 0,0,0,0,0,0);
}

// round 6
// speedup vs baseline: 2.4488x; 1.1943x over previous
#include <cuda_runtime.h>
#include <cuda_bf16.h>
#include <cstdint>

// ---------------- problem constants ----------------
// B=4, S=2048, D=4096, T=256, W=32, H=8, DH=512
#define DB   4
#define DS   2048
#define DD   4096
#define DT   256
#define DW   32
#define DH_  512
#define NH   8
#define NTOK (DB*DS)            // 8192
#define NQ   (DB*DT)            // 1024
#define SCL  0.044194173824159216f  // 1/sqrt(512)

typedef __nv_bfloat16 bf16;

// ---------------- device scratch (no allocations allowed) ----------------
// fp32 intermediates (only where consumed as fp32)
__device__ float g_qkv  [ (long)NTOK * 3 * DD ];
__device__ float g_y    [ (long)NTOK * DD ];
__device__ float g_kvg  [ (long)NTOK * 2 * DD ];
__device__ float g_sc   [ (long)DB * NH * DT * DS ];
__device__ float g_yg   [ (long)NQ * DD ];
// bf16 split operands (hi / lo), 16B-aligned for cp.async
__device__ __align__(16) bf16 b_vlm_h  [(long)NTOK*DD],      b_vlm_l  [(long)NTOK*DD];
__device__ __align__(16) bf16 b_liw_h  [(long)3*DD*DD],      b_liw_l  [(long)3*DD*DD];
__device__ __align__(16) bf16 b_low_h  [(long)DD*DD],        b_low_l  [(long)DD*DD];
__device__ __align__(16) bf16 b_lpw_h  [(long)DD*DD],        b_lpw_l  [(long)DD*DD];
__device__ __align__(16) bf16 b_giw_h  [(long)3*DD*DD],      b_giw_l  [(long)3*DD*DD];
__device__ __align__(16) bf16 b_gow_h  [(long)DD*DD],        b_gow_l  [(long)DD*DD];
__device__ __align__(16) bf16 b_opw_h  [(long)DD*DD],        b_opw_l  [(long)DD*DD];
__device__ __align__(16) bf16 b_attnl_h[(long)NTOK*DD],      b_attnl_l[(long)NTOK*DD];
__device__ __align__(16) bf16 b_ln_h   [(long)NTOK*DD],      b_ln_l   [(long)NTOK*DD];
__device__ __align__(16) bf16 b_lf_h   [(long)NTOK*DD],      b_lf_l   [(long)NTOK*DD];
__device__ __align__(16) bf16 b_qtok_h [(long)DT*DD],        b_qtok_l [(long)DT*DD];
__device__ __align__(16) bf16 b_qg_h   [(long)DT*DD],        b_qg_l   [(long)DT*DD];
__device__ __align__(16) bf16 b_kvk_h  [(long)NTOK*DD],      b_kvk_l  [(long)NTOK*DD];   // K half, ld=4096
__device__ __align__(16) bf16 b_vt_h   [(long)DB*DD*DS],     b_vt_l   [(long)DB*DD*DS];  // V^T
__device__ __align__(16) bf16 b_sc_h   [(long)DB*NH*DT*DS],  b_sc_l   [(long)DB*NH*DT*DS];
__device__ __align__(16) bf16 b_ag_h   [(long)NQ*DD],        b_ag_l   [(long)NQ*DD];
__device__ __align__(16) bf16 b_lng_h  [(long)NQ*DD],        b_lng_l  [(long)NQ*DD];

// ======================= helpers =======================
__device__ __forceinline__ uint32_t smem_u32(const void* p) {
    uint32_t a;
    asm("{ .reg .u64 t; cvta.to.shared.u64 t, %1; cvt.u32.u64 %0, t; }" : "=r"(a) : "l"(p));
    return a;
}
__device__ __forceinline__ void cp16(uint32_t dst, const void* src) {
    asm volatile("cp.async.cg.shared.global [%0], [%1], 16;" :: "r"(dst), "l"(src));
}
__device__ __forceinline__ void cp_commit() { asm volatile("cp.async.commit_group;" ::: "memory"); }
template <int N> __device__ __forceinline__ void cp_wait() {
    asm volatile("cp.async.wait_group %0;" :: "n"(N) : "memory");
}
__device__ __forceinline__ void ldsm4(uint32_t* r, uint32_t a) {
    asm volatile("ldmatrix.sync.aligned.m8n8.x4.shared.b16 {%0,%1,%2,%3}, [%4];"
        : "=r"(r[0]), "=r"(r[1]), "=r"(r[2]), "=r"(r[3]) : "r"(a));
}
__device__ __forceinline__ void mma16816(float* d, const uint32_t* a, const uint32_t* b) {
    asm volatile(
        "mma.sync.aligned.m16n8k16.row.col.f32.bf16.bf16.f32 "
        "{%0,%1,%2,%3}, {%4,%5,%6,%7}, {%8,%9}, {%0,%1,%2,%3};"
        : "+f"(d[0]), "+f"(d[1]), "+f"(d[2]), "+f"(d[3])
        : "r"(a[0]), "r"(a[1]), "r"(a[2]), "r"(a[3]), "r"(b[0]), "r"(b[1]));
}
__device__ __forceinline__ void split1(float v, bf16& h, bf16& l) {
    h = __float2bfloat16(v);
    l = __float2bfloat16(v - __bfloat162float(h));
}

// ======================= split-bf16 HMMA GEMM =======================
// C(M,N) = scale * (Ah+Al)(Bh+Bl)^T [3-product] + bias + res
// 128x128 tile, K-chunk 64, 3-stage cp.async, single __syncthreads/iter.
// stage layout (73728B): Ah[128][72] Al Bh[128][72] Bl  (72 bf16 = 144B rows)
#define GSTG  73728
#define GSMEM (3*GSTG)
#define OFF_AL 18432u
#define OFF_BH 36864u
#define OFF_BL 55296u

__device__ __forceinline__ void load_chunk(
    uint32_t sb, int slot, long k0, int tid,
    const bf16* __restrict__ Ah, const bf16* __restrict__ Al, long lda, long bm,
    const bf16* __restrict__ Bh, const bf16* __restrict__ Bl, long ldb, long bn)
{
    uint32_t base = sb + (uint32_t)slot * GSTG;
    #pragma unroll
    for (int it = 0; it < 4; it++) {
        int u = tid + it * 256;            // 0..1023
        int r = u >> 3, c = u & 7;         // row 0..127, 16B-col 0..7
        uint32_t off = (uint32_t)(r * 144 + c * 16);
        long srcA = (bm + r) * lda + k0 + c * 8;
        cp16(base + off,          Ah + srcA);
        cp16(base + OFF_AL + off, Al + srcA);
        long srcB = (bn + r) * ldb + k0 + c * 8;
        cp16(base + OFF_BH + off, Bh + srcB);
        cp16(base + OFF_BL + off, Bl + srcB);
    }
    cp_commit();
}

__global__ __launch_bounds__(256) void gemm_tc(
    const bf16* __restrict__ Ah, const bf16* __restrict__ Al, long lda,
    const bf16* __restrict__ Bh, const bf16* __restrict__ Bl, long ldb,
    float* __restrict__ C,                      // fp32 out (or null)
    bf16* __restrict__ Oh, bf16* __restrict__ Ol,  // bf16 split out (or null)
    long ldc,
    const float* __restrict__ bias,
    const float* __restrict__ res, int resMod, long resLd,
    int K, float scale, int nTm, int nTn,
    int zInner, long aIn, long aOut, long bIn, long bOut, long cIn, long cOut)
{
    extern __shared__ __align__(128) char smem[];
    const uint32_t sb = smem_u32(smem);
    const int tid = threadIdx.x;
    const int wid = tid >> 5;
    const int lane = tid & 31;

    const int z = blockIdx.z;
    const int zi = z % zInner, zo = z / zInner;
    Ah += (long)zi * aIn + (long)zo * aOut;  Al += (long)zi * aIn + (long)zo * aOut;
    Bh += (long)zi * bIn + (long)zo * bOut;  Bl += (long)zi * bIn + (long)zo * bOut;
    const long coff = (long)zi * cIn + (long)zo * cOut;
    if (C)  C  += coff;
    if (Oh) { Oh += coff; Ol += coff; }

    // L2-friendly rasterization: bands of 8 N-tiles
    const int idx = blockIdx.x;
    const int per = nTm * 8;
    const int band = idx / per, rem = idx % per;
    const long bm = (long)(rem % nTm) * 128;
    const long bn = (long)(band * 8 + rem / nTm) * 128;

    // warp layout: 4(M) x 2(N); warp tile 32x64
    const int wm = wid & 3;
    const int wn = wid >> 2;

    const uint32_t aBase = sb +
        (uint32_t)((wm * 32 + (lane & 15)) * 144 + (lane >> 4) * 16);
    const uint32_t bBase = sb + OFF_BH +
        (uint32_t)((wn * 64 + (lane & 7) + ((lane >> 4) & 1) * 8) * 144 +
                   ((lane >> 3) & 1) * 16);

    float acc[2][8][4];
    #pragma unroll
    for (int i = 0; i < 2; i++)
        #pragma unroll
        for (int j = 0; j < 8; j++)
            #pragma unroll
            for (int q = 0; q < 4; q++) acc[i][j][q] = 0.f;

    const int nCh = K >> 6;        // K-chunk 64; all K here divisible by 64
    load_chunk(sb, 0, 0,  tid, Ah, Al, lda, bm, Bh, Bl, ldb, bn);
    load_chunk(sb, 1, 64, tid, Ah, Al, lda, bm, Bh, Bl, ldb, bn);

    for (int i = 0; i < nCh; i++) {
        if (i + 1 < nCh) cp_wait<1>(); else cp_wait<0>();
        __syncthreads();
        // issue next loads first (into slot (i+2)%3 == slot (i-1)%3, consumed & synced)
        if (i + 2 < nCh)
            load_chunk(sb, (i + 2) % 3, (long)(i + 2) * 64, tid,
                       Ah, Al, lda, bm, Bh, Bl, ldb, bn);
        const uint32_t stg = (uint32_t)(i % 3) * GSTG;
        #pragma unroll
        for (int ks = 0; ks < 4; ks++) {
            uint32_t ah[2][4], al[2][4], bh[4][4], bl[4][4];
            #pragma unroll
            for (int m = 0; m < 2; m++) {
                uint32_t a = aBase + stg + (uint32_t)(m * 2304 + ks * 32);
                ldsm4(ah[m], a);
                ldsm4(al[m], a + OFF_AL);
            }
            #pragma unroll
            for (int p = 0; p < 4; p++) {
                uint32_t a = bBase + stg + (uint32_t)(p * 2304 + ks * 32);
                ldsm4(bh[p], a);
                ldsm4(bl[p], a + OFF_AL);     // Bl - Bh == OFF_AL too
            }
            #pragma unroll
            for (int m = 0; m < 2; m++)
                #pragma unroll
                for (int nt = 0; nt < 8; nt++) {
                    const uint32_t* BH = &bh[nt >> 1][(nt & 1) * 2];
                    const uint32_t* BL = &bl[nt >> 1][(nt & 1) * 2];
                    mma16816(acc[m][nt], ah[m], BH);
                    mma16816(acc[m][nt], al[m], BH);
                    mma16816(acc[m][nt], ah[m], BL);
                }
        }
    }

    // ---- epilogue: fused scale/bias/residual; fp32 and/or bf16-split out ----
    const int r0 = lane >> 2;
    const int c0 = (lane & 3) * 2;
    #pragma unroll
    for (int m = 0; m < 2; m++) {
        #pragma unroll
        for (int half = 0; half < 2; half++) {
            const long grow = bm + wm * 32 + m * 16 + r0 + half * 8;
            const long rrow = (grow % resMod) * resLd;
            #pragma unroll
            for (int nt = 0; nt < 8; nt++) {
                const long gcol = bn + wn * 64 + nt * 8 + c0;
                float vx = acc[m][nt][half * 2]     * scale;
                float vy = acc[m][nt][half * 2 + 1] * scale;
                if (bias) {
                    float2 bb = *(const float2*)&bias[gcol];
                    vx += bb.x; vy += bb.y;
                }
                if (res) {
                    float2 rr = *(const float2*)&res[rrow + gcol];
                    vx += rr.x; vy += rr.y;
                }
                if (C) {
                    float2 v; v.x = vx; v.y = vy;
                    *(float2*)&C[grow * ldc + gcol] = v;
                }
                if (Oh) {
                    bf16 hx, lx, hy, ly;
                    split1(vx, hx, lx); split1(vy, hy, ly);
                    __nv_bfloat162 hv; hv.x = hx; hv.y = hy;
                    __nv_bfloat162 lv; lv.x = lx; lv.y = ly;
                    *(__nv_bfloat162*)&Oh[grow * ldc + gcol] = hv;
                    *(__nv_bfloat162*)&Ol[grow * ldc + gcol] = lv;
                }
            }
        }
    }
}

// ======================= split / transpose conversions =======================
__global__ __launch_bounds__(256) void split_mat(
    const float* __restrict__ in, long ldIn,
    bf16* __restrict__ oh, bf16* __restrict__ ol, long ldOut,
    int cols4, long total4)
{
    long idx = (long)blockIdx.x * 256 + threadIdx.x;
    if (idx >= total4) return;
    long r = idx / cols4;
    int  c = (int)(idx - r * cols4);
    float4 v = *(const float4*)(in + r * ldIn + c * 4);
    bf16 h0, h1, h2, h3, l0, l1, l2, l3;
    split1(v.x, h0, l0); split1(v.y, h1, l1);
    split1(v.z, h2, l2); split1(v.w, h3, l3);
    __nv_bfloat162* ph = (__nv_bfloat162*)(oh + r * ldOut + c * 4);
    __nv_bfloat162* pl = (__nv_bfloat162*)(ol + r * ldOut + c * 4);
    __nv_bfloat162 a; a.x = h0; a.y = h1; ph[0] = a;
    a.x = h2; a.y = h3; ph[1] = a;
    a.x = l0; a.y = l1; pl[0] = a;
    a.x = l2; a.y = l3; pl[1] = a;
}

// V part of kvg -> transposed split: vt[(b*4096+d)*2048 + s]
__global__ __launch_bounds__(256) void vtrans_split(
    const float* __restrict__ kvg, bf16* __restrict__ vh, bf16* __restrict__ vl)
{
    __shared__ float tile[32][33];
    const int s0 = blockIdx.x * 32, d0 = blockIdx.y * 32, b = blockIdx.z;
    const int tx = threadIdx.x & 31, ty = threadIdx.x >> 5;
    #pragma unroll
    for (int j = 0; j < 4; j++) {
        int s = s0 + ty + j * 8;
        tile[ty + j * 8][tx] = kvg[((long)b * DS + s) * (2 * DD) + DD + d0 + tx];
    }
    __syncthreads();
    #pragma unroll
    for (int j = 0; j < 4; j++) {
        int d = d0 + ty + j * 8;
        float v = tile[tx][ty + j * 8];
        bf16 h, l; split1(v, h, l);
        long o = ((long)b * DD + d) * DS + s0 + tx;
        vh[o] = h; vl[o] = l;
    }
}

// ======================= reductions =======================
__device__ __forceinline__ float blockSum(float val) {
    __shared__ float sh[32];
    int lane = threadIdx.x & 31, w = threadIdx.x >> 5;
    #pragma unroll
    for (int o = 16; o; o >>= 1) val += __shfl_xor_sync(0xffffffffu, val, o);
    __syncthreads();
    if (lane == 0) sh[w] = val;
    __syncthreads();
    val = (lane < 8) ? sh[lane] : 0.f;
    #pragma unroll
    for (int o = 4; o; o >>= 1) val += __shfl_xor_sync(0xffffffffu, val, o);
    return __shfl_sync(0xffffffffu, val, 0);
}
__device__ __forceinline__ float blockMax(float val) {
    __shared__ float sh[32];
    int lane = threadIdx.x & 31, w = threadIdx.x >> 5;
    #pragma unroll
    for (int o = 16; o; o >>= 1) val = fmaxf(val, __shfl_xor_sync(0xffffffffu, val, o));
    __syncthreads();
    if (lane == 0) sh[w] = val;
    __syncthreads();
    val = (lane < 8) ? sh[lane] : -3.4e38f;
    #pragma unroll
    for (int o = 4; o; o >>= 1) val = fmaxf(val, __shfl_xor_sync(0xffffffffu, val, o));
    return __shfl_sync(0xffffffffu, val, 0);
}

// ---------------- local windowed attention: fp32 qkv -> bf16-split out ----------------
__global__ __launch_bounds__(256) void local_attn(
    const float* __restrict__ qkv, const int* __restrict__ mask,
    bf16* __restrict__ outH, bf16* __restrict__ outL)
{
    const int  bw   = blockIdx.x;
    const int  h    = blockIdx.y;
    const long tok0 = (long)bw * DW;
    const int  LD   = 3 * DD;
    const float* qb = qkv + tok0 * LD + h * DH_;
    const float* kb = qkv + tok0 * LD + DD + h * DH_;
    const float* vb = qkv + tok0 * LD + 2 * DD + h * DH_;

    __shared__ float s[DW][DW + 1];
    __shared__ float msk[DW];
    const int tid = threadIdx.x;
    if (tid < DW) msk[tid] = (mask[tok0 + tid] != 0) ? 0.f : -1e9f;

    #pragma unroll
    for (int p = tid; p < DW * DW; p += 256) {
        int i = p >> 5, j = p & 31;
        const float4* qp = (const float4*)(qb + (long)i * LD);
        const float4* kp = (const float4*)(kb + (long)j * LD);
        float acc = 0.f;
        #pragma unroll 8
        for (int d = 0; d < DH_ / 4; d++) {
            float4 a = qp[d], c = kp[d];
            acc += a.x * c.x + a.y * c.y + a.z * c.z + a.w * c.w;
        }
        s[i][j] = acc;
    }
    __syncthreads();

    if (tid < DW) {
        const int i = tid;
        const float mi = msk[i];
        float r[DW];
        float mx = -3.4e38f;
        #pragma unroll
        for (int j = 0; j < DW; j++) {
            float bias = (mi + msk[j] < -0.5f) ? -1e9f : 0.f;
            r[j] = s[i][j] * SCL + bias;
            mx = fmaxf(mx, r[j]);
        }
        float sum = 0.f;
        #pragma unroll
        for (int j = 0; j < DW; j++) { r[j] = expf(r[j] - mx); sum += r[j]; }
        const float inv = 1.f / sum;
        #pragma unroll
        for (int j = 0; j < DW; j++) s[i][j] = r[j] * inv;
    }
    __syncthreads();

    float2 acc[DW];
    #pragma unroll
    for (int i = 0; i < DW; i++) acc[i] = make_float2(0.f, 0.f);
    for (int j = 0; j < DW; j++) {
        float2 v2 = *(const float2*)(vb + (long)j * LD + tid * 2);
        #pragma unroll
        for (int i = 0; i < DW; i++) {
            float w = s[i][j];
            acc[i].x += w * v2.x;
            acc[i].y += w * v2.y;
        }
    }
    const long obase = tok0 * DD + h * DH_ + tid * 2;
    #pragma unroll
    for (int i = 0; i < DW; i++) {
        bf16 hx, lx, hy, ly;
        split1(acc[i].x, hx, lx); split1(acc[i].y, hy, ly);
        __nv_bfloat162 hv; hv.x = hx; hv.y = hy;
        __nv_bfloat162 lv; lv.x = lx; lv.y = ly;
        *(__nv_bfloat162*)&outH[obase + (long)i * DD] = hv;
        *(__nv_bfloat162*)&outL[obase + (long)i * DD] = lv;
    }
}

// ---------------- LayerNorm over rows of 4096 -> bf16 split out ----------------
__global__ __launch_bounds__(256) void layernorm_bf(
    const float* __restrict__ X, const float* __restrict__ g,
    const float* __restrict__ b, bf16* __restrict__ Yh, bf16* __restrict__ Yl)
{
    const long row = blockIdx.x;
    const float* x = X + row * DD;
    float v[16];
    float s = 0.f;
    #pragma unroll
    for (int i = 0; i < 16; i++) { v[i] = x[threadIdx.x + i * 256]; s += v[i]; }
    const float mean = blockSum(s) * (1.f / DD);
    float d2 = 0.f;
    #pragma unroll
    for (int i = 0; i < 16; i++) { float d = v[i] - mean; d2 += d * d; }
    const float var = blockSum(d2) * (1.f / DD);
    const float rs = rsqrtf(var + 1e-5f);
    #pragma unroll
    for (int i = 0; i < 16; i++) {
        int c = threadIdx.x + i * 256;
        float o = (v[i] - mean) * rs * g[c] + b[c];
        bf16 h, l; split1(o, h, l);
        Yh[row * DD + c] = h;
        Yl[row * DD + c] = l;
    }
}

// ---------------- global softmax over S=2048 keys -> bf16 split out ----------------
__global__ __launch_bounds__(256) void softmax_bf(
    const float* __restrict__ sc, const int* __restrict__ mask,
    bf16* __restrict__ oh, bf16* __restrict__ ol)
{
    const long row = blockIdx.x;
    const int  b   = (int)(row >> 11);
    const float* x = sc + row * DS;
    const int* m = mask + (long)b * DS;
    float v[8];
    float mx = -3.4e38f;
    #pragma unroll
    for (int i = 0; i < 8; i++) {
        int c = threadIdx.x + i * 256;
        float t = x[c] + ((m[c] != 0) ? 0.f : -1e9f);
        v[i] = t;
        mx = fmaxf(mx, t);
    }
    mx = blockMax(mx);
    float s = 0.f;
    #pragma unroll
    for (int i = 0; i < 8; i++) { v[i] = expf(v[i] - mx); s += v[i]; }
    s = blockSum(s);
    const float inv = 1.f / s;
    #pragma unroll
    for (int i = 0; i < 8; i++) {
        int c = threadIdx.x + i * 256;
        bf16 h, l; split1(v[i] * inv, h, l);
        oh[row * DS + c] = h;
        ol[row * DS + c] = l;
    }
}

// ======================= launch =======================
static void split_full(const float* in, bf16* oh, bf16* ol, long rows, long cols) {
    long total4 = rows * (cols / 4);
    split_mat<<<(unsigned)((total4 + 255) / 256), 256>>>(in, cols, oh, ol, cols, (int)(cols / 4), total4);
}

extern "C" void kernel_launch(void* const* d_in, const int* in_sizes, int n_in,
                              void* d_out, int out_size)
{
    const float* vlm    = (const float*)d_in[0];
    const int*   mask   = (const int*)d_in[1];
    const float* l_in_w = (const float*)d_in[2];
    const float* l_in_b = (const float*)d_in[3];
    const float* l_out_w= (const float*)d_in[4];
    const float* l_out_b= (const float*)d_in[5];
    const float* l_ng   = (const float*)d_in[6];
    const float* l_nb   = (const float*)d_in[7];
    const float* l_pw   = (const float*)d_in[8];
    const float* l_pb   = (const float*)d_in[9];
    const float* g_in_w = (const float*)d_in[10];
    const float* g_in_b = (const float*)d_in[11];
    const float* g_out_w= (const float*)d_in[12];
    const float* g_out_b= (const float*)d_in[13];
    const float* g_ng   = (const float*)d_in[14];
    const float* g_nb   = (const float*)d_in[15];
    const float* qtok   = (const float*)d_in[16];
    const float* o_pw   = (const float*)d_in[17];
    const float* o_pb   = (const float*)d_in[18];
    float* out = (float*)d_out;

    cudaFuncSetAttribute(gemm_tc, cudaFuncAttributeMaxDynamicSharedMemorySize, GSMEM);

    float *p_qkv, *p_y, *p_kvg, *p_sc, *p_yg;
    cudaGetSymbolAddress((void**)&p_qkv, g_qkv);
    cudaGetSymbolAddress((void**)&p_y,   g_y);
    cudaGetSymbolAddress((void**)&p_kvg, g_kvg);
    cudaGetSymbolAddress((void**)&p_sc,  g_sc);
    cudaGetSymbolAddress((void**)&p_yg,  g_yg);

    bf16 *vlm_h,*vlm_l,*liw_h,*liw_l,*low_h,*low_l,*lpw_h,*lpw_l,*giw_h,*giw_l,
         *gow_h,*gow_l,*opw_h,*opw_l,*attnl_h,*attnl_l,*ln_h,*ln_l,*lf_h,*lf_l,
         *qtok_h,*qtok_l,*qg_h,*qg_l,*kvk_h,*kvk_l,*vt_h,*vt_l,*sc_h,*sc_l,
         *ag_h,*ag_l,*lng_h,*lng_l;
    cudaGetSymbolAddress((void**)&vlm_h, b_vlm_h);   cudaGetSymbolAddress((void**)&vlm_l, b_vlm_l);
    cudaGetSymbolAddress((void**)&liw_h, b_liw_h);   cudaGetSymbolAddress((void**)&liw_l, b_liw_l);
    cudaGetSymbolAddress((void**)&low_h, b_low_h);   cudaGetSymbolAddress((void**)&low_l, b_low_l);
    cudaGetSymbolAddress((void**)&lpw_h, b_lpw_h);   cudaGetSymbolAddress((void**)&lpw_l, b_lpw_l);
    cudaGetSymbolAddress((void**)&giw_h, b_giw_h);   cudaGetSymbolAddress((void**)&giw_l, b_giw_l);
    cudaGetSymbolAddress((void**)&gow_h, b_gow_h);   cudaGetSymbolAddress((void**)&gow_l, b_gow_l);
    cudaGetSymbolAddress((void**)&opw_h, b_opw_h);   cudaGetSymbolAddress((void**)&opw_l, b_opw_l);
    cudaGetSymbolAddress((void**)&attnl_h, b_attnl_h); cudaGetSymbolAddress((void**)&attnl_l, b_attnl_l);
    cudaGetSymbolAddress((void**)&ln_h,  b_ln_h);    cudaGetSymbolAddress((void**)&ln_l,  b_ln_l);
    cudaGetSymbolAddress((void**)&lf_h,  b_lf_h);    cudaGetSymbolAddress((void**)&lf_l,  b_lf_l);
    cudaGetSymbolAddress((void**)&qtok_h,b_qtok_h);  cudaGetSymbolAddress((void**)&qtok_l,b_qtok_l);
    cudaGetSymbolAddress((void**)&qg_h,  b_qg_h);    cudaGetSymbolAddress((void**)&qg_l,  b_qg_l);
    cudaGetSymbolAddress((void**)&kvk_h, b_kvk_h);   cudaGetSymbolAddress((void**)&kvk_l, b_kvk_l);
    cudaGetSymbolAddress((void**)&vt_h,  b_vt_h);    cudaGetSymbolAddress((void**)&vt_l,  b_vt_l);
    cudaGetSymbolAddress((void**)&sc_h,  b_sc_h);    cudaGetSymbolAddress((void**)&sc_l,  b_sc_l);
    cudaGetSymbolAddress((void**)&ag_h,  b_ag_h);    cudaGetSymbolAddress((void**)&ag_l,  b_ag_l);
    cudaGetSymbolAddress((void**)&lng_h, b_lng_h);   cudaGetSymbolAddress((void**)&lng_l, b_lng_l);

    const dim3 T256(256);
    #define GEMM(Ah,Al,lda,Bh,Bl,ldb,C,Oh,Ol,ldc,bias,res,resMod,resLd,K,scale,M,N,zTot,zInner,aIn,aOut,bIn,bOut,cIn,cOut) \
        gemm_tc<<<dim3(((M)/128)*((N)/128), 1, zTot), T256, GSMEM>>>( \
            Ah, Al, lda, Bh, Bl, ldb, C, Oh, Ol, ldc, bias, res, resMod, resLd, \
            K, scale, (M)/128, (N)/128, zInner, aIn, aOut, bIn, bOut, cIn, cOut)
    #define NOF (const float*)nullptr
    #define NOC (float*)nullptr
    #define NOB (bf16*)nullptr

    // input/weight splits
    split_full(vlm,     vlm_h,  vlm_l,  NTOK,   DD);
    split_full(l_in_w,  liw_h,  liw_l,  3*DD,   DD);
    split_full(l_out_w, low_h,  low_l,  DD,     DD);
    split_full(l_pw,    lpw_h,  lpw_l,  DD,     DD);
    split_full(g_in_w,  giw_h,  giw_l,  3*DD,   DD);
    split_full(g_out_w, gow_h,  gow_l,  DD,     DD);
    split_full(o_pw,    opw_h,  opw_l,  DD,     DD);
    split_full(qtok,    qtok_h, qtok_l, DT,     DD);

    // 1) local QKV: (8192 x 12288), fp32 out (consumed by local_attn)
    GEMM(vlm_h, vlm_l, DD, liw_h, liw_l, DD, p_qkv, NOB, NOB, 3*DD, l_in_b,
         NOF, 1, 1, DD, 1.f, NTOK, 3*DD, 1, 1, 0,0,0,0,0,0);

    // 2) local windowed attention -> bf16 split directly
    local_attn<<<dim3(DB * (DS / DW), NH), T256>>>(p_qkv, mask, attnl_h, attnl_l);

    // 3) local out_proj + residual(vlm), fp32 out (consumed by LN)
    GEMM(attnl_h, attnl_l, DD, low_h, low_l, DD, p_y, NOB, NOB, DD, l_out_b,
         vlm, NTOK, DD, DD, 1.f, NTOK, DD, 1, 1, 0,0,0,0,0,0);

    // 4) LN local -> bf16 split directly
    layernorm_bf<<<NTOK, T256>>>(p_y, l_ng, l_nb, ln_h, ln_l);

    // 5) local_proj -> local_features (bf16 split only)
    GEMM(ln_h, ln_l, DD, lpw_h, lpw_l, DD, NOC, lf_h, lf_l, DD, l_pb,
         NOF, 1, 1, DD, 1.f, NTOK, DD, 1, 1, 0,0,0,0,0,0);

    // 6) global q (batch-invariant, bf16 split only)
    GEMM(qtok_h, qtok_l, DD, giw_h, giw_l, DD, NOC, qg_h, qg_l, DD, g_in_b,
         NOF, 1, 1, DD, 1.f, DT, DD, 1, 1, 0,0,0,0,0,0);

    // 7) global k,v (fp32 out; consumed by split + vtrans)
    GEMM(lf_h, lf_l, DD, giw_h + (long)DD*DD, giw_l + (long)DD*DD, DD,
         p_kvg, NOB, NOB, 2*DD, g_in_b + DD,
         NOF, 1, 1, DD, 1.f, NTOK, 2*DD, 1, 1, 0,0,0,0,0,0);

    // split K half (compact ld 4096), transpose-split V half
    {
        long total4 = (long)NTOK * (DD / 4);
        split_mat<<<(unsigned)((total4 + 255) / 256), 256>>>(
            p_kvg, 2*DD, kvk_h, kvk_l, DD, DD / 4, total4);
    }
    vtrans_split<<<dim3(DS/32, DD/32, DB), T256>>>(p_kvg, vt_h, vt_l);

    // 8) scores (batched 32): (256 x 2048 x 512), scaled, fp32 out
    GEMM(qg_h, qg_l, DD, kvk_h, kvk_l, DD, p_sc, NOB, NOB, DS,
         NOF, NOF, 1, 1,
         DH_, SCL, DT, DS, DB*NH, NH,
         /*aIn*/DH_, /*aOut*/0,
         /*bIn*/DH_, /*bOut*/(long)DS * DD,
         /*cIn*/(long)DT * DS, /*cOut*/(long)NH * DT * DS);

    // 9) softmax over keys -> bf16 split directly
    softmax_bf<<<DB * NH * DT, T256>>>(p_sc, mask, sc_h, sc_l);

    // 10) AV (batched 32): (256 x 512 x 2048), bf16 split only
    GEMM(sc_h, sc_l, DS, vt_h, vt_l, DS, NOC, ag_h, ag_l, DD,
         NOF, NOF, 1, 1,
         DS, 1.f, DT, DH_, DB*NH, NH,
         /*aIn*/(long)DT * DS, /*aOut*/(long)NH * DT * DS,
         /*bIn*/(long)DH_ * DS, /*bOut*/(long)DD * DS,
         /*cIn*/DH_, /*cOut*/(long)DT * DD);

    // 11) global out_proj + residual(query_tokens broadcast), fp32 out
    GEMM(ag_h, ag_l, DD, gow_h, gow_l, DD, p_yg, NOB, NOB, DD, g_out_b,
         qtok, DT, DD, DD, 1.f, NQ, DD, 1, 1, 0,0,0,0,0,0);

    // 12) LN global -> bf16 split directly
    layernorm_bf<<<NQ, T256>>>(p_yg, g_ng, g_nb, lng_h, lng_l);

    // 13) output_proj -> d_out (fp32)
    GEMM(lng_h, lng_l, DD, opw_h, opw_l, DD, out, NOB, NOB, DD, o_pb,
         NOF, 1, 1, DD, 1.f, NQ, DD, 1, 1, 0,0,0,0,0,0);
}

// round 8
// speedup vs baseline: 2.8401x; 1.1598x over previous
#include <cuda_runtime.h>
#include <cuda_bf16.h>
#include <cstdint>

// ---------------- problem constants ----------------
// B=4, S=2048, D=4096, T=256, W=32, H=8, DH=512
#define DB   4
#define DS   2048
#define DD   4096
#define DT   256
#define DW   32
#define DH_  512
#define NH   8
#define NTOK (DB*DS)            // 8192
#define NQ   (DB*DT)            // 1024
#define SCL  0.044194173824159216f  // 1/sqrt(512)

typedef __nv_bfloat16 bf16;

// ---------------- device scratch (no allocations allowed) ----------------
__device__ float g_qkv  [ (long)NTOK * 3 * DD ];
__device__ float g_y    [ (long)NTOK * DD ];
__device__ float g_kvg  [ (long)NTOK * 2 * DD ];
__device__ float g_sc   [ (long)DB * NH * DT * DS ];
__device__ float g_yg   [ (long)NQ * DD ];
// bf16 split operands (hi / lo), 16B-aligned for cp.async
__device__ __align__(16) bf16 b_vlm_h  [(long)NTOK*DD],      b_vlm_l  [(long)NTOK*DD];
__device__ __align__(16) bf16 b_liw_h  [(long)3*DD*DD],      b_liw_l  [(long)3*DD*DD];
__device__ __align__(16) bf16 b_low_h  [(long)DD*DD],        b_low_l  [(long)DD*DD];
__device__ __align__(16) bf16 b_lpw_h  [(long)DD*DD],        b_lpw_l  [(long)DD*DD];
__device__ __align__(16) bf16 b_giw_h  [(long)3*DD*DD],      b_giw_l  [(long)3*DD*DD];
__device__ __align__(16) bf16 b_gow_h  [(long)DD*DD],        b_gow_l  [(long)DD*DD];
__device__ __align__(16) bf16 b_opw_h  [(long)DD*DD],        b_opw_l  [(long)DD*DD];
__device__ __align__(16) bf16 b_attnl_h[(long)NTOK*DD],      b_attnl_l[(long)NTOK*DD];
__device__ __align__(16) bf16 b_ln_h   [(long)NTOK*DD],      b_ln_l   [(long)NTOK*DD];
__device__ __align__(16) bf16 b_lf_h   [(long)NTOK*DD],      b_lf_l   [(long)NTOK*DD];
__device__ __align__(16) bf16 b_qtok_h [(long)DT*DD],        b_qtok_l [(long)DT*DD];
__device__ __align__(16) bf16 b_qg_h   [(long)DT*DD],        b_qg_l   [(long)DT*DD];
__device__ __align__(16) bf16 b_kvk_h  [(long)NTOK*DD],      b_kvk_l  [(long)NTOK*DD];
__device__ __align__(16) bf16 b_vt_h   [(long)DB*DD*DS],     b_vt_l   [(long)DB*DD*DS];
__device__ __align__(16) bf16 b_sc_h   [(long)DB*NH*DT*DS],  b_sc_l   [(long)DB*NH*DT*DS];
__device__ __align__(16) bf16 b_ag_h   [(long)NQ*DD],        b_ag_l   [(long)NQ*DD];
__device__ __align__(16) bf16 b_lng_h  [(long)NQ*DD],        b_lng_l  [(long)NQ*DD];

// ======================= helpers =======================
__device__ __forceinline__ uint32_t smem_u32(const void* p) {
    uint32_t a;
    asm("{ .reg .u64 t; cvta.to.shared.u64 t, %1; cvt.u32.u64 %0, t; }" : "=r"(a) : "l"(p));
    return a;
}
__device__ __forceinline__ void cp16(uint32_t dst, const void* src) {
    asm volatile("cp.async.cg.shared.global [%0], [%1], 16;" :: "r"(dst), "l"(src));
}
__device__ __forceinline__ void cp_commit() { asm volatile("cp.async.commit_group;" ::: "memory"); }
template <int N> __device__ __forceinline__ void cp_wait() {
    asm volatile("cp.async.wait_group %0;" :: "n"(N) : "memory");
}
__device__ __forceinline__ void ldsm4(uint32_t* r, uint32_t a) {
    asm volatile("ldmatrix.sync.aligned.m8n8.x4.shared.b16 {%0,%1,%2,%3}, [%4];"
        : "=r"(r[0]), "=r"(r[1]), "=r"(r[2]), "=r"(r[3]) : "r"(a));
}
__device__ __forceinline__ void mma16816(float* d, const uint32_t* a, const uint32_t* b) {
    asm volatile(
        "mma.sync.aligned.m16n8k16.row.col.f32.bf16.bf16.f32 "
        "{%0,%1,%2,%3}, {%4,%5,%6,%7}, {%8,%9}, {%0,%1,%2,%3};"
        : "+f"(d[0]), "+f"(d[1]), "+f"(d[2]), "+f"(d[3])
        : "r"(a[0]), "r"(a[1]), "r"(a[2]), "r"(a[3]), "r"(b[0]), "r"(b[1]));
}
__device__ __forceinline__ void split1(float v, bf16& h, bf16& l) {
    h = __float2bfloat16(v);
    l = __float2bfloat16(v - __bfloat162float(h));
}
// XOR swizzle: row pitch 64B, 16B unit c in 0..3; conflict-free 8-row ldmatrix groups
__device__ __forceinline__ uint32_t swz(int r, int c) {
    return (uint32_t)(r * 64 + ((c ^ ((r >> 1) & 3)) << 4));
}

// ======================= split-bf16 HMMA GEMM =======================
// C(M,N) = scale * (Ah+Al)(Bh+Bl)^T [3-product] + bias + res
// 128x128 tile, K-chunk 32, 3-stage cp.async, single __syncthreads/iter.
// 2 CTAs/SM (smem 96KB/CTA). Pitch 64B with XOR swizzle (16B aligned, conflict-free).
#define GSTG   32768
#define GSMEM  (3*GSTG)
#define OFF_AL 8192u
#define OFF_BH 16384u

__device__ __forceinline__ void load_chunk(
    uint32_t sb, int slot, long k0, int tid,
    const bf16* __restrict__ Ah, const bf16* __restrict__ Al, long lda, long bm,
    const bf16* __restrict__ Bh, const bf16* __restrict__ Bl, long ldb, long bn)
{
    uint32_t base = sb + (uint32_t)slot * GSTG;
    #pragma unroll
    for (int it = 0; it < 2; it++) {
        int u = tid + it * 256;            // 0..511
        int r = u >> 2, c = u & 3;         // row 0..127, 16B-col 0..3
        uint32_t off = swz(r, c);
        long srcA = (bm + r) * lda + k0 + c * 8;
        cp16(base + off,                    Ah + srcA);
        cp16(base + OFF_AL + off,           Al + srcA);
        long srcB = (bn + r) * ldb + k0 + c * 8;
        cp16(base + OFF_BH + off,           Bh + srcB);
        cp16(base + OFF_BH + OFF_AL + off,  Bl + srcB);
    }
    cp_commit();
}

__global__ __launch_bounds__(256, 2) void gemm_tc(
    const bf16* __restrict__ Ah, const bf16* __restrict__ Al, long lda,
    const bf16* __restrict__ Bh, const bf16* __restrict__ Bl, long ldb,
    float* __restrict__ C,
    bf16* __restrict__ Oh, bf16* __restrict__ Ol,
    long ldc,
    const float* __restrict__ bias,
    const float* __restrict__ res, int resMod, long resLd,
    int K, float scale, int nTm, int nTn,
    int zInner, long aIn, long aOut, long bIn, long bOut, long cIn, long cOut)
{
    extern __shared__ __align__(128) char smem[];
    const uint32_t sb = smem_u32(smem);
    const int tid = threadIdx.x;
    const int wid = tid >> 5;
    const int lane = tid & 31;

    const int z = blockIdx.z;
    const int zi = z % zInner, zo = z / zInner;
    Ah += (long)zi * aIn + (long)zo * aOut;  Al += (long)zi * aIn + (long)zo * aOut;
    Bh += (long)zi * bIn + (long)zo * bOut;  Bl += (long)zi * bIn + (long)zo * bOut;
    const long coff = (long)zi * cIn + (long)zo * cOut;
    if (C)  C  += coff;
    if (Oh) { Oh += coff; Ol += coff; }

    // L2-friendly rasterization: bands of 8 N-tiles
    const int idx = blockIdx.x;
    const int per = nTm * 8;
    const int band = idx / per, rem = idx % per;
    const long bm = (long)(rem % nTm) * 128;
    const long bn = (long)(band * 8 + rem / nTm) * 128;

    // warp layout: 4(M) x 2(N); warp tile 32x64
    const int wm = wid & 3;
    const int wn = wid >> 2;

    // per-lane fragment rows (swizzled offsets computed per access)
    const int aRow = wm * 32 + (lane & 15);           // + m*16
    const int aC0  = (lane >> 4);                      // + ks*2
    const int bRow = wn * 64 + (lane & 7) + ((lane >> 4) & 1) * 8;  // + p*16
    const int bC0  = ((lane >> 3) & 1);                // + ks*2

    float acc[2][8][4];
    #pragma unroll
    for (int i = 0; i < 2; i++)
        #pragma unroll
        for (int j = 0; j < 8; j++)
            #pragma unroll
            for (int q = 0; q < 4; q++) acc[i][j][q] = 0.f;

    const int nCh = K >> 5;        // K-chunk 32; all K divisible by 32
    load_chunk(sb, 0, 0,  tid, Ah, Al, lda, bm, Bh, Bl, ldb, bn);
    load_chunk(sb, 1, 32, tid, Ah, Al, lda, bm, Bh, Bl, ldb, bn);

    for (int i = 0; i < nCh; i++) {
        if (i + 1 < nCh) cp_wait<1>(); else cp_wait<0>();
        __syncthreads();
        if (i + 2 < nCh)
            load_chunk(sb, (i + 2) % 3, (long)(i + 2) * 32, tid,
                       Ah, Al, lda, bm, Bh, Bl, ldb, bn);
        const uint32_t stg = sb + (uint32_t)(i % 3) * GSTG;
        #pragma unroll
        for (int ks = 0; ks < 2; ks++) {
            uint32_t ah[2][4], al[2][4];
            #pragma unroll
            for (int m = 0; m < 2; m++) {
                uint32_t a = stg + swz(aRow + m * 16, aC0 + ks * 2);
                ldsm4(ah[m], a);
                ldsm4(al[m], a + OFF_AL);
            }
            #pragma unroll
            for (int p = 0; p < 4; p++) {
                uint32_t bh[4], bl[4];
                uint32_t a = stg + OFF_BH + swz(bRow + p * 16, bC0 + ks * 2);
                ldsm4(bh, a);
                ldsm4(bl, a + OFF_AL);        // Bl - Bh == OFF_AL
                #pragma unroll
                for (int m = 0; m < 2; m++)
                    #pragma unroll
                    for (int s = 0; s < 2; s++) {
                        const int nt = p * 2 + s;
                        mma16816(acc[m][nt], ah[m], &bh[s * 2]);
                        mma16816(acc[m][nt], al[m], &bh[s * 2]);
                        mma16816(acc[m][nt], ah[m], &bl[s * 2]);
                    }
            }
        }
    }

    // ---- epilogue: fused scale/bias/residual; fp32 and/or bf16-split out ----
    const int r0 = lane >> 2;
    const int c0 = (lane & 3) * 2;
    #pragma unroll
    for (int m = 0; m < 2; m++) {
        #pragma unroll
        for (int half = 0; half < 2; half++) {
            const long grow = bm + wm * 32 + m * 16 + r0 + half * 8;
            const long rrow = (grow % resMod) * resLd;
            #pragma unroll
            for (int nt = 0; nt < 8; nt++) {
                const long gcol = bn + wn * 64 + nt * 8 + c0;
                float vx = acc[m][nt][half * 2]     * scale;
                float vy = acc[m][nt][half * 2 + 1] * scale;
                if (bias) {
                    float2 bb = *(const float2*)&bias[gcol];
                    vx += bb.x; vy += bb.y;
                }
                if (res) {
                    float2 rr = *(const float2*)&res[rrow + gcol];
                    vx += rr.x; vy += rr.y;
                }
                if (C) {
                    float2 v; v.x = vx; v.y = vy;
                    *(float2*)&C[grow * ldc + gcol] = v;
                }
                if (Oh) {
                    bf16 hx, lx, hy, ly;
                    split1(vx, hx, lx); split1(vy, hy, ly);
                    __nv_bfloat162 hv; hv.x = hx; hv.y = hy;
                    __nv_bfloat162 lv; lv.x = lx; lv.y = ly;
                    *(__nv_bfloat162*)&Oh[grow * ldc + gcol] = hv;
                    *(__nv_bfloat162*)&Ol[grow * ldc + gcol] = lv;
                }
            }
        }
    }
}

// ======================= split / transpose conversions =======================
__global__ __launch_bounds__(256) void split_mat(
    const float* __restrict__ in, long ldIn,
    bf16* __restrict__ oh, bf16* __restrict__ ol, long ldOut,
    int cols4, long total4)
{
    long idx = (long)blockIdx.x * 256 + threadIdx.x;
    if (idx >= total4) return;
    long r = idx / cols4;
    int  c = (int)(idx - r * cols4);
    float4 v = *(const float4*)(in + r * ldIn + c * 4);
    bf16 h0, h1, h2, h3, l0, l1, l2, l3;
    split1(v.x, h0, l0); split1(v.y, h1, l1);
    split1(v.z, h2, l2); split1(v.w, h3, l3);
    __nv_bfloat162* ph = (__nv_bfloat162*)(oh + r * ldOut + c * 4);
    __nv_bfloat162* pl = (__nv_bfloat162*)(ol + r * ldOut + c * 4);
    __nv_bfloat162 a; a.x = h0; a.y = h1; ph[0] = a;
    a.x = h2; a.y = h3; ph[1] = a;
    a.x = l0; a.y = l1; pl[0] = a;
    a.x = l2; a.y = l3; pl[1] = a;
}

// V part of kvg -> transposed split: vt[(b*4096+d)*2048 + s]
__global__ __launch_bounds__(256) void vtrans_split(
    const float* __restrict__ kvg, bf16* __restrict__ vh, bf16* __restrict__ vl)
{
    __shared__ float tile[32][33];
    const int s0 = blockIdx.x * 32, d0 = blockIdx.y * 32, b = blockIdx.z;
    const int tx = threadIdx.x & 31, ty = threadIdx.x >> 5;
    #pragma unroll
    for (int j = 0; j < 4; j++) {
        int s = s0 + ty + j * 8;
        tile[ty + j * 8][tx] = kvg[((long)b * DS + s) * (2 * DD) + DD + d0 + tx];
    }
    __syncthreads();
    #pragma unroll
    for (int j = 0; j < 4; j++) {
        int d = d0 + ty + j * 8;
        float v = tile[tx][ty + j * 8];
        bf16 h, l; split1(v, h, l);
        long o = ((long)b * DD + d) * DS + s0 + tx;
        vh[o] = h; vl[o] = l;
    }
}

// ======================= reductions =======================
__device__ __forceinline__ float blockSum(float val) {
    __shared__ float sh[32];
    int lane = threadIdx.x & 31, w = threadIdx.x >> 5;
    #pragma unroll
    for (int o = 16; o; o >>= 1) val += __shfl_xor_sync(0xffffffffu, val, o);
    __syncthreads();
    if (lane == 0) sh[w] = val;
    __syncthreads();
    val = (lane < 8) ? sh[lane] : 0.f;
    #pragma unroll
    for (int o = 4; o; o >>= 1) val += __shfl_xor_sync(0xffffffffu, val, o);
    return __shfl_sync(0xffffffffu, val, 0);
}
__device__ __forceinline__ float blockMax(float val) {
    __shared__ float sh[32];
    int lane = threadIdx.x & 31, w = threadIdx.x >> 5;
    #pragma unroll
    for (int o = 16; o; o >>= 1) val = fmaxf(val, __shfl_xor_sync(0xffffffffu, val, o));
    __syncthreads();
    if (lane == 0) sh[w] = val;
    __syncthreads();
    val = (lane < 8) ? sh[lane] : -3.4e38f;
    #pragma unroll
    for (int o = 4; o; o >>= 1) val = fmaxf(val, __shfl_xor_sync(0xffffffffu, val, o));
    return __shfl_sync(0xffffffffu, val, 0);
}

// ---------------- local windowed attention: fp32 qkv -> bf16-split out ----------------
__global__ __launch_bounds__(256) void local_attn(
    const float* __restrict__ qkv, const int* __restrict__ mask,
    bf16* __restrict__ outH, bf16* __restrict__ outL)
{
    const int  bw   = blockIdx.x;
    const int  h    = blockIdx.y;
    const long tok0 = (long)bw * DW;
    const int  LD   = 3 * DD;
    const float* qb = qkv + tok0 * LD + h * DH_;
    const float* kb = qkv + tok0 * LD + DD + h * DH_;
    const float* vb = qkv + tok0 * LD + 2 * DD + h * DH_;

    __shared__ float s[DW][DW + 1];
    __shared__ float msk[DW];
    const int tid = threadIdx.x;
    if (tid < DW) msk[tid] = (mask[tok0 + tid] != 0) ? 0.f : -1e9f;

    #pragma unroll
    for (int p = tid; p < DW * DW; p += 256) {
        int i = p >> 5, j = p & 31;
        const float4* qp = (const float4*)(qb + (long)i * LD);
        const float4* kp = (const float4*)(kb + (long)j * LD);
        float acc = 0.f;
        #pragma unroll 8
        for (int d = 0; d < DH_ / 4; d++) {
            float4 a = qp[d], c = kp[d];
            acc += a.x * c.x + a.y * c.y + a.z * c.z + a.w * c.w;
        }
        s[i][j] = acc;
    }
    __syncthreads();

    if (tid < DW) {
        const int i = tid;
        const float mi = msk[i];
        float r[DW];
        float mx = -3.4e38f;
        #pragma unroll
        for (int j = 0; j < DW; j++) {
            float bias = (mi + msk[j] < -0.5f) ? -1e9f : 0.f;
            r[j] = s[i][j] * SCL + bias;
            mx = fmaxf(mx, r[j]);
        }
        float sum = 0.f;
        #pragma unroll
        for (int j = 0; j < DW; j++) { r[j] = expf(r[j] - mx); sum += r[j]; }
        const float inv = 1.f / sum;
        #pragma unroll
        for (int j = 0; j < DW; j++) s[i][j] = r[j] * inv;
    }
    __syncthreads();

    float2 acc[DW];
    #pragma unroll
    for (int i = 0; i < DW; i++) acc[i] = make_float2(0.f, 0.f);
    for (int j = 0; j < DW; j++) {
        float2 v2 = *(const float2*)(vb + (long)j * LD + tid * 2);
        #pragma unroll
        for (int i = 0; i < DW; i++) {
            float w = s[i][j];
            acc[i].x += w * v2.x;
            acc[i].y += w * v2.y;
        }
    }
    const long obase = tok0 * DD + h * DH_ + tid * 2;
    #pragma unroll
    for (int i = 0; i < DW; i++) {
        bf16 hx, lx, hy, ly;
        split1(acc[i].x, hx, lx); split1(acc[i].y, hy, ly);
        __nv_bfloat162 hv; hv.x = hx; hv.y = hy;
        __nv_bfloat162 lv; lv.x = lx; lv.y = ly;
        *(__nv_bfloat162*)&outH[obase + (long)i * DD] = hv;
        *(__nv_bfloat162*)&outL[obase + (long)i * DD] = lv;
    }
}

// ---------------- LayerNorm over rows of 4096 -> bf16 split out ----------------
__global__ __launch_bounds__(256) void layernorm_bf(
    const float* __restrict__ X, const float* __restrict__ g,
    const float* __restrict__ b, bf16* __restrict__ Yh, bf16* __restrict__ Yl)
{
    const long row = blockIdx.x;
    const float* x = X + row * DD;
    float v[16];
    float s = 0.f;
    #pragma unroll
    for (int i = 0; i < 16; i++) { v[i] = x[threadIdx.x + i * 256]; s += v[i]; }
    const float mean = blockSum(s) * (1.f / DD);
    float d2 = 0.f;
    #pragma unroll
    for (int i = 0; i < 16; i++) { float d = v[i] - mean; d2 += d * d; }
    const float var = blockSum(d2) * (1.f / DD);
    const float rs = rsqrtf(var + 1e-5f);
    #pragma unroll
    for (int i = 0; i < 16; i++) {
        int c = threadIdx.x + i * 256;
        float o = (v[i] - mean) * rs * g[c] + b[c];
        bf16 h, l; split1(o, h, l);
        Yh[row * DD + c] = h;
        Yl[row * DD + c] = l;
    }
}

// ---------------- global softmax over S=2048 keys -> bf16 split out ----------------
__global__ __launch_bounds__(256) void softmax_bf(
    const float* __restrict__ sc, const int* __restrict__ mask,
    bf16* __restrict__ oh, bf16* __restrict__ ol)
{
    const long row = blockIdx.x;
    const int  b   = (int)(row >> 11);
    const float* x = sc + row * DS;
    const int* m = mask + (long)b * DS;
    float v[8];
    float mx = -3.4e38f;
    #pragma unroll
    for (int i = 0; i < 8; i++) {
        int c = threadIdx.x + i * 256;
        float t = x[c] + ((m[c] != 0) ? 0.f : -1e9f);
        v[i] = t;
        mx = fmaxf(mx, t);
    }
    mx = blockMax(mx);
    float s = 0.f;
    #pragma unroll
    for (int i = 0; i < 8; i++) { v[i] = expf(v[i] - mx); s += v[i]; }
    s = blockSum(s);
    const float inv = 1.f / s;
    #pragma unroll
    for (int i = 0; i < 8; i++) {
        int c = threadIdx.x + i * 256;
        bf16 h, l; split1(v[i] * inv, h, l);
        oh[row * DS + c] = h;
        ol[row * DS + c] = l;
    }
}

// ======================= launch =======================
static void split_full(const float* in, bf16* oh, bf16* ol, long rows, long cols) {
    long total4 = rows * (cols / 4);
    split_mat<<<(unsigned)((total4 + 255) / 256), 256>>>(in, cols, oh, ol, cols, (int)(cols / 4), total4);
}

extern "C" void kernel_launch(void* const* d_in, const int* in_sizes, int n_in,
                              void* d_out, int out_size)
{
    const float* vlm    = (const float*)d_in[0];
    const int*   mask   = (const int*)d_in[1];
    const float* l_in_w = (const float*)d_in[2];
    const float* l_in_b = (const float*)d_in[3];
    const float* l_out_w= (const float*)d_in[4];
    const float* l_out_b= (const float*)d_in[5];
    const float* l_ng   = (const float*)d_in[6];
    const float* l_nb   = (const float*)d_in[7];
    const float* l_pw   = (const float*)d_in[8];
    const float* l_pb   = (const float*)d_in[9];
    const float* g_in_w = (const float*)d_in[10];
    const float* g_in_b = (const float*)d_in[11];
    const float* g_out_w= (const float*)d_in[12];
    const float* g_out_b= (const float*)d_in[13];
    const float* g_ng   = (const float*)d_in[14];
    const float* g_nb   = (const float*)d_in[15];
    const float* qtok   = (const float*)d_in[16];
    const float* o_pw   = (const float*)d_in[17];
    const float* o_pb   = (const float*)d_in[18];
    float* out = (float*)d_out;

    cudaFuncSetAttribute(gemm_tc, cudaFuncAttributeMaxDynamicSharedMemorySize, GSMEM);

    float *p_qkv, *p_y, *p_kvg, *p_sc, *p_yg;
    cudaGetSymbolAddress((void**)&p_qkv, g_qkv);
    cudaGetSymbolAddress((void**)&p_y,   g_y);
    cudaGetSymbolAddress((void**)&p_kvg, g_kvg);
    cudaGetSymbolAddress((void**)&p_sc,  g_sc);
    cudaGetSymbolAddress((void**)&p_yg,  g_yg);

    bf16 *vlm_h,*vlm_l,*liw_h,*liw_l,*low_h,*low_l,*lpw_h,*lpw_l,*giw_h,*giw_l,
         *gow_h,*gow_l,*opw_h,*opw_l,*attnl_h,*attnl_l,*ln_h,*ln_l,*lf_h,*lf_l,
         *qtok_h,*qtok_l,*qg_h,*qg_l,*kvk_h,*kvk_l,*vt_h,*vt_l,*sc_h,*sc_l,
         *ag_h,*ag_l,*lng_h,*lng_l;
    cudaGetSymbolAddress((void**)&vlm_h, b_vlm_h);   cudaGetSymbolAddress((void**)&vlm_l, b_vlm_l);
    cudaGetSymbolAddress((void**)&liw_h, b_liw_h);   cudaGetSymbolAddress((void**)&liw_l, b_liw_l);
    cudaGetSymbolAddress((void**)&low_h, b_low_h);   cudaGetSymbolAddress((void**)&low_l, b_low_l);
    cudaGetSymbolAddress((void**)&lpw_h, b_lpw_h);   cudaGetSymbolAddress((void**)&lpw_l, b_lpw_l);
    cudaGetSymbolAddress((void**)&giw_h, b_giw_h);   cudaGetSymbolAddress((void**)&giw_l, b_giw_l);
    cudaGetSymbolAddress((void**)&gow_h, b_gow_h);   cudaGetSymbolAddress((void**)&gow_l, b_gow_l);
    cudaGetSymbolAddress((void**)&opw_h, b_opw_h);   cudaGetSymbolAddress((void**)&opw_l, b_opw_l);
    cudaGetSymbolAddress((void**)&attnl_h, b_attnl_h); cudaGetSymbolAddress((void**)&attnl_l, b_attnl_l);
    cudaGetSymbolAddress((void**)&ln_h,  b_ln_h);    cudaGetSymbolAddress((void**)&ln_l,  b_ln_l);
    cudaGetSymbolAddress((void**)&lf_h,  b_lf_h);    cudaGetSymbolAddress((void**)&lf_l,  b_lf_l);
    cudaGetSymbolAddress((void**)&qtok_h,b_qtok_h);  cudaGetSymbolAddress((void**)&qtok_l,b_qtok_l);
    cudaGetSymbolAddress((void**)&qg_h,  b_qg_h);    cudaGetSymbolAddress((void**)&qg_l,  b_qg_l);
    cudaGetSymbolAddress((void**)&kvk_h, b_kvk_h);   cudaGetSymbolAddress((void**)&kvk_l, b_kvk_l);
    cudaGetSymbolAddress((void**)&vt_h,  b_vt_h);    cudaGetSymbolAddress((void**)&vt_l,  b_vt_l);
    cudaGetSymbolAddress((void**)&sc_h,  b_sc_h);    cudaGetSymbolAddress((void**)&sc_l,  b_sc_l);
    cudaGetSymbolAddress((void**)&ag_h,  b_ag_h);    cudaGetSymbolAddress((void**)&ag_l,  b_ag_l);
    cudaGetSymbolAddress((void**)&lng_h, b_lng_h);   cudaGetSymbolAddress((void**)&lng_l, b_lng_l);

    const dim3 T256(256);
    #define GEMM(Ah,Al,lda,Bh,Bl,ldb,C,Oh,Ol,ldc,bias,res,resMod,resLd,K,scale,M,N,zTot,zInner,aIn,aOut,bIn,bOut,cIn,cOut) \
        gemm_tc<<<dim3(((M)/128)*((N)/128), 1, zTot), T256, GSMEM>>>( \
            Ah, Al, lda, Bh, Bl, ldb, C, Oh, Ol, ldc, bias, res, resMod, resLd, \
            K, scale, (M)/128, (N)/128, zInner, aIn, aOut, bIn, bOut, cIn, cOut)
    #define NOF (const float*)nullptr
    #define NOC (float*)nullptr
    #define NOB (bf16*)nullptr

    // input/weight splits
    split_full(vlm,     vlm_h,  vlm_l,  NTOK,   DD);
    split_full(l_in_w,  liw_h,  liw_l,  3*DD,   DD);
    split_full(l_out_w, low_h,  low_l,  DD,     DD);
    split_full(l_pw,    lpw_h,  lpw_l,  DD,     DD);
    split_full(g_in_w,  giw_h,  giw_l,  3*DD,   DD);
    split_full(g_out_w, gow_h,  gow_l,  DD,     DD);
    split_full(o_pw,    opw_h,  opw_l,  DD,     DD);
    split_full(qtok,    qtok_h, qtok_l, DT,     DD);

    // 1) local QKV: (8192 x 12288), fp32 out (consumed by local_attn)
    GEMM(vlm_h, vlm_l, DD, liw_h, liw_l, DD, p_qkv, NOB, NOB, 3*DD, l_in_b,
         NOF, 1, 1, DD, 1.f, NTOK, 3*DD, 1, 1, 0,0,0,0,0,0);

    // 2) local windowed attention -> bf16 split directly
    local_attn<<<dim3(DB * (DS / DW), NH), T256>>>(p_qkv, mask, attnl_h, attnl_l);

    // 3) local out_proj + residual(vlm), fp32 out (consumed by LN)
    GEMM(attnl_h, attnl_l, DD, low_h, low_l, DD, p_y, NOB, NOB, DD, l_out_b,
         vlm, NTOK, DD, DD, 1.f, NTOK, DD, 1, 1, 0,0,0,0,0,0);

    // 4) LN local -> bf16 split directly
    layernorm_bf<<<NTOK, T256>>>(p_y, l_ng, l_nb, ln_h, ln_l);

    // 5) local_proj -> local_features (bf16 split only)
    GEMM(ln_h, ln_l, DD, lpw_h, lpw_l, DD, NOC, lf_h, lf_l, DD, l_pb,
         NOF, 1, 1, DD, 1.f, NTOK, DD, 1, 1, 0,0,0,0,0,0);

    // 6) global q (batch-invariant, bf16 split only)
    GEMM(qtok_h, qtok_l, DD, giw_h, giw_l, DD, NOC, qg_h, qg_l, DD, g_in_b,
         NOF, 1, 1, DD, 1.f, DT, DD, 1, 1, 0,0,0,0,0,0);

    // 7) global k,v (fp32 out; consumed by split + vtrans)
    GEMM(lf_h, lf_l, DD, giw_h + (long)DD*DD, giw_l + (long)DD*DD, DD,
         p_kvg, NOB, NOB, 2*DD, g_in_b + DD,
         NOF, 1, 1, DD, 1.f, NTOK, 2*DD, 1, 1, 0,0,0,0,0,0);

    // split K half (compact ld 4096), transpose-split V half
    {
        long total4 = (long)NTOK * (DD / 4);
        split_mat<<<(unsigned)((total4 + 255) / 256), 256>>>(
            p_kvg, 2*DD, kvk_h, kvk_l, DD, DD / 4, total4);
    }
    vtrans_split<<<dim3(DS/32, DD/32, DB), T256>>>(p_kvg, vt_h, vt_l);

    // 8) scores (batched 32): (256 x 2048 x 512), scaled, fp32 out
    GEMM(qg_h, qg_l, DD, kvk_h, kvk_l, DD, p_sc, NOB, NOB, DS,
         NOF, NOF, 1, 1,
         DH_, SCL, DT, DS, DB*NH, NH,
         /*aIn*/DH_, /*aOut*/0,
         /*bIn*/DH_, /*bOut*/(long)DS * DD,
         /*cIn*/(long)DT * DS, /*cOut*/(long)NH * DT * DS);

    // 9) softmax over keys -> bf16 split directly
    softmax_bf<<<DB * NH * DT, T256>>>(p_sc, mask, sc_h, sc_l);

    // 10) AV (batched 32): (256 x 512 x 2048), bf16 split only
    GEMM(sc_h, sc_l, DS, vt_h, vt_l, DS, NOC, ag_h, ag_l, DD,
         NOF, NOF, 1, 1,
         DS, 1.f, DT, DH_, DB*NH, NH,
         /*aIn*/(long)DT * DS, /*aOut*/(long)NH * DT * DS,
         /*bIn*/(long)DH_ * DS, /*bOut*/(long)DD * DS,
         /*cIn*/DH_, /*cOut*/(long)DT * DD);

    // 11) global out_proj + residual(query_tokens broadcast), fp32 out
    GEMM(ag_h, ag_l, DD, gow_h, gow_l, DD, p_yg, NOB, NOB, DD, g_out_b,
         qtok, DT, DD, DD, 1.f, NQ, DD, 1, 1, 0,0,0,0,0,0);

    // 12) LN global -> bf16 split directly
    layernorm_bf<<<NQ, T256>>>(p_yg, g_ng, g_nb, lng_h, lng_l);

    // 13) output_proj -> d_out (fp32)
    GEMM(lng_h, lng_l, DD, opw_h, opw_l, DD, out, NOB, NOB, DD, o_pb,
         NOF, 1, 1, DD, 1.f, NQ, DD, 1, 1, 0,0,0,0,0,0);
}

// round 9
// speedup vs baseline: 3.8278x; 1.3478x over previous
#include <cuda_runtime.h>
#include <cuda_fp16.h>
#include <cstdint>

// ---------------- problem constants ----------------
// B=4, S=2048, D=4096, T=256, W=32, H=8, DH=512
#define DB   4
#define DS   2048
#define DD   4096
#define DT   256
#define DW   32
#define DH_  512
#define NH   8
#define NTOK (DB*DS)            // 8192
#define NQ   (DB*DT)            // 1024
#define SCL  0.044194173824159216f  // 1/sqrt(512)

typedef __half hf;

// ---------------- device scratch (no allocations allowed) ----------------
__device__ float g_qkv  [ (long)NTOK * 3 * DD ];
__device__ float g_y    [ (long)NTOK * DD ];
__device__ float g_kvg  [ (long)NTOK * 2 * DD ];
__device__ float g_sc   [ (long)DB * NH * DT * DS ];
__device__ float g_yg   [ (long)NQ * DD ];
// fp16 split operands: hi for everything; lo only for A-role matrices
__device__ __align__(16) hf b_vlm_h  [(long)NTOK*DD],      b_vlm_l  [(long)NTOK*DD];
__device__ __align__(16) hf b_liw_h  [(long)3*DD*DD];
__device__ __align__(16) hf b_low_h  [(long)DD*DD];
__device__ __align__(16) hf b_lpw_h  [(long)DD*DD];
__device__ __align__(16) hf b_giw_h  [(long)3*DD*DD];
__device__ __align__(16) hf b_gow_h  [(long)DD*DD];
__device__ __align__(16) hf b_opw_h  [(long)DD*DD];
__device__ __align__(16) hf b_attnl_h[(long)NTOK*DD],      b_attnl_l[(long)NTOK*DD];
__device__ __align__(16) hf b_ln_h   [(long)NTOK*DD],      b_ln_l   [(long)NTOK*DD];
__device__ __align__(16) hf b_lf_h   [(long)NTOK*DD],      b_lf_l   [(long)NTOK*DD];
__device__ __align__(16) hf b_qtok_h [(long)DT*DD],        b_qtok_l [(long)DT*DD];
__device__ __align__(16) hf b_qg_h   [(long)DT*DD],        b_qg_l   [(long)DT*DD];
__device__ __align__(16) hf b_kvk_h  [(long)NTOK*DD];                    // B-role only
__device__ __align__(16) hf b_vt_h   [(long)DB*DD*DS];                   // B-role only
__device__ __align__(16) hf b_sc_h   [(long)DB*NH*DT*DS],  b_sc_l   [(long)DB*NH*DT*DS];
__device__ __align__(16) hf b_ag_h   [(long)NQ*DD],        b_ag_l   [(long)NQ*DD];
__device__ __align__(16) hf b_lng_h  [(long)NQ*DD],        b_lng_l  [(long)NQ*DD];

// ======================= helpers =======================
__device__ __forceinline__ uint32_t smem_u32(const void* p) {
    uint32_t a;
    asm("{ .reg .u64 t; cvta.to.shared.u64 t, %1; cvt.u32.u64 %0, t; }" : "=r"(a) : "l"(p));
    return a;
}
__device__ __forceinline__ void cp16(uint32_t dst, const void* src) {
    asm volatile("cp.async.cg.shared.global [%0], [%1], 16;" :: "r"(dst), "l"(src));
}
__device__ __forceinline__ void cp_commit() { asm volatile("cp.async.commit_group;" ::: "memory"); }
template <int N> __device__ __forceinline__ void cp_wait() {
    asm volatile("cp.async.wait_group %0;" :: "n"(N) : "memory");
}
__device__ __forceinline__ void ldsm4(uint32_t* r, uint32_t a) {
    asm volatile("ldmatrix.sync.aligned.m8n8.x4.shared.b16 {%0,%1,%2,%3}, [%4];"
        : "=r"(r[0]), "=r"(r[1]), "=r"(r[2]), "=r"(r[3]) : "r"(a));
}
// D += A*B  (m16n8k16, fp16 in, fp32 acc)
__device__ __forceinline__ void mma16816(float* d, const uint32_t* a, const uint32_t* b) {
    asm volatile(
        "mma.sync.aligned.m16n8k16.row.col.f32.f16.f16.f32 "
        "{%0,%1,%2,%3}, {%4,%5,%6,%7}, {%8,%9}, {%0,%1,%2,%3};"
        : "+f"(d[0]), "+f"(d[1]), "+f"(d[2]), "+f"(d[3])
        : "r"(a[0]), "r"(a[1]), "r"(a[2]), "r"(a[3]), "r"(b[0]), "r"(b[1]));
}
__device__ __forceinline__ void split1(float v, hf& h, hf& l) {
    h = __float2half_rn(v);
    l = __float2half_rn(v - __half2float(h));
}
// XOR swizzle: row pitch 64B, 16B unit c in 0..3; conflict-free 8-row ldmatrix groups
__device__ __forceinline__ uint32_t swz(int r, int c) {
    return (uint32_t)(r * 64 + ((c ^ ((r >> 1) & 3)) << 4));
}

// ======================= fp16x2 HMMA GEMM =======================
// C(M,N) = scale * (Ah+Al) @ Bh^T [2-product fp16] + bias + res
// 128x128 tile, K-chunk 32, 3-stage cp.async, single __syncthreads/iter, 2 CTAs/SM.
// stage (24KB): Ah[128][32] Al Bh[128][32], pitch 64B, XOR-swizzled.
#define GSTG   24576
#define GSMEM  (3*GSTG)
#define OFF_AL 8192u
#define OFF_BH 16384u

__device__ __forceinline__ void load_chunk(
    uint32_t sb, int slot, long k0, int tid,
    const hf* __restrict__ Ah, const hf* __restrict__ Al, long lda, long bm,
    const hf* __restrict__ Bh, long ldb, long bn)
{
    uint32_t base = sb + (uint32_t)slot * GSTG;
    #pragma unroll
    for (int it = 0; it < 2; it++) {
        int u = tid + it * 256;            // 0..511
        int r = u >> 2, c = u & 3;         // row 0..127, 16B-col 0..3
        uint32_t off = swz(r, c);
        long srcA = (bm + r) * lda + k0 + c * 8;
        cp16(base + off,          Ah + srcA);
        cp16(base + OFF_AL + off, Al + srcA);
        cp16(base + OFF_BH + off, Bh + (bn + r) * ldb + k0 + c * 8);
    }
    cp_commit();
}

__global__ __launch_bounds__(256, 2) void gemm_tc(
    const hf* __restrict__ Ah, const hf* __restrict__ Al, long lda,
    const hf* __restrict__ Bh, long ldb,
    float* __restrict__ C,
    hf* __restrict__ Oh, hf* __restrict__ Ol,
    long ldc,
    const float* __restrict__ bias,
    const float* __restrict__ res, int resMod, long resLd,
    int K, float scale, int nTm, int nTn,
    int zInner, long aIn, long aOut, long bIn, long bOut, long cIn, long cOut)
{
    extern __shared__ __align__(128) char smem[];
    const uint32_t sb = smem_u32(smem);
    const int tid = threadIdx.x;
    const int wid = tid >> 5;
    const int lane = tid & 31;

    const int z = blockIdx.z;
    const int zi = z % zInner, zo = z / zInner;
    Ah += (long)zi * aIn + (long)zo * aOut;  Al += (long)zi * aIn + (long)zo * aOut;
    Bh += (long)zi * bIn + (long)zo * bOut;
    const long coff = (long)zi * cIn + (long)zo * cOut;
    if (C)  C  += coff;
    if (Oh) { Oh += coff; Ol += coff; }

    // L2-friendly rasterization: bands of 8 N-tiles
    const int idx = blockIdx.x;
    const int per = nTm * 8;
    const int band = idx / per, rem = idx % per;
    const long bm = (long)(rem % nTm) * 128;
    const long bn = (long)(band * 8 + rem / nTm) * 128;

    // warp layout: 4(M) x 2(N); warp tile 32x64
    const int wm = wid & 3;
    const int wn = wid >> 2;

    const int aRow = wm * 32 + (lane & 15);           // + m*16
    const int aC0  = (lane >> 4);                      // + ks*2
    const int bRow = wn * 64 + (lane & 7) + ((lane >> 4) & 1) * 8;  // + p*16
    const int bC0  = ((lane >> 3) & 1);                // + ks*2

    float acc[2][8][4];
    #pragma unroll
    for (int i = 0; i < 2; i++)
        #pragma unroll
        for (int j = 0; j < 8; j++)
            #pragma unroll
            for (int q = 0; q < 4; q++) acc[i][j][q] = 0.f;

    const int nCh = K >> 5;        // K-chunk 32; all K divisible by 32
    load_chunk(sb, 0, 0,  tid, Ah, Al, lda, bm, Bh, ldb, bn);
    load_chunk(sb, 1, 32, tid, Ah, Al, lda, bm, Bh, ldb, bn);

    for (int i = 0; i < nCh; i++) {
        if (i + 1 < nCh) cp_wait<1>(); else cp_wait<0>();
        __syncthreads();
        if (i + 2 < nCh)
            load_chunk(sb, (i + 2) % 3, (long)(i + 2) * 32, tid,
                       Ah, Al, lda, bm, Bh, ldb, bn);
        const uint32_t stg = sb + (uint32_t)(i % 3) * GSTG;
        #pragma unroll
        for (int ks = 0; ks < 2; ks++) {
            uint32_t ah[2][4], al[2][4];
            #pragma unroll
            for (int m = 0; m < 2; m++) {
                uint32_t a = stg + swz(aRow + m * 16, aC0 + ks * 2);
                ldsm4(ah[m], a);
                ldsm4(al[m], a + OFF_AL);
            }
            #pragma unroll
            for (int p = 0; p < 4; p++) {
                uint32_t bh[4];
                ldsm4(bh, stg + OFF_BH + swz(bRow + p * 16, bC0 + ks * 2));
                #pragma unroll
                for (int m = 0; m < 2; m++)
                    #pragma unroll
                    for (int s = 0; s < 2; s++) {
                        const int nt = p * 2 + s;
                        mma16816(acc[m][nt], ah[m], &bh[s * 2]);
                        mma16816(acc[m][nt], al[m], &bh[s * 2]);
                    }
            }
        }
    }

    // ---- epilogue: fused scale/bias/residual; fp32 and/or fp16-split out ----
    const int r0 = lane >> 2;
    const int c0 = (lane & 3) * 2;
    #pragma unroll
    for (int m = 0; m < 2; m++) {
        #pragma unroll
        for (int half = 0; half < 2; half++) {
            const long grow = bm + wm * 32 + m * 16 + r0 + half * 8;
            const long rrow = (grow % resMod) * resLd;
            #pragma unroll
            for (int nt = 0; nt < 8; nt++) {
                const long gcol = bn + wn * 64 + nt * 8 + c0;
                float vx = acc[m][nt][half * 2]     * scale;
                float vy = acc[m][nt][half * 2 + 1] * scale;
                if (bias) {
                    float2 bb = *(const float2*)&bias[gcol];
                    vx += bb.x; vy += bb.y;
                }
                if (res) {
                    float2 rr = *(const float2*)&res[rrow + gcol];
                    vx += rr.x; vy += rr.y;
                }
                if (C) {
                    float2 v; v.x = vx; v.y = vy;
                    *(float2*)&C[grow * ldc + gcol] = v;
                }
                if (Oh) {
                    hf hx, lx, hy, ly;
                    split1(vx, hx, lx); split1(vy, hy, ly);
                    __half2 hv; hv.x = hx; hv.y = hy;
                    __half2 lv; lv.x = lx; lv.y = ly;
                    *(__half2*)&Oh[grow * ldc + gcol] = hv;
                    *(__half2*)&Ol[grow * ldc + gcol] = lv;
                }
            }
        }
    }
}

// ======================= split / transpose conversions =======================
// ol may be null (B-role matrices: hi only)
__global__ __launch_bounds__(256) void split_mat(
    const float* __restrict__ in, long ldIn,
    hf* __restrict__ oh, hf* __restrict__ ol, long ldOut,
    int cols4, long total4)
{
    long idx = (long)blockIdx.x * 256 + threadIdx.x;
    if (idx >= total4) return;
    long r = idx / cols4;
    int  c = (int)(idx - r * cols4);
    float4 v = *(const float4*)(in + r * ldIn + c * 4);
    hf h0, h1, h2, h3, l0, l1, l2, l3;
    split1(v.x, h0, l0); split1(v.y, h1, l1);
    split1(v.z, h2, l2); split1(v.w, h3, l3);
    __half2* ph = (__half2*)(oh + r * ldOut + c * 4);
    __half2 a; a.x = h0; a.y = h1; ph[0] = a;
    a.x = h2; a.y = h3; ph[1] = a;
    if (ol) {
        __half2* pl = (__half2*)(ol + r * ldOut + c * 4);
        a.x = l0; a.y = l1; pl[0] = a;
        a.x = l2; a.y = l3; pl[1] = a;
    }
}

// V part of kvg -> transposed hi: vt[(b*4096+d)*2048 + s]
__global__ __launch_bounds__(256) void vtrans_split(
    const float* __restrict__ kvg, hf* __restrict__ vh)
{
    __shared__ float tile[32][33];
    const int s0 = blockIdx.x * 32, d0 = blockIdx.y * 32, b = blockIdx.z;
    const int tx = threadIdx.x & 31, ty = threadIdx.x >> 5;
    #pragma unroll
    for (int j = 0; j < 4; j++) {
        int s = s0 + ty + j * 8;
        tile[ty + j * 8][tx] = kvg[((long)b * DS + s) * (2 * DD) + DD + d0 + tx];
    }
    __syncthreads();
    #pragma unroll
    for (int j = 0; j < 4; j++) {
        int d = d0 + ty + j * 8;
        long o = ((long)b * DD + d) * DS + s0 + tx;
        vh[o] = __float2half_rn(tile[tx][ty + j * 8]);
    }
}

// ======================= reductions =======================
__device__ __forceinline__ float blockSum(float val) {
    __shared__ float sh[32];
    int lane = threadIdx.x & 31, w = threadIdx.x >> 5;
    #pragma unroll
    for (int o = 16; o; o >>= 1) val += __shfl_xor_sync(0xffffffffu, val, o);
    __syncthreads();
    if (lane == 0) sh[w] = val;
    __syncthreads();
    val = (lane < 8) ? sh[lane] : 0.f;
    #pragma unroll
    for (int o = 4; o; o >>= 1) val += __shfl_xor_sync(0xffffffffu, val, o);
    return __shfl_sync(0xffffffffu, val, 0);
}
__device__ __forceinline__ float blockMax(float val) {
    __shared__ float sh[32];
    int lane = threadIdx.x & 31, w = threadIdx.x >> 5;
    #pragma unroll
    for (int o = 16; o; o >>= 1) val = fmaxf(val, __shfl_xor_sync(0xffffffffu, val, o));
    __syncthreads();
    if (lane == 0) sh[w] = val;
    __syncthreads();
    val = (lane < 8) ? sh[lane] : -3.4e38f;
    #pragma unroll
    for (int o = 4; o; o >>= 1) val = fmaxf(val, __shfl_xor_sync(0xffffffffu, val, o));
    return __shfl_sync(0xffffffffu, val, 0);
}

// ---------------- local windowed attention: fp32 qkv -> fp16-split out ----------------
__global__ __launch_bounds__(256) void local_attn(
    const float* __restrict__ qkv, const int* __restrict__ mask,
    hf* __restrict__ outH, hf* __restrict__ outL)
{
    const int  bw   = blockIdx.x;
    const int  h    = blockIdx.y;
    const long tok0 = (long)bw * DW;
    const int  LD   = 3 * DD;
    const float* qb = qkv + tok0 * LD + h * DH_;
    const float* kb = qkv + tok0 * LD + DD + h * DH_;
    const float* vb = qkv + tok0 * LD + 2 * DD + h * DH_;

    __shared__ float s[DW][DW + 1];
    __shared__ float msk[DW];
    const int tid = threadIdx.x;
    if (tid < DW) msk[tid] = (mask[tok0 + tid] != 0) ? 0.f : -1e9f;

    #pragma unroll
    for (int p = tid; p < DW * DW; p += 256) {
        int i = p >> 5, j = p & 31;
        const float4* qp = (const float4*)(qb + (long)i * LD);
        const float4* kp = (const float4*)(kb + (long)j * LD);
        float acc = 0.f;
        #pragma unroll 8
        for (int d = 0; d < DH_ / 4; d++) {
            float4 a = qp[d], c = kp[d];
            acc += a.x * c.x + a.y * c.y + a.z * c.z + a.w * c.w;
        }
        s[i][j] = acc;
    }
    __syncthreads();

    if (tid < DW) {
        const int i = tid;
        const float mi = msk[i];
        float r[DW];
        float mx = -3.4e38f;
        #pragma unroll
        for (int j = 0; j < DW; j++) {
            float bias = (mi + msk[j] < -0.5f) ? -1e9f : 0.f;
            r[j] = s[i][j] * SCL + bias;
            mx = fmaxf(mx, r[j]);
        }
        float sum = 0.f;
        #pragma unroll
        for (int j = 0; j < DW; j++) { r[j] = expf(r[j] - mx); sum += r[j]; }
        const float inv = 1.f / sum;
        #pragma unroll
        for (int j = 0; j < DW; j++) s[i][j] = r[j] * inv;
    }
    __syncthreads();

    float2 acc[DW];
    #pragma unroll
    for (int i = 0; i < DW; i++) acc[i] = make_float2(0.f, 0.f);
    for (int j = 0; j < DW; j++) {
        float2 v2 = *(const float2*)(vb + (long)j * LD + tid * 2);
        #pragma unroll
        for (int i = 0; i < DW; i++) {
            float w = s[i][j];
            acc[i].x += w * v2.x;
            acc[i].y += w * v2.y;
        }
    }
    const long obase = tok0 * DD + h * DH_ + tid * 2;
    #pragma unroll
    for (int i = 0; i < DW; i++) {
        hf hx, lx, hy, ly;
        split1(acc[i].x, hx, lx); split1(acc[i].y, hy, ly);
        __half2 hv; hv.x = hx; hv.y = hy;
        __half2 lv; lv.x = lx; lv.y = ly;
        *(__half2*)&outH[obase + (long)i * DD] = hv;
        *(__half2*)&outL[obase + (long)i * DD] = lv;
    }
}

// ---------------- LayerNorm over rows of 4096 -> fp16 split out ----------------
__global__ __launch_bounds__(256) void layernorm_bf(
    const float* __restrict__ X, const float* __restrict__ g,
    const float* __restrict__ b, hf* __restrict__ Yh, hf* __restrict__ Yl)
{
    const long row = blockIdx.x;
    const float* x = X + row * DD;
    float v[16];
    float s = 0.f;
    #pragma unroll
    for (int i = 0; i < 16; i++) { v[i] = x[threadIdx.x + i * 256]; s += v[i]; }
    const float mean = blockSum(s) * (1.f / DD);
    float d2 = 0.f;
    #pragma unroll
    for (int i = 0; i < 16; i++) { float d = v[i] - mean; d2 += d * d; }
    const float var = blockSum(d2) * (1.f / DD);
    const float rs = rsqrtf(var + 1e-5f);
    #pragma unroll
    for (int i = 0; i < 16; i++) {
        int c = threadIdx.x + i * 256;
        float o = (v[i] - mean) * rs * g[c] + b[c];
        hf h, l; split1(o, h, l);
        Yh[row * DD + c] = h;
        Yl[row * DD + c] = l;
    }
}

// ---------------- global softmax over S=2048 keys -> fp16 split out ----------------
__global__ __launch_bounds__(256) void softmax_bf(
    const float* __restrict__ sc, const int* __restrict__ mask,
    hf* __restrict__ oh, hf* __restrict__ ol)
{
    const long row = blockIdx.x;
    const int  b   = (int)(row >> 11);
    const float* x = sc + row * DS;
    const int* m = mask + (long)b * DS;
    float v[8];
    float mx = -3.4e38f;
    #pragma unroll
    for (int i = 0; i < 8; i++) {
        int c = threadIdx.x + i * 256;
        float t = x[c] + ((m[c] != 0) ? 0.f : -1e9f);
        v[i] = t;
        mx = fmaxf(mx, t);
    }
    mx = blockMax(mx);
    float s = 0.f;
    #pragma unroll
    for (int i = 0; i < 8; i++) { v[i] = expf(v[i] - mx); s += v[i]; }
    s = blockSum(s);
    const float inv = 1.f / s;
    #pragma unroll
    for (int i = 0; i < 8; i++) {
        int c = threadIdx.x + i * 256;
        hf h, l; split1(v[i] * inv, h, l);
        oh[row * DS + c] = h;
        ol[row * DS + c] = l;
    }
}

// ======================= launch =======================
static void split_full(const float* in, hf* oh, hf* ol, long rows, long cols) {
    long total4 = rows * (cols / 4);
    split_mat<<<(unsigned)((total4 + 255) / 256), 256>>>(in, cols, oh, ol, cols, (int)(cols / 4), total4);
}

extern "C" void kernel_launch(void* const* d_in, const int* in_sizes, int n_in,
                              void* d_out, int out_size)
{
    const float* vlm    = (const float*)d_in[0];
    const int*   mask   = (const int*)d_in[1];
    const float* l_in_w = (const float*)d_in[2];
    const float* l_in_b = (const float*)d_in[3];
    const float* l_out_w= (const float*)d_in[4];
    const float* l_out_b= (const float*)d_in[5];
    const float* l_ng   = (const float*)d_in[6];
    const float* l_nb   = (const float*)d_in[7];
    const float* l_pw   = (const float*)d_in[8];
    const float* l_pb   = (const float*)d_in[9];
    const float* g_in_w = (const float*)d_in[10];
    const float* g_in_b = (const float*)d_in[11];
    const float* g_out_w= (const float*)d_in[12];
    const float* g_out_b= (const float*)d_in[13];
    const float* g_ng   = (const float*)d_in[14];
    const float* g_nb   = (const float*)d_in[15];
    const float* qtok   = (const float*)d_in[16];
    const float* o_pw   = (const float*)d_in[17];
    const float* o_pb   = (const float*)d_in[18];
    float* out = (float*)d_out;

    cudaFuncSetAttribute(gemm_tc, cudaFuncAttributeMaxDynamicSharedMemorySize, GSMEM);

    float *p_qkv, *p_y, *p_kvg, *p_sc, *p_yg;
    cudaGetSymbolAddress((void**)&p_qkv, g_qkv);
    cudaGetSymbolAddress((void**)&p_y,   g_y);
    cudaGetSymbolAddress((void**)&p_kvg, g_kvg);
    cudaGetSymbolAddress((void**)&p_sc,  g_sc);
    cudaGetSymbolAddress((void**)&p_yg,  g_yg);

    hf *vlm_h,*vlm_l,*liw_h,*low_h,*lpw_h,*giw_h,*gow_h,*opw_h,
       *attnl_h,*attnl_l,*ln_h,*ln_l,*lf_h,*lf_l,*qtok_h,*qtok_l,
       *qg_h,*qg_l,*kvk_h,*vt_h,*sc_h,*sc_l,*ag_h,*ag_l,*lng_h,*lng_l;
    cudaGetSymbolAddress((void**)&vlm_h, b_vlm_h);   cudaGetSymbolAddress((void**)&vlm_l, b_vlm_l);
    cudaGetSymbolAddress((void**)&liw_h, b_liw_h);
    cudaGetSymbolAddress((void**)&low_h, b_low_h);
    cudaGetSymbolAddress((void**)&lpw_h, b_lpw_h);
    cudaGetSymbolAddress((void**)&giw_h, b_giw_h);
    cudaGetSymbolAddress((void**)&gow_h, b_gow_h);
    cudaGetSymbolAddress((void**)&opw_h, b_opw_h);
    cudaGetSymbolAddress((void**)&attnl_h, b_attnl_h); cudaGetSymbolAddress((void**)&attnl_l, b_attnl_l);
    cudaGetSymbolAddress((void**)&ln_h,  b_ln_h);    cudaGetSymbolAddress((void**)&ln_l,  b_ln_l);
    cudaGetSymbolAddress((void**)&lf_h,  b_lf_h);    cudaGetSymbolAddress((void**)&lf_l,  b_lf_l);
    cudaGetSymbolAddress((void**)&qtok_h,b_qtok_h);  cudaGetSymbolAddress((void**)&qtok_l,b_qtok_l);
    cudaGetSymbolAddress((void**)&qg_h,  b_qg_h);    cudaGetSymbolAddress((void**)&qg_l,  b_qg_l);
    cudaGetSymbolAddress((void**)&kvk_h, b_kvk_h);
    cudaGetSymbolAddress((void**)&vt_h,  b_vt_h);
    cudaGetSymbolAddress((void**)&sc_h,  b_sc_h);    cudaGetSymbolAddress((void**)&sc_l,  b_sc_l);
    cudaGetSymbolAddress((void**)&ag_h,  b_ag_h);    cudaGetSymbolAddress((void**)&ag_l,  b_ag_l);
    cudaGetSymbolAddress((void**)&lng_h, b_lng_h);   cudaGetSymbolAddress((void**)&lng_l, b_lng_l);

    const dim3 T256(256);
    #define GEMM(Ah,Al,lda,Bh,ldb,C,Oh,Ol,ldc,bias,res,resMod,resLd,K,scale,M,N,zTot,zInner,aIn,aOut,bIn,bOut,cIn,cOut) \
        gemm_tc<<<dim3(((M)/128)*((N)/128), 1, zTot), T256, GSMEM>>>( \
            Ah, Al, lda, Bh, ldb, C, Oh, Ol, ldc, bias, res, resMod, resLd, \
            K, scale, (M)/128, (N)/128, zInner, aIn, aOut, bIn, bOut, cIn, cOut)
    #define NOF (const float*)nullptr
    #define NOC (float*)nullptr
    #define NOH (hf*)nullptr

    // input/weight splits (weights: hi only — B role)
    split_full(vlm,     vlm_h,  vlm_l,  NTOK,   DD);
    split_full(l_in_w,  liw_h,  NOH,    3*DD,   DD);
    split_full(l_out_w, low_h,  NOH,    DD,     DD);
    split_full(l_pw,    lpw_h,  NOH,    DD,     DD);
    split_full(g_in_w,  giw_h,  NOH,    3*DD,   DD);
    split_full(g_out_w, gow_h,  NOH,    DD,     DD);
    split_full(o_pw,    opw_h,  NOH,    DD,     DD);
    split_full(qtok,    qtok_h, qtok_l, DT,     DD);

    // 1) local QKV: (8192 x 12288), fp32 out (consumed by local_attn)
    GEMM(vlm_h, vlm_l, DD, liw_h, DD, p_qkv, NOH, NOH, 3*DD, l_in_b,
         NOF, 1, 1, DD, 1.f, NTOK, 3*DD, 1, 1, 0,0,0,0,0,0);

    // 2) local windowed attention -> fp16 split directly
    local_attn<<<dim3(DB * (DS / DW), NH), T256>>>(p_qkv, mask, attnl_h, attnl_l);

    // 3) local out_proj + residual(vlm), fp32 out (consumed by LN)
    GEMM(attnl_h, attnl_l, DD, low_h, DD, p_y, NOH, NOH, DD, l_out_b,
         vlm, NTOK, DD, DD, 1.f, NTOK, DD, 1, 1, 0,0,0,0,0,0);

    // 4) LN local -> fp16 split directly
    layernorm_bf<<<NTOK, T256>>>(p_y, l_ng, l_nb, ln_h, ln_l);

    // 5) local_proj -> local_features (fp16 split only)
    GEMM(ln_h, ln_l, DD, lpw_h, DD, NOC, lf_h, lf_l, DD, l_pb,
         NOF, 1, 1, DD, 1.f, NTOK, DD, 1, 1, 0,0,0,0,0,0);

    // 6) global q (batch-invariant, fp16 split only)
    GEMM(qtok_h, qtok_l, DD, giw_h, DD, NOC, qg_h, qg_l, DD, g_in_b,
         NOF, 1, 1, DD, 1.f, DT, DD, 1, 1, 0,0,0,0,0,0);

    // 7) global k,v (fp32 out; consumed by split + vtrans)
    GEMM(lf_h, lf_l, DD, giw_h + (long)DD*DD, DD,
         p_kvg, NOH, NOH, 2*DD, g_in_b + DD,
         NOF, 1, 1, DD, 1.f, NTOK, 2*DD, 1, 1, 0,0,0,0,0,0);

    // split K half (compact ld 4096, hi only), transpose V half (hi only)
    {
        long total4 = (long)NTOK * (DD / 4);
        split_mat<<<(unsigned)((total4 + 255) / 256), 256>>>(
            p_kvg, 2*DD, kvk_h, NOH, DD, DD / 4, total4);
    }
    vtrans_split<<<dim3(DS/32, DD/32, DB), T256>>>(p_kvg, vt_h);

    // 8) scores (batched 32): (256 x 2048 x 512), scaled, fp32 out
    GEMM(qg_h, qg_l, DD, kvk_h, DD, p_sc, NOH, NOH, DS,
         NOF, NOF, 1, 1,
         DH_, SCL, DT, DS, DB*NH, NH,
         /*aIn*/DH_, /*aOut*/0,
         /*bIn*/DH_, /*bOut*/(long)DS * DD,
         /*cIn*/(long)DT * DS, /*cOut*/(long)NH * DT * DS);

    // 9) softmax over keys -> fp16 split directly
    softmax_bf<<<DB * NH * DT, T256>>>(p_sc, mask, sc_h, sc_l);

    // 10) AV (batched 32): (256 x 512 x 2048), fp16 split only
    GEMM(sc_h, sc_l, DS, vt_h, DS, NOC, ag_h, ag_l, DD,
         NOF, NOF, 1, 1,
         DS, 1.f, DT, DH_, DB*NH, NH,
         /*aIn*/(long)DT * DS, /*aOut*/(long)NH * DT * DS,
         /*bIn*/(long)DH_ * DS, /*bOut*/(long)DD * DS,
         /*cIn*/DH_, /*cOut*/(long)DT * DD);

    // 11) global out_proj + residual(query_tokens broadcast), fp32 out
    GEMM(ag_h, ag_l, DD, gow_h, DD, p_yg, NOH, NOH, DD, g_out_b,
         qtok, DT, DD, DD, 1.f, NQ, DD, 1, 1, 0,0,0,0,0,0);

    // 12) LN global -> fp16 split directly
    layernorm_bf<<<NQ, T256>>>(p_yg, g_ng, g_nb, lng_h, lng_l);

    // 13) output_proj -> d_out (fp32)
    GEMM(lng_h, lng_l, DD, opw_h, DD, out, NOH, NOH, DD, o_pb,
         NOF, 1, 1, DD, 1.f, NQ, DD, 1, 1, 0,0,0,0,0,0);
}

// round 10
// speedup vs baseline: 4.0790x; 1.0656x over previous
#include <cuda_runtime.h>
#include <cuda_fp16.h>
#include <cstdint>

// ---------------- problem constants ----------------
// B=4, S=2048, D=4096, T=256, W=32, H=8, DH=512
#define DB   4
#define DS   2048
#define DD   4096
#define DT   256
#define DW   32
#define DH_  512
#define NH   8
#define NTOK (DB*DS)            // 8192
#define NQ   (DB*DT)            // 1024
#define SCL  0.044194173824159216f  // 1/sqrt(512)

typedef __half hf;

// ---------------- device scratch (no allocations allowed) ----------------
__device__ float g_qkv  [ (long)NTOK * 3 * DD ];
__device__ float g_y    [ (long)NTOK * DD ];
__device__ float g_sc   [ (long)DB * NH * DT * DS ];
__device__ float g_yg   [ (long)NQ * DD ];
// fp16 split operands: hi for everything; lo only for A-role matrices
__device__ __align__(16) hf b_vlm_h  [(long)NTOK*DD],      b_vlm_l  [(long)NTOK*DD];
__device__ __align__(16) hf b_liw_h  [(long)3*DD*DD];
__device__ __align__(16) hf b_low_h  [(long)DD*DD];
__device__ __align__(16) hf b_lpw_h  [(long)DD*DD];
__device__ __align__(16) hf b_giw_h  [(long)3*DD*DD];
__device__ __align__(16) hf b_gow_h  [(long)DD*DD];
__device__ __align__(16) hf b_opw_h  [(long)DD*DD];
__device__ __align__(16) hf b_attnl_h[(long)NTOK*DD],      b_attnl_l[(long)NTOK*DD];
__device__ __align__(16) hf b_ln_h   [(long)NTOK*DD],      b_ln_l   [(long)NTOK*DD];
__device__ __align__(16) hf b_lf_h   [(long)NTOK*DD],      b_lf_l   [(long)NTOK*DD];
__device__ __align__(16) hf b_qtok_h [(long)DT*DD],        b_qtok_l [(long)DT*DD];
__device__ __align__(16) hf b_qg_h   [(long)DT*DD],        b_qg_l   [(long)DT*DD];
__device__ __align__(16) hf b_kvk_h  [(long)NTOK*DD];                    // B-role only
__device__ __align__(16) hf b_vt_h   [(long)DB*DD*DS];                   // B-role only
__device__ __align__(16) hf b_sc_h   [(long)DB*NH*DT*DS],  b_sc_l   [(long)DB*NH*DT*DS];
__device__ __align__(16) hf b_ag_h   [(long)NQ*DD],        b_ag_l   [(long)NQ*DD];
__device__ __align__(16) hf b_lng_h  [(long)NQ*DD],        b_lng_l  [(long)NQ*DD];

// ======================= helpers =======================
__device__ __forceinline__ uint32_t smem_u32(const void* p) {
    uint32_t a;
    asm("{ .reg .u64 t; cvta.to.shared.u64 t, %1; cvt.u32.u64 %0, t; }" : "=r"(a) : "l"(p));
    return a;
}
__device__ __forceinline__ void cp16(uint32_t dst, const void* src) {
    asm volatile("cp.async.cg.shared.global [%0], [%1], 16;" :: "r"(dst), "l"(src));
}
__device__ __forceinline__ void cp_commit() { asm volatile("cp.async.commit_group;" ::: "memory"); }
template <int N> __device__ __forceinline__ void cp_wait() {
    asm volatile("cp.async.wait_group %0;" :: "n"(N) : "memory");
}
__device__ __forceinline__ void ldsm4(uint32_t* r, uint32_t a) {
    asm volatile("ldmatrix.sync.aligned.m8n8.x4.shared.b16 {%0,%1,%2,%3}, [%4];"
        : "=r"(r[0]), "=r"(r[1]), "=r"(r[2]), "=r"(r[3]) : "r"(a));
}
// D += A*B  (m16n8k16, fp16 in, fp32 acc)
__device__ __forceinline__ void mma16816(float* d, const uint32_t* a, const uint32_t* b) {
    asm volatile(
        "mma.sync.aligned.m16n8k16.row.col.f32.f16.f16.f32 "
        "{%0,%1,%2,%3}, {%4,%5,%6,%7}, {%8,%9}, {%0,%1,%2,%3};"
        : "+f"(d[0]), "+f"(d[1]), "+f"(d[2]), "+f"(d[3])
        : "r"(a[0]), "r"(a[1]), "r"(a[2]), "r"(a[3]), "r"(b[0]), "r"(b[1]));
}
__device__ __forceinline__ void split1(float v, hf& h, hf& l) {
    h = __float2half_rn(v);
    l = __float2half_rn(v - __half2float(h));
}
// XOR swizzle: row pitch 64B, 16B unit c in 0..3; conflict-free 8-row ldmatrix groups
__device__ __forceinline__ uint32_t swz(int r, int c) {
    return (uint32_t)(r * 64 + ((c ^ ((r >> 1) & 3)) << 4));
}

// ======================= fp16x2 HMMA GEMM =======================
// C(M,N) = scale * (Ah+Al) @ Bh^T [2-product fp16] + bias + res
// 128x128 tile, K-chunk 32, 4-stage cp.async, single __syncthreads/iter, 2 CTAs/SM.
// stage (24KB): Ah[128][32] Al Bh[128][32], pitch 64B, XOR-swizzled.
#define GSTG   24576
#define GSMEM  (4*GSTG)
#define OFF_AL 8192u
#define OFF_BH 16384u

__device__ __forceinline__ void load_chunk(
    uint32_t sb, int slot, long k0, int tid,
    const hf* __restrict__ Ah, const hf* __restrict__ Al, long lda, long bm,
    const hf* __restrict__ Bh, long ldb, long bn)
{
    uint32_t base = sb + (uint32_t)slot * GSTG;
    #pragma unroll
    for (int it = 0; it < 2; it++) {
        int u = tid + it * 256;            // 0..511
        int r = u >> 2, c = u & 3;         // row 0..127, 16B-col 0..3
        uint32_t off = swz(r, c);
        long srcA = (bm + r) * lda + k0 + c * 8;
        cp16(base + off,          Ah + srcA);
        cp16(base + OFF_AL + off, Al + srcA);
        cp16(base + OFF_BH + off, Bh + (bn + r) * ldb + k0 + c * 8);
    }
    cp_commit();
}

__global__ __launch_bounds__(256, 2) void gemm_tc(
    const hf* __restrict__ Ah, const hf* __restrict__ Al, long lda,
    const hf* __restrict__ Bh, long ldb,
    float* __restrict__ C,
    hf* __restrict__ Oh, hf* __restrict__ Ol,
    long ldc,
    const float* __restrict__ bias,
    const float* __restrict__ res, int resMod, long resLd,
    int K, float scale, int nTm, int nTn, int kvMode,
    int zInner, long aIn, long aOut, long bIn, long bOut, long cIn, long cOut)
{
    extern __shared__ __align__(128) char smem[];
    const uint32_t sb = smem_u32(smem);
    const int tid = threadIdx.x;
    const int wid = tid >> 5;
    const int lane = tid & 31;

    const int z = blockIdx.z;
    const int zi = z % zInner, zo = z / zInner;
    Ah += (long)zi * aIn + (long)zo * aOut;  Al += (long)zi * aIn + (long)zo * aOut;
    Bh += (long)zi * bIn + (long)zo * bOut;
    const long coff = (long)zi * cIn + (long)zo * cOut;
    if (C)  C  += coff;
    if (Oh && !kvMode) { Oh += coff; Ol += coff; }

    // L2-friendly rasterization: bands of 8 N-tiles
    const int idx = blockIdx.x;
    const int per = nTm * 8;
    const int band = idx / per, rem = idx % per;
    const long bm = (long)(rem % nTm) * 128;
    const long bn = (long)(band * 8 + rem / nTm) * 128;

    // warp layout: 4(M) x 2(N); warp tile 32x64
    const int wm = wid & 3;
    const int wn = wid >> 2;

    const int aRow = wm * 32 + (lane & 15);           // + m*16
    const int aC0  = (lane >> 4);                      // + ks*2
    const int bRow = wn * 64 + (lane & 7) + ((lane >> 4) & 1) * 8;  // + p*16
    const int bC0  = ((lane >> 3) & 1);                // + ks*2

    float acc[2][8][4];
    #pragma unroll
    for (int i = 0; i < 2; i++)
        #pragma unroll
        for (int j = 0; j < 8; j++)
            #pragma unroll
            for (int q = 0; q < 4; q++) acc[i][j][q] = 0.f;

    const int nCh = K >> 5;        // K-chunk 32; all K here >= 512
    load_chunk(sb, 0, 0,  tid, Ah, Al, lda, bm, Bh, ldb, bn);
    load_chunk(sb, 1, 32, tid, Ah, Al, lda, bm, Bh, ldb, bn);
    load_chunk(sb, 2, 64, tid, Ah, Al, lda, bm, Bh, ldb, bn);

    for (int i = 0; i < nCh; i++) {
        if (i + 2 < nCh)      cp_wait<2>();
        else if (i + 1 < nCh) cp_wait<1>();
        else                  cp_wait<0>();
        __syncthreads();
        if (i + 3 < nCh)
            load_chunk(sb, (i + 3) & 3, (long)(i + 3) * 32, tid,
                       Ah, Al, lda, bm, Bh, ldb, bn);
        const uint32_t stg = sb + (uint32_t)(i & 3) * GSTG;
        #pragma unroll
        for (int ks = 0; ks < 2; ks++) {
            uint32_t ah[2][4], al[2][4];
            #pragma unroll
            for (int m = 0; m < 2; m++) {
                uint32_t a = stg + swz(aRow + m * 16, aC0 + ks * 2);
                ldsm4(ah[m], a);
                ldsm4(al[m], a + OFF_AL);
            }
            #pragma unroll
            for (int p = 0; p < 4; p++) {
                uint32_t bh[4];
                ldsm4(bh, stg + OFF_BH + swz(bRow + p * 16, bC0 + ks * 2));
                #pragma unroll
                for (int m = 0; m < 2; m++)
                    #pragma unroll
                    for (int s = 0; s < 2; s++) {
                        const int nt = p * 2 + s;
                        mma16816(acc[m][nt], ah[m], &bh[s * 2]);
                        mma16816(acc[m][nt], al[m], &bh[s * 2]);
                    }
            }
        }
    }

    // ---- epilogue: fused scale/bias/residual; fp32 / fp16-split / KV out ----
    const int r0 = lane >> 2;
    const int c0 = (lane & 3) * 2;
    const bool isV = kvMode && (bn >= DD);   // 128-wide tiles never straddle K/V halves
    #pragma unroll
    for (int m = 0; m < 2; m++) {
        #pragma unroll
        for (int half = 0; half < 2; half++) {
            const long grow = bm + wm * 32 + m * 16 + r0 + half * 8;
            const long rrow = (grow % resMod) * resLd;
            #pragma unroll
            for (int nt = 0; nt < 8; nt++) {
                const long gcol = bn + wn * 64 + nt * 8 + c0;
                float vx = acc[m][nt][half * 2]     * scale;
                float vy = acc[m][nt][half * 2 + 1] * scale;
                if (bias) {
                    float2 bb = *(const float2*)&bias[gcol];
                    vx += bb.x; vy += bb.y;
                }
                if (res) {
                    float2 rr = *(const float2*)&res[rrow + gcol];
                    vx += rr.x; vy += rr.y;
                }
                if (kvMode) {
                    if (!isV) {
                        // K half: kvk_h[grow*DD + gcol], hi only, coalesced half2
                        __half2 hv; hv.x = __float2half_rn(vx); hv.y = __float2half_rn(vy);
                        *(__half2*)&Oh[grow * DD + gcol] = hv;
                    } else {
                        // V half: transposed vt_h[((b*DD)+d)*DS + s], hi only
                        const int d = (int)(gcol - DD);
                        const long b = grow >> 11;        // grow / DS
                        const long s = grow & (DS - 1);
                        const long o = (b * DD + d) * DS + s;
                        Ol[o]      = __float2half_rn(vx);
                        Ol[o + DS] = __float2half_rn(vy);
                    }
                } else {
                    if (C) {
                        float2 v; v.x = vx; v.y = vy;
                        *(float2*)&C[grow * ldc + gcol] = v;
                    }
                    if (Oh) {
                        hf hx, lx, hy, ly;
                        split1(vx, hx, lx); split1(vy, hy, ly);
                        __half2 hv; hv.x = hx; hv.y = hy;
                        __half2 lv; lv.x = lx; lv.y = ly;
                        *(__half2*)&Oh[grow * ldc + gcol] = hv;
                        *(__half2*)&Ol[grow * ldc + gcol] = lv;
                    }
                }
            }
        }
    }
}

// ======================= split conversions =======================
// ol may be null (B-role matrices: hi only)
__global__ __launch_bounds__(256) void split_mat(
    const float* __restrict__ in, long ldIn,
    hf* __restrict__ oh, hf* __restrict__ ol, long ldOut,
    int cols4, long total4)
{
    long idx = (long)blockIdx.x * 256 + threadIdx.x;
    if (idx >= total4) return;
    long r = idx / cols4;
    int  c = (int)(idx - r * cols4);
    float4 v = *(const float4*)(in + r * ldIn + c * 4);
    hf h0, h1, h2, h3, l0, l1, l2, l3;
    split1(v.x, h0, l0); split1(v.y, h1, l1);
    split1(v.z, h2, l2); split1(v.w, h3, l3);
    __half2* ph = (__half2*)(oh + r * ldOut + c * 4);
    __half2 a; a.x = h0; a.y = h1; ph[0] = a;
    a.x = h2; a.y = h3; ph[1] = a;
    if (ol) {
        __half2* pl = (__half2*)(ol + r * ldOut + c * 4);
        a.x = l0; a.y = l1; pl[0] = a;
        a.x = l2; a.y = l3; pl[1] = a;
    }
}

// ======================= reductions =======================
__device__ __forceinline__ float blockSum(float val) {
    __shared__ float sh[32];
    int lane = threadIdx.x & 31, w = threadIdx.x >> 5;
    #pragma unroll
    for (int o = 16; o; o >>= 1) val += __shfl_xor_sync(0xffffffffu, val, o);
    __syncthreads();
    if (lane == 0) sh[w] = val;
    __syncthreads();
    val = (lane < 8) ? sh[lane] : 0.f;
    #pragma unroll
    for (int o = 4; o; o >>= 1) val += __shfl_xor_sync(0xffffffffu, val, o);
    return __shfl_sync(0xffffffffu, val, 0);
}
__device__ __forceinline__ float blockMax(float val) {
    __shared__ float sh[32];
    int lane = threadIdx.x & 31, w = threadIdx.x >> 5;
    #pragma unroll
    for (int o = 16; o; o >>= 1) val = fmaxf(val, __shfl_xor_sync(0xffffffffu, val, o));
    __syncthreads();
    if (lane == 0) sh[w] = val;
    __syncthreads();
    val = (lane < 8) ? sh[lane] : -3.4e38f;
    #pragma unroll
    for (int o = 4; o; o >>= 1) val = fmaxf(val, __shfl_xor_sync(0xffffffffu, val, o));
    return __shfl_sync(0xffffffffu, val, 0);
}

// ---------------- local windowed attention: fp32 qkv -> fp16-split out ----------------
__global__ __launch_bounds__(256) void local_attn(
    const float* __restrict__ qkv, const int* __restrict__ mask,
    hf* __restrict__ outH, hf* __restrict__ outL)
{
    const int  bw   = blockIdx.x;
    const int  h    = blockIdx.y;
    const long tok0 = (long)bw * DW;
    const int  LD   = 3 * DD;
    const float* qb = qkv + tok0 * LD + h * DH_;
    const float* kb = qkv + tok0 * LD + DD + h * DH_;
    const float* vb = qkv + tok0 * LD + 2 * DD + h * DH_;

    __shared__ float s[DW][DW + 1];
    __shared__ float msk[DW];
    const int tid = threadIdx.x;
    if (tid < DW) msk[tid] = (mask[tok0 + tid] != 0) ? 0.f : -1e9f;

    #pragma unroll
    for (int p = tid; p < DW * DW; p += 256) {
        int i = p >> 5, j = p & 31;
        const float4* qp = (const float4*)(qb + (long)i * LD);
        const float4* kp = (const float4*)(kb + (long)j * LD);
        float acc = 0.f;
        #pragma unroll 8
        for (int d = 0; d < DH_ / 4; d++) {
            float4 a = qp[d], c = kp[d];
            acc += a.x * c.x + a.y * c.y + a.z * c.z + a.w * c.w;
        }
        s[i][j] = acc;
    }
    __syncthreads();

    if (tid < DW) {
        const int i = tid;
        const float mi = msk[i];
        float r[DW];
        float mx = -3.4e38f;
        #pragma unroll
        for (int j = 0; j < DW; j++) {
            float bias = (mi + msk[j] < -0.5f) ? -1e9f : 0.f;
            r[j] = s[i][j] * SCL + bias;
            mx = fmaxf(mx, r[j]);
        }
        float sum = 0.f;
        #pragma unroll
        for (int j = 0; j < DW; j++) { r[j] = expf(r[j] - mx); sum += r[j]; }
        const float inv = 1.f / sum;
        #pragma unroll
        for (int j = 0; j < DW; j++) s[i][j] = r[j] * inv;
    }
    __syncthreads();

    float2 acc[DW];
    #pragma unroll
    for (int i = 0; i < DW; i++) acc[i] = make_float2(0.f, 0.f);
    for (int j = 0; j < DW; j++) {
        float2 v2 = *(const float2*)(vb + (long)j * LD + tid * 2);
        #pragma unroll
        for (int i = 0; i < DW; i++) {
            float w = s[i][j];
            acc[i].x += w * v2.x;
            acc[i].y += w * v2.y;
        }
    }
    const long obase = tok0 * DD + h * DH_ + tid * 2;
    #pragma unroll
    for (int i = 0; i < DW; i++) {
        hf hx, lx, hy, ly;
        split1(acc[i].x, hx, lx); split1(acc[i].y, hy, ly);
        __half2 hv; hv.x = hx; hv.y = hy;
        __half2 lv; lv.x = lx; lv.y = ly;
        *(__half2*)&outH[obase + (long)i * DD] = hv;
        *(__half2*)&outL[obase + (long)i * DD] = lv;
    }
}

// ---------------- LayerNorm over rows of 4096 -> fp16 split out ----------------
__global__ __launch_bounds__(256) void layernorm_bf(
    const float* __restrict__ X, const float* __restrict__ g,
    const float* __restrict__ b, hf* __restrict__ Yh, hf* __restrict__ Yl)
{
    const long row = blockIdx.x;
    const float* x = X + row * DD;
    float v[16];
    float s = 0.f;
    #pragma unroll
    for (int i = 0; i < 16; i++) { v[i] = x[threadIdx.x + i * 256]; s += v[i]; }
    const float mean = blockSum(s) * (1.f / DD);
    float d2 = 0.f;
    #pragma unroll
    for (int i = 0; i < 16; i++) { float d = v[i] - mean; d2 += d * d; }
    const float var = blockSum(d2) * (1.f / DD);
    const float rs = rsqrtf(var + 1e-5f);
    #pragma unroll
    for (int i = 0; i < 16; i++) {
        int c = threadIdx.x + i * 256;
        float o = (v[i] - mean) * rs * g[c] + b[c];
        hf h, l; split1(o, h, l);
        Yh[row * DD + c] = h;
        Yl[row * DD + c] = l;
    }
}

// ---------------- global softmax over S=2048 keys -> fp16 split out ----------------
__global__ __launch_bounds__(256) void softmax_bf(
    const float* __restrict__ sc, const int* __restrict__ mask,
    hf* __restrict__ oh, hf* __restrict__ ol)
{
    const long row = blockIdx.x;
    const int  b   = (int)(row >> 11);
    const float* x = sc + row * DS;
    const int* m = mask + (long)b * DS;
    float v[8];
    float mx = -3.4e38f;
    #pragma unroll
    for (int i = 0; i < 8; i++) {
        int c = threadIdx.x + i * 256;
        float t = x[c] + ((m[c] != 0) ? 0.f : -1e9f);
        v[i] = t;
        mx = fmaxf(mx, t);
    }
    mx = blockMax(mx);
    float s = 0.f;
    #pragma unroll
    for (int i = 0; i < 8; i++) { v[i] = expf(v[i] - mx); s += v[i]; }
    s = blockSum(s);
    const float inv = 1.f / s;
    #pragma unroll
    for (int i = 0; i < 8; i++) {
        int c = threadIdx.x + i * 256;
        hf h, l; split1(v[i] * inv, h, l);
        oh[row * DS + c] = h;
        ol[row * DS + c] = l;
    }
}

// ======================= launch =======================
static void split_full(const float* in, hf* oh, hf* ol, long rows, long cols) {
    long total4 = rows * (cols / 4);
    split_mat<<<(unsigned)((total4 + 255) / 256), 256>>>(in, cols, oh, ol, cols, (int)(cols / 4), total4);
}

extern "C" void kernel_launch(void* const* d_in, const int* in_sizes, int n_in,
                              void* d_out, int out_size)
{
    const float* vlm    = (const float*)d_in[0];
    const int*   mask   = (const int*)d_in[1];
    const float* l_in_w = (const float*)d_in[2];
    const float* l_in_b = (const float*)d_in[3];
    const float* l_out_w= (const float*)d_in[4];
    const float* l_out_b= (const float*)d_in[5];
    const float* l_ng   = (const float*)d_in[6];
    const float* l_nb   = (const float*)d_in[7];
    const float* l_pw   = (const float*)d_in[8];
    const float* l_pb   = (const float*)d_in[9];
    const float* g_in_w = (const float*)d_in[10];
    const float* g_in_b = (const float*)d_in[11];
    const float* g_out_w= (const float*)d_in[12];
    const float* g_out_b= (const float*)d_in[13];
    const float* g_ng   = (const float*)d_in[14];
    const float* g_nb   = (const float*)d_in[15];
    const float* qtok   = (const float*)d_in[16];
    const float* o_pw   = (const float*)d_in[17];
    const float* o_pb   = (const float*)d_in[18];
    float* out = (float*)d_out;

    cudaFuncSetAttribute(gemm_tc, cudaFuncAttributeMaxDynamicSharedMemorySize, GSMEM);

    float *p_qkv, *p_y, *p_sc, *p_yg;
    cudaGetSymbolAddress((void**)&p_qkv, g_qkv);
    cudaGetSymbolAddress((void**)&p_y,   g_y);
    cudaGetSymbolAddress((void**)&p_sc,  g_sc);
    cudaGetSymbolAddress((void**)&p_yg,  g_yg);

    hf *vlm_h,*vlm_l,*liw_h,*low_h,*lpw_h,*giw_h,*gow_h,*opw_h,
       *attnl_h,*attnl_l,*ln_h,*ln_l,*lf_h,*lf_l,*qtok_h,*qtok_l,
       *qg_h,*qg_l,*kvk_h,*vt_h,*sc_h,*sc_l,*ag_h,*ag_l,*lng_h,*lng_l;
    cudaGetSymbolAddress((void**)&vlm_h, b_vlm_h);   cudaGetSymbolAddress((void**)&vlm_l, b_vlm_l);
    cudaGetSymbolAddress((void**)&liw_h, b_liw_h);
    cudaGetSymbolAddress((void**)&low_h, b_low_h);
    cudaGetSymbolAddress((void**)&lpw_h, b_lpw_h);
    cudaGetSymbolAddress((void**)&giw_h, b_giw_h);
    cudaGetSymbolAddress((void**)&gow_h, b_gow_h);
    cudaGetSymbolAddress((void**)&opw_h, b_opw_h);
    cudaGetSymbolAddress((void**)&attnl_h, b_attnl_h); cudaGetSymbolAddress((void**)&attnl_l, b_attnl_l);
    cudaGetSymbolAddress((void**)&ln_h,  b_ln_h);    cudaGetSymbolAddress((void**)&ln_l,  b_ln_l);
    cudaGetSymbolAddress((void**)&lf_h,  b_lf_h);    cudaGetSymbolAddress((void**)&lf_l,  b_lf_l);
    cudaGetSymbolAddress((void**)&qtok_h,b_qtok_h);  cudaGetSymbolAddress((void**)&qtok_l,b_qtok_l);
    cudaGetSymbolAddress((void**)&qg_h,  b_qg_h);    cudaGetSymbolAddress((void**)&qg_l,  b_qg_l);
    cudaGetSymbolAddress((void**)&kvk_h, b_kvk_h);
    cudaGetSymbolAddress((void**)&vt_h,  b_vt_h);
    cudaGetSymbolAddress((void**)&sc_h,  b_sc_h);    cudaGetSymbolAddress((void**)&sc_l,  b_sc_l);
    cudaGetSymbolAddress((void**)&ag_h,  b_ag_h);    cudaGetSymbolAddress((void**)&ag_l,  b_ag_l);
    cudaGetSymbolAddress((void**)&lng_h, b_lng_h);   cudaGetSymbolAddress((void**)&lng_l, b_lng_l);

    const dim3 T256(256);
    #define GEMM(Ah,Al,lda,Bh,ldb,C,Oh,Ol,ldc,bias,res,resMod,resLd,K,scale,M,N,kvM,zTot,zInner,aIn,aOut,bIn,bOut,cIn,cOut) \
        gemm_tc<<<dim3(((M)/128)*((N)/128), 1, zTot), T256, GSMEM>>>( \
            Ah, Al, lda, Bh, ldb, C, Oh, Ol, ldc, bias, res, resMod, resLd, \
            K, scale, (M)/128, (N)/128, kvM, zInner, aIn, aOut, bIn, bOut, cIn, cOut)
    #define NOF (const float*)nullptr
    #define NOC (float*)nullptr
    #define NOH (hf*)nullptr

    // input/weight splits (weights: hi only — B role)
    split_full(vlm,     vlm_h,  vlm_l,  NTOK,   DD);
    split_full(l_in_w,  liw_h,  NOH,    3*DD,   DD);
    split_full(l_out_w, low_h,  NOH,    DD,     DD);
    split_full(l_pw,    lpw_h,  NOH,    DD,     DD);
    split_full(g_in_w,  giw_h,  NOH,    3*DD,   DD);
    split_full(g_out_w, gow_h,  NOH,    DD,     DD);
    split_full(o_pw,    opw_h,  NOH,    DD,     DD);
    split_full(qtok,    qtok_h, qtok_l, DT,     DD);

    // 1) local QKV: (8192 x 12288), fp32 out (consumed by local_attn)
    GEMM(vlm_h, vlm_l, DD, liw_h, DD, p_qkv, NOH, NOH, 3*DD, l_in_b,
         NOF, 1, 1, DD, 1.f, NTOK, 3*DD, 0, 1, 1, 0,0,0,0,0,0);

    // 2) local windowed attention -> fp16 split directly
    local_attn<<<dim3(DB * (DS / DW), NH), T256>>>(p_qkv, mask, attnl_h, attnl_l);

    // 3) local out_proj + residual(vlm), fp32 out (consumed by LN)
    GEMM(attnl_h, attnl_l, DD, low_h, DD, p_y, NOH, NOH, DD, l_out_b,
         vlm, NTOK, DD, DD, 1.f, NTOK, DD, 0, 1, 1, 0,0,0,0,0,0);

    // 4) LN local -> fp16 split directly
    layernorm_bf<<<NTOK, T256>>>(p_y, l_ng, l_nb, ln_h, ln_l);

    // 5) local_proj -> local_features (fp16 split only)
    GEMM(ln_h, ln_l, DD, lpw_h, DD, NOC, lf_h, lf_l, DD, l_pb,
         NOF, 1, 1, DD, 1.f, NTOK, DD, 0, 1, 1, 0,0,0,0,0,0);

    // 6) global q (batch-invariant, fp16 split only)
    GEMM(qtok_h, qtok_l, DD, giw_h, DD, NOC, qg_h, qg_l, DD, g_in_b,
         NOF, 1, 1, DD, 1.f, DT, DD, 0, 1, 1, 0,0,0,0,0,0);

    // 7) global k,v — fused epilogue: K half -> kvk_h (ld=4096), V half -> vt_h transposed
    GEMM(lf_h, lf_l, DD, giw_h + (long)DD*DD, DD,
         NOC, kvk_h, vt_h, DD, g_in_b + DD,
         NOF, 1, 1, DD, 1.f, NTOK, 2*DD, 1, 1, 1, 0,0,0,0,0,0);

    // 8) scores (batched 32): (256 x 2048 x 512), scaled, fp32 out
    GEMM(qg_h, qg_l, DD, kvk_h, DD, p_sc, NOH, NOH, DS,
         NOF, NOF, 1, 1,
         DH_, SCL, DT, DS, 0, DB*NH, NH,
         /*aIn*/DH_, /*aOut*/0,
         /*bIn*/DH_, /*bOut*/(long)DS * DD,
         /*cIn*/(long)DT * DS, /*cOut*/(long)NH * DT * DS);

    // 9) softmax over keys -> fp16 split directly
    softmax_bf<<<DB * NH * DT, T256>>>(p_sc, mask, sc_h, sc_l);

    // 10) AV (batched 32): (256 x 512 x 2048), fp16 split only
    GEMM(sc_h, sc_l, DS, vt_h, DS, NOC, ag_h, ag_l, DD,
         NOF, NOF, 1, 1,
         DS, 1.f, DT, DH_, 0, DB*NH, NH,
         /*aIn*/(long)DT * DS, /*aOut*/(long)NH * DT * DS,
         /*bIn*/(long)DH_ * DS, /*bOut*/(long)DD * DS,
         /*cIn*/DH_, /*cOut*/(long)DT * DD);

    // 11) global out_proj + residual(query_tokens broadcast), fp32 out
    GEMM(ag_h, ag_l, DD, gow_h, DD, p_yg, NOH, NOH, DD, g_out_b,
         qtok, DT, DD, DD, 1.f, NQ, DD, 0, 1, 1, 0,0,0,0,0,0);

    // 12) LN global -> fp16 split directly
    layernorm_bf<<<NQ, T256>>>(p_yg, g_ng, g_nb, lng_h, lng_l);

    // 13) output_proj -> d_out (fp32)
    GEMM(lng_h, lng_l, DD, opw_h, DD, out, NOH, NOH, DD, o_pb,
         NOF, 1, 1, DD, 1.f, NQ, DD, 0, 1, 1, 0,0,0,0,0,0);
}

// round 11
// speedup vs baseline: 5.4331x; 1.3320x over previous
#include <cuda_runtime.h>
#include <cuda_fp16.h>
#include <cstdint>

// ---------------- problem constants ----------------
// B=4, S=2048, D=4096, T=256, W=32, H=8, DH=512
#define DB   4
#define DS   2048
#define DD   4096
#define DT   256
#define DW   32
#define DH_  512
#define NH   8
#define NTOK (DB*DS)            // 8192
#define NQ   (DB*DT)            // 1024
#define SCL  0.044194173824159216f  // 1/sqrt(512)

typedef __half hf;

// ---------------- device scratch (no allocations allowed) ----------------
__device__ float g_qkv  [ (long)NTOK * 3 * DD ];
__device__ float g_y    [ (long)NTOK * DD ];
__device__ float g_sc   [ (long)DB * NH * DT * DS ];
__device__ float g_yg   [ (long)NQ * DD ];
// fp16 split operands: hi for everything; lo only where consumed by 2-product GEMMs
__device__ __align__(16) hf b_vlm_h  [(long)NTOK*DD];
__device__ __align__(16) hf b_liw_h  [(long)3*DD*DD];
__device__ __align__(16) hf b_low_h  [(long)DD*DD];
__device__ __align__(16) hf b_lpw_h  [(long)DD*DD];
__device__ __align__(16) hf b_giw_h  [(long)3*DD*DD];
__device__ __align__(16) hf b_gow_h  [(long)DD*DD];
__device__ __align__(16) hf b_opw_h  [(long)DD*DD];
__device__ __align__(16) hf b_attnl_h[(long)NTOK*DD],      b_attnl_l[(long)NTOK*DD];
__device__ __align__(16) hf b_ln_h   [(long)NTOK*DD],      b_ln_l   [(long)NTOK*DD];
__device__ __align__(16) hf b_lf_h   [(long)NTOK*DD];
__device__ __align__(16) hf b_qtok_h [(long)DT*DD],        b_qtok_l [(long)DT*DD];
__device__ __align__(16) hf b_qg_h   [(long)DT*DD],        b_qg_l   [(long)DT*DD];
__device__ __align__(16) hf b_kvk_h  [(long)NTOK*DD];                    // B-role only
__device__ __align__(16) hf b_vt_h   [(long)DB*DD*DS];                   // B-role only
__device__ __align__(16) hf b_sc_h   [(long)DB*NH*DT*DS],  b_sc_l   [(long)DB*NH*DT*DS];
__device__ __align__(16) hf b_ag_h   [(long)NQ*DD],        b_ag_l   [(long)NQ*DD];
__device__ __align__(16) hf b_lng_h  [(long)NQ*DD],        b_lng_l  [(long)NQ*DD];

// ======================= helpers =======================
__device__ __forceinline__ uint32_t smem_u32(const void* p) {
    uint32_t a;
    asm("{ .reg .u64 t; cvta.to.shared.u64 t, %1; cvt.u32.u64 %0, t; }" : "=r"(a) : "l"(p));
    return a;
}
__device__ __forceinline__ void cp16(uint32_t dst, const void* src) {
    asm volatile("cp.async.cg.shared.global [%0], [%1], 16;" :: "r"(dst), "l"(src));
}
__device__ __forceinline__ void cp_commit() { asm volatile("cp.async.commit_group;" ::: "memory"); }
template <int N> __device__ __forceinline__ void cp_wait() {
    asm volatile("cp.async.wait_group %0;" :: "n"(N) : "memory");
}
__device__ __forceinline__ void ldsm4(uint32_t* r, uint32_t a) {
    asm volatile("ldmatrix.sync.aligned.m8n8.x4.shared.b16 {%0,%1,%2,%3}, [%4];"
        : "=r"(r[0]), "=r"(r[1]), "=r"(r[2]), "=r"(r[3]) : "r"(a));
}
// D += A*B  (m16n8k16, fp16 in, fp32 acc)
__device__ __forceinline__ void mma16816(float* d, const uint32_t* a, const uint32_t* b) {
    asm volatile(
        "mma.sync.aligned.m16n8k16.row.col.f32.f16.f16.f32 "
        "{%0,%1,%2,%3}, {%4,%5,%6,%7}, {%8,%9}, {%0,%1,%2,%3};"
        : "+f"(d[0]), "+f"(d[1]), "+f"(d[2]), "+f"(d[3])
        : "r"(a[0]), "r"(a[1]), "r"(a[2]), "r"(a[3]), "r"(b[0]), "r"(b[1]));
}
__device__ __forceinline__ void split1(float v, hf& h, hf& l) {
    h = __float2half_rn(v);
    l = __float2half_rn(v - __half2float(h));
}
// XOR swizzle: row pitch 64B, 16B unit c in 0..3; conflict-free 8-row ldmatrix groups
__device__ __forceinline__ uint32_t swz(int r, int c) {
    return (uint32_t)(r * 64 + ((c ^ ((r >> 1) & 3)) << 4));
}

// ======================= fp16 HMMA GEMM (1 or 2 products) =======================
// C(M,N) = scale * (Ah [+Al]) @ Bh^T + bias + res
// 128x128 tile, K-chunk 32, 4-stage cp.async, single __syncthreads/iter, 2 CTAs/SM.
// stage (24KB): Ah[128][32] Al Bh[128][32], pitch 64B, XOR-swizzled.
#define GSTG   24576
#define GSMEM  (4*GSTG)
#define OFF_AL 8192u
#define OFF_BH 16384u

template <int USELO>
__device__ __forceinline__ void load_chunk(
    uint32_t sb, int slot, long k0, int tid,
    const hf* __restrict__ Ah, const hf* __restrict__ Al, long lda, long bm,
    const hf* __restrict__ Bh, long ldb, long bn)
{
    uint32_t base = sb + (uint32_t)slot * GSTG;
    #pragma unroll
    for (int it = 0; it < 2; it++) {
        int u = tid + it * 256;            // 0..511
        int r = u >> 2, c = u & 3;         // row 0..127, 16B-col 0..3
        uint32_t off = swz(r, c);
        long srcA = (bm + r) * lda + k0 + c * 8;
        cp16(base + off, Ah + srcA);
        if (USELO) cp16(base + OFF_AL + off, Al + srcA);
        cp16(base + OFF_BH + off, Bh + (bn + r) * ldb + k0 + c * 8);
    }
    cp_commit();
}

template <int USELO>
__global__ __launch_bounds__(256, 2) void gemm_tc(
    const hf* __restrict__ Ah, const hf* __restrict__ Al, long lda,
    const hf* __restrict__ Bh, long ldb,
    float* __restrict__ C,
    hf* __restrict__ Oh, hf* __restrict__ Ol,
    long ldc,
    const float* __restrict__ bias,
    const float* __restrict__ res, int resMod, long resLd,
    int K, float scale, int nTm, int nTn, int kvMode,
    int zInner, long aIn, long aOut, long bIn, long bOut, long cIn, long cOut)
{
    extern __shared__ __align__(128) char smem[];
    const uint32_t sb = smem_u32(smem);
    const int tid = threadIdx.x;
    const int wid = tid >> 5;
    const int lane = tid & 31;

    const int z = blockIdx.z;
    const int zi = z % zInner, zo = z / zInner;
    Ah += (long)zi * aIn + (long)zo * aOut;  Al += (long)zi * aIn + (long)zo * aOut;
    Bh += (long)zi * bIn + (long)zo * bOut;
    const long coff = (long)zi * cIn + (long)zo * cOut;
    if (C)  C  += coff;
    if (Oh && !kvMode) { Oh += coff; if (Ol) Ol += coff; }

    // L2-friendly rasterization: bands of 8 N-tiles
    const int idx = blockIdx.x;
    const int per = nTm * 8;
    const int band = idx / per, rem = idx % per;
    const long bm = (long)(rem % nTm) * 128;
    const long bn = (long)(band * 8 + rem / nTm) * 128;

    // warp layout: 4(M) x 2(N); warp tile 32x64
    const int wm = wid & 3;
    const int wn = wid >> 2;

    const int aRow = wm * 32 + (lane & 15);           // + m*16
    const int aC0  = (lane >> 4);                      // + ks*2
    const int bRow = wn * 64 + (lane & 7) + ((lane >> 4) & 1) * 8;  // + p*16
    const int bC0  = ((lane >> 3) & 1);                // + ks*2

    float acc[2][8][4];
    #pragma unroll
    for (int i = 0; i < 2; i++)
        #pragma unroll
        for (int j = 0; j < 8; j++)
            #pragma unroll
            for (int q = 0; q < 4; q++) acc[i][j][q] = 0.f;

    const int nCh = K >> 5;        // K-chunk 32; all K here >= 512
    load_chunk<USELO>(sb, 0, 0,  tid, Ah, Al, lda, bm, Bh, ldb, bn);
    load_chunk<USELO>(sb, 1, 32, tid, Ah, Al, lda, bm, Bh, ldb, bn);
    load_chunk<USELO>(sb, 2, 64, tid, Ah, Al, lda, bm, Bh, ldb, bn);

    for (int i = 0; i < nCh; i++) {
        if (i + 2 < nCh)      cp_wait<2>();
        else if (i + 1 < nCh) cp_wait<1>();
        else                  cp_wait<0>();
        __syncthreads();
        if (i + 3 < nCh)
            load_chunk<USELO>(sb, (i + 3) & 3, (long)(i + 3) * 32, tid,
                              Ah, Al, lda, bm, Bh, ldb, bn);
        const uint32_t stg = sb + (uint32_t)(i & 3) * GSTG;
        #pragma unroll
        for (int ks = 0; ks < 2; ks++) {
            uint32_t ah[2][4], al[2][4];
            #pragma unroll
            for (int m = 0; m < 2; m++) {
                uint32_t a = stg + swz(aRow + m * 16, aC0 + ks * 2);
                ldsm4(ah[m], a);
                if (USELO) ldsm4(al[m], a + OFF_AL);
            }
            #pragma unroll
            for (int p = 0; p < 4; p++) {
                uint32_t bh[4];
                ldsm4(bh, stg + OFF_BH + swz(bRow + p * 16, bC0 + ks * 2));
                #pragma unroll
                for (int m = 0; m < 2; m++)
                    #pragma unroll
                    for (int s = 0; s < 2; s++) {
                        const int nt = p * 2 + s;
                        mma16816(acc[m][nt], ah[m], &bh[s * 2]);
                        if (USELO) mma16816(acc[m][nt], al[m], &bh[s * 2]);
                    }
            }
        }
    }

    // ---- epilogue: fused scale/bias/residual; fp32 / fp16-split / KV out ----
    const int r0 = lane >> 2;
    const int c0 = (lane & 3) * 2;
    const bool isV = kvMode && (bn >= DD);   // 128-wide tiles never straddle K/V halves
    #pragma unroll
    for (int m = 0; m < 2; m++) {
        #pragma unroll
        for (int half = 0; half < 2; half++) {
            const long grow = bm + wm * 32 + m * 16 + r0 + half * 8;
            const long rrow = (grow % resMod) * resLd;
            #pragma unroll
            for (int nt = 0; nt < 8; nt++) {
                const long gcol = bn + wn * 64 + nt * 8 + c0;
                float vx = acc[m][nt][half * 2]     * scale;
                float vy = acc[m][nt][half * 2 + 1] * scale;
                if (bias) {
                    float2 bb = *(const float2*)&bias[gcol];
                    vx += bb.x; vy += bb.y;
                }
                if (res) {
                    float2 rr = *(const float2*)&res[rrow + gcol];
                    vx += rr.x; vy += rr.y;
                }
                if (kvMode) {
                    if (!isV) {
                        // K half: kvk_h[grow*DD + gcol], hi only, coalesced half2
                        __half2 hv; hv.x = __float2half_rn(vx); hv.y = __float2half_rn(vy);
                        *(__half2*)&Oh[grow * DD + gcol] = hv;
                    } else {
                        // V half: transposed vt_h[((b*DD)+d)*DS + s], hi only
                        const int d = (int)(gcol - DD);
                        const long b = grow >> 11;        // grow / DS
                        const long s = grow & (DS - 1);
                        const long o = (b * DD + d) * DS + s;
                        Ol[o]      = __float2half_rn(vx);
                        Ol[o + DS] = __float2half_rn(vy);
                    }
                } else {
                    if (C) {
                        float2 v; v.x = vx; v.y = vy;
                        *(float2*)&C[grow * ldc + gcol] = v;
                    }
                    if (Oh) {
                        hf hx, lx, hy, ly;
                        split1(vx, hx, lx); split1(vy, hy, ly);
                        __half2 hv; hv.x = hx; hv.y = hy;
                        *(__half2*)&Oh[grow * ldc + gcol] = hv;
                        if (Ol) {
                            __half2 lv; lv.x = lx; lv.y = ly;
                            *(__half2*)&Ol[grow * ldc + gcol] = lv;
                        }
                    }
                }
            }
        }
    }
}

// ======================= split conversions =======================
// ol may be null (hi only)
__global__ __launch_bounds__(256) void split_mat(
    const float* __restrict__ in, long ldIn,
    hf* __restrict__ oh, hf* __restrict__ ol, long ldOut,
    int cols4, long total4)
{
    long idx = (long)blockIdx.x * 256 + threadIdx.x;
    if (idx >= total4) return;
    long r = idx / cols4;
    int  c = (int)(idx - r * cols4);
    float4 v = *(const float4*)(in + r * ldIn + c * 4);
    hf h0, h1, h2, h3, l0, l1, l2, l3;
    split1(v.x, h0, l0); split1(v.y, h1, l1);
    split1(v.z, h2, l2); split1(v.w, h3, l3);
    __half2* ph = (__half2*)(oh + r * ldOut + c * 4);
    __half2 a; a.x = h0; a.y = h1; ph[0] = a;
    a.x = h2; a.y = h3; ph[1] = a;
    if (ol) {
        __half2* pl = (__half2*)(ol + r * ldOut + c * 4);
        a.x = l0; a.y = l1; pl[0] = a;
        a.x = l2; a.y = l3; pl[1] = a;
    }
}

// ======================= reductions =======================
__device__ __forceinline__ float blockSum(float val) {
    __shared__ float sh[32];
    int lane = threadIdx.x & 31, w = threadIdx.x >> 5;
    #pragma unroll
    for (int o = 16; o; o >>= 1) val += __shfl_xor_sync(0xffffffffu, val, o);
    __syncthreads();
    if (lane == 0) sh[w] = val;
    __syncthreads();
    val = (lane < 8) ? sh[lane] : 0.f;
    #pragma unroll
    for (int o = 4; o; o >>= 1) val += __shfl_xor_sync(0xffffffffu, val, o);
    return __shfl_sync(0xffffffffu, val, 0);
}
__device__ __forceinline__ float blockMax(float val) {
    __shared__ float sh[32];
    int lane = threadIdx.x & 31, w = threadIdx.x >> 5;
    #pragma unroll
    for (int o = 16; o; o >>= 1) val = fmaxf(val, __shfl_xor_sync(0xffffffffu, val, o));
    __syncthreads();
    if (lane == 0) sh[w] = val;
    __syncthreads();
    val = (lane < 8) ? sh[lane] : -3.4e38f;
    #pragma unroll
    for (int o = 4; o; o >>= 1) val = fmaxf(val, __shfl_xor_sync(0xffffffffu, val, o));
    return __shfl_sync(0xffffffffu, val, 0);
}

// ---------------- local windowed attention: fp32 qkv -> fp16-split out ----------------
__global__ __launch_bounds__(256) void local_attn(
    const float* __restrict__ qkv, const int* __restrict__ mask,
    hf* __restrict__ outH, hf* __restrict__ outL)
{
    const int  bw   = blockIdx.x;
    const int  h    = blockIdx.y;
    const long tok0 = (long)bw * DW;
    const int  LD   = 3 * DD;
    const float* qb = qkv + tok0 * LD + h * DH_;
    const float* kb = qkv + tok0 * LD + DD + h * DH_;
    const float* vb = qkv + tok0 * LD + 2 * DD + h * DH_;

    __shared__ float s[DW][DW + 1];
    __shared__ float msk[DW];
    const int tid = threadIdx.x;
    if (tid < DW) msk[tid] = (mask[tok0 + tid] != 0) ? 0.f : -1e9f;

    #pragma unroll
    for (int p = tid; p < DW * DW; p += 256) {
        int i = p >> 5, j = p & 31;
        const float4* qp = (const float4*)(qb + (long)i * LD);
        const float4* kp = (const float4*)(kb + (long)j * LD);
        float acc = 0.f;
        #pragma unroll 8
        for (int d = 0; d < DH_ / 4; d++) {
            float4 a = qp[d], c = kp[d];
            acc += a.x * c.x + a.y * c.y + a.z * c.z + a.w * c.w;
        }
        s[i][j] = acc;
    }
    __syncthreads();

    if (tid < DW) {
        const int i = tid;
        const float mi = msk[i];
        float r[DW];
        float mx = -3.4e38f;
        #pragma unroll
        for (int j = 0; j < DW; j++) {
            float bias = (mi + msk[j] < -0.5f) ? -1e9f : 0.f;
            r[j] = s[i][j] * SCL + bias;
            mx = fmaxf(mx, r[j]);
        }
        float sum = 0.f;
        #pragma unroll
        for (int j = 0; j < DW; j++) { r[j] = expf(r[j] - mx); sum += r[j]; }
        const float inv = 1.f / sum;
        #pragma unroll
        for (int j = 0; j < DW; j++) s[i][j] = r[j] * inv;
    }
    __syncthreads();

    float2 acc[DW];
    #pragma unroll
    for (int i = 0; i < DW; i++) acc[i] = make_float2(0.f, 0.f);
    for (int j = 0; j < DW; j++) {
        float2 v2 = *(const float2*)(vb + (long)j * LD + tid * 2);
        #pragma unroll
        for (int i = 0; i < DW; i++) {
            float w = s[i][j];
            acc[i].x += w * v2.x;
            acc[i].y += w * v2.y;
        }
    }
    const long obase = tok0 * DD + h * DH_ + tid * 2;
    #pragma unroll
    for (int i = 0; i < DW; i++) {
        hf hx, lx, hy, ly;
        split1(acc[i].x, hx, lx); split1(acc[i].y, hy, ly);
        __half2 hv; hv.x = hx; hv.y = hy;
        __half2 lv; lv.x = lx; lv.y = ly;
        *(__half2*)&outH[obase + (long)i * DD] = hv;
        *(__half2*)&outL[obase + (long)i * DD] = lv;
    }
}

// ---------------- LayerNorm over rows of 4096 -> fp16 split out ----------------
__global__ __launch_bounds__(256) void layernorm_bf(
    const float* __restrict__ X, const float* __restrict__ g,
    const float* __restrict__ b, hf* __restrict__ Yh, hf* __restrict__ Yl)
{
    const long row = blockIdx.x;
    const float* x = X + row * DD;
    float v[16];
    float s = 0.f;
    #pragma unroll
    for (int i = 0; i < 16; i++) { v[i] = x[threadIdx.x + i * 256]; s += v[i]; }
    const float mean = blockSum(s) * (1.f / DD);
    float d2 = 0.f;
    #pragma unroll
    for (int i = 0; i < 16; i++) { float d = v[i] - mean; d2 += d * d; }
    const float var = blockSum(d2) * (1.f / DD);
    const float rs = rsqrtf(var + 1e-5f);
    #pragma unroll
    for (int i = 0; i < 16; i++) {
        int c = threadIdx.x + i * 256;
        float o = (v[i] - mean) * rs * g[c] + b[c];
        hf h, l; split1(o, h, l);
        Yh[row * DD + c] = h;
        Yl[row * DD + c] = l;
    }
}

// ---------------- global softmax over S=2048 keys -> fp16 split out ----------------
__global__ __launch_bounds__(256) void softmax_bf(
    const float* __restrict__ sc, const int* __restrict__ mask,
    hf* __restrict__ oh, hf* __restrict__ ol)
{
    const long row = blockIdx.x;
    const int  b   = (int)(row >> 11);
    const float* x = sc + row * DS;
    const int* m = mask + (long)b * DS;
    float v[8];
    float mx = -3.4e38f;
    #pragma unroll
    for (int i = 0; i < 8; i++) {
        int c = threadIdx.x + i * 256;
        float t = x[c] + ((m[c] != 0) ? 0.f : -1e9f);
        v[i] = t;
        mx = fmaxf(mx, t);
    }
    mx = blockMax(mx);
    float s = 0.f;
    #pragma unroll
    for (int i = 0; i < 8; i++) { v[i] = expf(v[i] - mx); s += v[i]; }
    s = blockSum(s);
    const float inv = 1.f / s;
    #pragma unroll
    for (int i = 0; i < 8; i++) {
        int c = threadIdx.x + i * 256;
        hf h, l; split1(v[i] * inv, h, l);
        oh[row * DS + c] = h;
        ol[row * DS + c] = l;
    }
}

// ======================= launch =======================
static void split_full(const float* in, hf* oh, hf* ol, long rows, long cols) {
    long total4 = rows * (cols / 4);
    split_mat<<<(unsigned)((total4 + 255) / 256), 256>>>(in, cols, oh, ol, cols, (int)(cols / 4), total4);
}

extern "C" void kernel_launch(void* const* d_in, const int* in_sizes, int n_in,
                              void* d_out, int out_size)
{
    const float* vlm    = (const float*)d_in[0];
    const int*   mask   = (const int*)d_in[1];
    const float* l_in_w = (const float*)d_in[2];
    const float* l_in_b = (const float*)d_in[3];
    const float* l_out_w= (const float*)d_in[4];
    const float* l_out_b= (const float*)d_in[5];
    const float* l_ng   = (const float*)d_in[6];
    const float* l_nb   = (const float*)d_in[7];
    const float* l_pw   = (const float*)d_in[8];
    const float* l_pb   = (const float*)d_in[9];
    const float* g_in_w = (const float*)d_in[10];
    const float* g_in_b = (const float*)d_in[11];
    const float* g_out_w= (const float*)d_in[12];
    const float* g_out_b= (const float*)d_in[13];
    const float* g_ng   = (const float*)d_in[14];
    const float* g_nb   = (const float*)d_in[15];
    const float* qtok   = (const float*)d_in[16];
    const float* o_pw   = (const float*)d_in[17];
    const float* o_pb   = (const float*)d_in[18];
    float* out = (float*)d_out;

    cudaFuncSetAttribute(gemm_tc<0>, cudaFuncAttributeMaxDynamicSharedMemorySize, GSMEM);
    cudaFuncSetAttribute(gemm_tc<1>, cudaFuncAttributeMaxDynamicSharedMemorySize, GSMEM);

    float *p_qkv, *p_y, *p_sc, *p_yg;
    cudaGetSymbolAddress((void**)&p_qkv, g_qkv);
    cudaGetSymbolAddress((void**)&p_y,   g_y);
    cudaGetSymbolAddress((void**)&p_sc,  g_sc);
    cudaGetSymbolAddress((void**)&p_yg,  g_yg);

    hf *vlm_h,*liw_h,*low_h,*lpw_h,*giw_h,*gow_h,*opw_h,
       *attnl_h,*attnl_l,*ln_h,*ln_l,*lf_h,*qtok_h,*qtok_l,
       *qg_h,*qg_l,*kvk_h,*vt_h,*sc_h,*sc_l,*ag_h,*ag_l,*lng_h,*lng_l;
    cudaGetSymbolAddress((void**)&vlm_h, b_vlm_h);
    cudaGetSymbolAddress((void**)&liw_h, b_liw_h);
    cudaGetSymbolAddress((void**)&low_h, b_low_h);
    cudaGetSymbolAddress((void**)&lpw_h, b_lpw_h);
    cudaGetSymbolAddress((void**)&giw_h, b_giw_h);
    cudaGetSymbolAddress((void**)&gow_h, b_gow_h);
    cudaGetSymbolAddress((void**)&opw_h, b_opw_h);
    cudaGetSymbolAddress((void**)&attnl_h, b_attnl_h); cudaGetSymbolAddress((void**)&attnl_l, b_attnl_l);
    cudaGetSymbolAddress((void**)&ln_h,  b_ln_h);    cudaGetSymbolAddress((void**)&ln_l,  b_ln_l);
    cudaGetSymbolAddress((void**)&lf_h,  b_lf_h);
    cudaGetSymbolAddress((void**)&qtok_h,b_qtok_h);  cudaGetSymbolAddress((void**)&qtok_l,b_qtok_l);
    cudaGetSymbolAddress((void**)&qg_h,  b_qg_h);    cudaGetSymbolAddress((void**)&qg_l,  b_qg_l);
    cudaGetSymbolAddress((void**)&kvk_h, b_kvk_h);
    cudaGetSymbolAddress((void**)&vt_h,  b_vt_h);
    cudaGetSymbolAddress((void**)&sc_h,  b_sc_h);    cudaGetSymbolAddress((void**)&sc_l,  b_sc_l);
    cudaGetSymbolAddress((void**)&ag_h,  b_ag_h);    cudaGetSymbolAddress((void**)&ag_l,  b_ag_l);
    cudaGetSymbolAddress((void**)&lng_h, b_lng_h);   cudaGetSymbolAddress((void**)&lng_l, b_lng_l);

    const dim3 T256(256);
    #define GEMM(UL,Ah,Al,lda,Bh,ldb,C,Oh,Ol,ldc,bias,res,resMod,resLd,K,scale,M,N,kvM,zTot,zInner,aIn,aOut,bIn,bOut,cIn,cOut) \
        gemm_tc<UL><<<dim3(((M)/128)*((N)/128), 1, zTot), T256, GSMEM>>>( \
            Ah, Al, lda, Bh, ldb, C, Oh, Ol, ldc, bias, res, resMod, resLd, \
            K, scale, (M)/128, (N)/128, kvM, zInner, aIn, aOut, bIn, bOut, cIn, cOut)
    #define NOF (const float*)nullptr
    #define NOC (float*)nullptr
    #define NOH (hf*)nullptr

    // input/weight splits (weights + vlm: hi only)
    split_full(vlm,     vlm_h,  NOH,    NTOK,   DD);
    split_full(l_in_w,  liw_h,  NOH,    3*DD,   DD);
    split_full(l_out_w, low_h,  NOH,    DD,     DD);
    split_full(l_pw,    lpw_h,  NOH,    DD,     DD);
    split_full(g_in_w,  giw_h,  NOH,    3*DD,   DD);
    split_full(g_out_w, gow_h,  NOH,    DD,     DD);
    split_full(o_pw,    opw_h,  NOH,    DD,     DD);
    split_full(qtok,    qtok_h, qtok_l, DT,     DD);

    // 1) local QKV (single-product fp16 A), fp32 out (consumed by local_attn)
    GEMM(0, vlm_h, vlm_h, DD, liw_h, DD, p_qkv, NOH, NOH, 3*DD, l_in_b,
         NOF, 1, 1, DD, 1.f, NTOK, 3*DD, 0, 1, 1, 0,0,0,0,0,0);

    // 2) local windowed attention -> fp16 split directly
    local_attn<<<dim3(DB * (DS / DW), NH), T256>>>(p_qkv, mask, attnl_h, attnl_l);

    // 3) local out_proj + residual(vlm) [2-product], fp32 out (consumed by LN)
    GEMM(1, attnl_h, attnl_l, DD, low_h, DD, p_y, NOH, NOH, DD, l_out_b,
         vlm, NTOK, DD, DD, 1.f, NTOK, DD, 0, 1, 1, 0,0,0,0,0,0);

    // 4) LN local -> fp16 split directly
    layernorm_bf<<<NTOK, T256>>>(p_y, l_ng, l_nb, ln_h, ln_l);

    // 5) local_proj -> local_features [2-product], hi-only out (stage 7 is 1-product)
    GEMM(1, ln_h, ln_l, DD, lpw_h, DD, NOC, lf_h, NOH, DD, l_pb,
         NOF, 1, 1, DD, 1.f, NTOK, DD, 0, 1, 1, 0,0,0,0,0,0);

    // 6) global q (batch-invariant) [2-product], fp16 split out
    GEMM(1, qtok_h, qtok_l, DD, giw_h, DD, NOC, qg_h, qg_l, DD, g_in_b,
         NOF, 1, 1, DD, 1.f, DT, DD, 0, 1, 1, 0,0,0,0,0,0);

    // 7) global k,v (single-product fp16 A) — fused: K -> kvk_h, V -> vt_h transposed
    GEMM(0, lf_h, lf_h, DD, giw_h + (long)DD*DD, DD,
         NOC, kvk_h, vt_h, DD, g_in_b + DD,
         NOF, 1, 1, DD, 1.f, NTOK, 2*DD, 1, 1, 1, 0,0,0,0,0,0);

    // 8) scores (batched 32): (256 x 2048 x 512) [2-product], scaled, fp32 out
    GEMM(1, qg_h, qg_l, DD, kvk_h, DD, p_sc, NOH, NOH, DS,
         NOF, NOF, 1, 1,
         DH_, SCL, DT, DS, 0, DB*NH, NH,
         /*aIn*/DH_, /*aOut*/0,
         /*bIn*/DH_, /*bOut*/(long)DS * DD,
         /*cIn*/(long)DT * DS, /*cOut*/(long)NH * DT * DS);

    // 9) softmax over keys -> fp16 split directly
    softmax_bf<<<DB * NH * DT, T256>>>(p_sc, mask, sc_h, sc_l);

    // 10) AV (batched 32): (256 x 512 x 2048) [2-product], fp16 split out
    GEMM(1, sc_h, sc_l, DS, vt_h, DS, NOC, ag_h, ag_l, DD,
         NOF, NOF, 1, 1,
         DS, 1.f, DT, DH_, 0, DB*NH, NH,
         /*aIn*/(long)DT * DS, /*aOut*/(long)NH * DT * DS,
         /*bIn*/(long)DH_ * DS, /*bOut*/(long)DD * DS,
         /*cIn*/DH_, /*cOut*/(long)DT * DD);

    // 11) global out_proj + residual(query_tokens broadcast) [2-product], fp32 out
    GEMM(1, ag_h, ag_l, DD, gow_h, DD, p_yg, NOH, NOH, DD, g_out_b,
         qtok, DT, DD, DD, 1.f, NQ, DD, 0, 1, 1, 0,0,0,0,0,0);

    // 12) LN global -> fp16 split directly
    layernorm_bf<<<NQ, T256>>>(p_yg, g_ng, g_nb, lng_h, lng_l);

    // 13) output_proj -> d_out (fp32) [2-product]
    GEMM(1, lng_h, lng_l, DD, opw_h, DD, out, NOH, NOH, DD, o_pb,
         NOF, 1, 1, DD, 1.f, NQ, DD, 0, 1, 1, 0,0,0,0,0,0);
}

// round 12
// speedup vs baseline: 6.2999x; 1.1595x over previous
#include <cuda_runtime.h>
#include <cuda_fp16.h>
#include <cstdint>

// ---------------- problem constants ----------------
// B=4, S=2048, D=4096, T=256, W=32, H=8, DH=512
#define DB   4
#define DS   2048
#define DD   4096
#define DT   256
#define DW   32
#define DH_  512
#define NH   8
#define NTOK (DB*DS)            // 8192
#define NQ   (DB*DT)            // 1024
#define SCL  0.044194173824159216f  // 1/sqrt(512)

typedef __half hf;

// ---------------- device scratch (no allocations allowed) ----------------
__device__ float g_qkv  [ (long)NTOK * 3 * DD ];
__device__ float g_y    [ (long)NTOK * DD ];
__device__ float g_sc   [ (long)DB * NH * DT * DS ];
__device__ float g_yg   [ (long)NQ * DD ];
// fp16 split operands: hi for everything; lo only where consumed by 2-product GEMMs
__device__ __align__(16) hf b_vlm_h  [(long)NTOK*DD];
__device__ __align__(16) hf b_liw_h  [(long)3*DD*DD];
__device__ __align__(16) hf b_low_h  [(long)DD*DD];
__device__ __align__(16) hf b_lpw_h  [(long)DD*DD];
__device__ __align__(16) hf b_giw_h  [(long)3*DD*DD];
__device__ __align__(16) hf b_gow_h  [(long)DD*DD];
__device__ __align__(16) hf b_opw_h  [(long)DD*DD];
__device__ __align__(16) hf b_attnl_h[(long)NTOK*DD];
__device__ __align__(16) hf b_ln_h   [(long)NTOK*DD];
__device__ __align__(16) hf b_lf_h   [(long)NTOK*DD];
__device__ __align__(16) hf b_qtok_h [(long)DT*DD],        b_qtok_l [(long)DT*DD];
__device__ __align__(16) hf b_qg_h   [(long)DT*DD],        b_qg_l   [(long)DT*DD];
__device__ __align__(16) hf b_kvk_h  [(long)NTOK*DD];                    // B-role only
__device__ __align__(16) hf b_vt_h   [(long)DB*DD*DS];                   // B-role only
__device__ __align__(16) hf b_sc_h   [(long)DB*NH*DT*DS],  b_sc_l   [(long)DB*NH*DT*DS];
__device__ __align__(16) hf b_ag_h   [(long)NQ*DD],        b_ag_l   [(long)NQ*DD];
__device__ __align__(16) hf b_lng_h  [(long)NQ*DD],        b_lng_l  [(long)NQ*DD];

// ======================= helpers =======================
__device__ __forceinline__ uint32_t smem_u32(const void* p) {
    uint32_t a;
    asm("{ .reg .u64 t; cvta.to.shared.u64 t, %1; cvt.u32.u64 %0, t; }" : "=r"(a) : "l"(p));
    return a;
}
__device__ __forceinline__ void cp16(uint32_t dst, const void* src) {
    asm volatile("cp.async.cg.shared.global [%0], [%1], 16;" :: "r"(dst), "l"(src));
}
__device__ __forceinline__ void cp_commit() { asm volatile("cp.async.commit_group;" ::: "memory"); }
template <int N> __device__ __forceinline__ void cp_wait() {
    asm volatile("cp.async.wait_group %0;" :: "n"(N) : "memory");
}
__device__ __forceinline__ void ldsm4(uint32_t* r, uint32_t a) {
    asm volatile("ldmatrix.sync.aligned.m8n8.x4.shared.b16 {%0,%1,%2,%3}, [%4];"
        : "=r"(r[0]), "=r"(r[1]), "=r"(r[2]), "=r"(r[3]) : "r"(a));
}
// D += A*B  (m16n8k16, fp16 in, fp32 acc)
__device__ __forceinline__ void mma16816(float* d, const uint32_t* a, const uint32_t* b) {
    asm volatile(
        "mma.sync.aligned.m16n8k16.row.col.f32.f16.f16.f32 "
        "{%0,%1,%2,%3}, {%4,%5,%6,%7}, {%8,%9}, {%0,%1,%2,%3};"
        : "+f"(d[0]), "+f"(d[1]), "+f"(d[2]), "+f"(d[3])
        : "r"(a[0]), "r"(a[1]), "r"(a[2]), "r"(a[3]), "r"(b[0]), "r"(b[1]));
}
__device__ __forceinline__ void split1(float v, hf& h, hf& l) {
    h = __float2half_rn(v);
    l = __float2half_rn(v - __half2float(h));
}
// XOR swizzle: row pitch 64B, 16B unit c in 0..3; conflict-free 8-row ldmatrix groups
__device__ __forceinline__ uint32_t swz(int r, int c) {
    return (uint32_t)(r * 64 + ((c ^ ((r >> 1) & 3)) << 4));
}

// ======================= fp16 HMMA GEMM (1 or 2 products) =======================
// C(M,N) = scale * (Ah [+Al]) @ Bh^T + bias + res
// 128x128 tile, K-chunk 32, 4-stage cp.async, single __syncthreads/iter, 2 CTAs/SM.
// stage (24KB): Ah[128][32] Al Bh[128][32], pitch 64B, XOR-swizzled.
#define GSTG   24576
#define GSMEM  (4*GSTG)
#define OFF_AL 8192u
#define OFF_BH 16384u

template <int USELO>
__device__ __forceinline__ void load_chunk(
    uint32_t sb, int slot, long k0, int tid,
    const hf* __restrict__ Ah, const hf* __restrict__ Al, long lda, long bm,
    const hf* __restrict__ Bh, long ldb, long bn)
{
    uint32_t base = sb + (uint32_t)slot * GSTG;
    #pragma unroll
    for (int it = 0; it < 2; it++) {
        int u = tid + it * 256;            // 0..511
        int r = u >> 2, c = u & 3;         // row 0..127, 16B-col 0..3
        uint32_t off = swz(r, c);
        long srcA = (bm + r) * lda + k0 + c * 8;
        cp16(base + off, Ah + srcA);
        if (USELO) cp16(base + OFF_AL + off, Al + srcA);
        cp16(base + OFF_BH + off, Bh + (bn + r) * ldb + k0 + c * 8);
    }
    cp_commit();
}

template <int USELO>
__global__ __launch_bounds__(256, 2) void gemm_tc(
    const hf* __restrict__ Ah, const hf* __restrict__ Al, long lda,
    const hf* __restrict__ Bh, long ldb,
    float* __restrict__ C,
    hf* __restrict__ Oh, hf* __restrict__ Ol,
    long ldc,
    const float* __restrict__ bias,
    const float* __restrict__ res, int resMod, long resLd,
    int K, float scale, int nTm, int nTn, int kvMode,
    int zInner, long aIn, long aOut, long bIn, long bOut, long cIn, long cOut)
{
    extern __shared__ __align__(128) char smem[];
    const uint32_t sb = smem_u32(smem);
    const int tid = threadIdx.x;
    const int wid = tid >> 5;
    const int lane = tid & 31;

    const int z = blockIdx.z;
    const int zi = z % zInner, zo = z / zInner;
    Ah += (long)zi * aIn + (long)zo * aOut;  Al += (long)zi * aIn + (long)zo * aOut;
    Bh += (long)zi * bIn + (long)zo * bOut;
    const long coff = (long)zi * cIn + (long)zo * cOut;
    if (C)  C  += coff;
    if (Oh && !kvMode) { Oh += coff; if (Ol) Ol += coff; }

    // L2-friendly rasterization: bands of 8 N-tiles
    const int idx = blockIdx.x;
    const int per = nTm * 8;
    const int band = idx / per, rem = idx % per;
    const long bm = (long)(rem % nTm) * 128;
    const long bn = (long)(band * 8 + rem / nTm) * 128;

    // warp layout: 4(M) x 2(N); warp tile 32x64
    const int wm = wid & 3;
    const int wn = wid >> 2;

    const int aRow = wm * 32 + (lane & 15);           // + m*16
    const int aC0  = (lane >> 4);                      // + ks*2
    const int bRow = wn * 64 + (lane & 7) + ((lane >> 4) & 1) * 8;  // + p*16
    const int bC0  = ((lane >> 3) & 1);                // + ks*2

    float acc[2][8][4];
    #pragma unroll
    for (int i = 0; i < 2; i++)
        #pragma unroll
        for (int j = 0; j < 8; j++)
            #pragma unroll
            for (int q = 0; q < 4; q++) acc[i][j][q] = 0.f;

    const int nCh = K >> 5;        // K-chunk 32; all K here >= 512
    load_chunk<USELO>(sb, 0, 0,  tid, Ah, Al, lda, bm, Bh, ldb, bn);
    load_chunk<USELO>(sb, 1, 32, tid, Ah, Al, lda, bm, Bh, ldb, bn);
    load_chunk<USELO>(sb, 2, 64, tid, Ah, Al, lda, bm, Bh, ldb, bn);

    for (int i = 0; i < nCh; i++) {
        if (i + 2 < nCh)      cp_wait<2>();
        else if (i + 1 < nCh) cp_wait<1>();
        else                  cp_wait<0>();
        __syncthreads();
        if (i + 3 < nCh)
            load_chunk<USELO>(sb, (i + 3) & 3, (long)(i + 3) * 32, tid,
                              Ah, Al, lda, bm, Bh, ldb, bn);
        const uint32_t stg = sb + (uint32_t)(i & 3) * GSTG;
        #pragma unroll
        for (int ks = 0; ks < 2; ks++) {
            uint32_t ah[2][4], al[2][4];
            #pragma unroll
            for (int m = 0; m < 2; m++) {
                uint32_t a = stg + swz(aRow + m * 16, aC0 + ks * 2);
                ldsm4(ah[m], a);
                if (USELO) ldsm4(al[m], a + OFF_AL);
            }
            #pragma unroll
            for (int p = 0; p < 4; p++) {
                uint32_t bh[4];
                ldsm4(bh, stg + OFF_BH + swz(bRow + p * 16, bC0 + ks * 2));
                #pragma unroll
                for (int m = 0; m < 2; m++)
                    #pragma unroll
                    for (int s = 0; s < 2; s++) {
                        const int nt = p * 2 + s;
                        mma16816(acc[m][nt], ah[m], &bh[s * 2]);
                        if (USELO) mma16816(acc[m][nt], al[m], &bh[s * 2]);
                    }
            }
        }
    }

    // ---- epilogue: fused scale/bias/residual; fp32 / fp16-split / KV out ----
    const int r0 = lane >> 2;
    const int c0 = (lane & 3) * 2;
    const bool isV = kvMode && (bn >= DD);   // 128-wide tiles never straddle K/V halves
    #pragma unroll
    for (int m = 0; m < 2; m++) {
        #pragma unroll
        for (int half = 0; half < 2; half++) {
            const long grow = bm + wm * 32 + m * 16 + r0 + half * 8;
            const long rrow = (grow % resMod) * resLd;
            #pragma unroll
            for (int nt = 0; nt < 8; nt++) {
                const long gcol = bn + wn * 64 + nt * 8 + c0;
                float vx = acc[m][nt][half * 2]     * scale;
                float vy = acc[m][nt][half * 2 + 1] * scale;
                if (bias) {
                    float2 bb = *(const float2*)&bias[gcol];
                    vx += bb.x; vy += bb.y;
                }
                if (res) {
                    float2 rr = *(const float2*)&res[rrow + gcol];
                    vx += rr.x; vy += rr.y;
                }
                if (kvMode) {
                    if (!isV) {
                        // K half: kvk_h[grow*DD + gcol], hi only, coalesced half2
                        __half2 hv; hv.x = __float2half_rn(vx); hv.y = __float2half_rn(vy);
                        *(__half2*)&Oh[grow * DD + gcol] = hv;
                    } else {
                        // V half: transposed vt_h[((b*DD)+d)*DS + s], hi only
                        const int d = (int)(gcol - DD);
                        const long b = grow >> 11;        // grow / DS
                        const long s = grow & (DS - 1);
                        const long o = (b * DD + d) * DS + s;
                        Ol[o]      = __float2half_rn(vx);
                        Ol[o + DS] = __float2half_rn(vy);
                    }
                } else {
                    if (C) {
                        float2 v; v.x = vx; v.y = vy;
                        *(float2*)&C[grow * ldc + gcol] = v;
                    }
                    if (Oh) {
                        hf hx, lx, hy, ly;
                        split1(vx, hx, lx); split1(vy, hy, ly);
                        __half2 hv; hv.x = hx; hv.y = hy;
                        *(__half2*)&Oh[grow * ldc + gcol] = hv;
                        if (Ol) {
                            __half2 lv; lv.x = lx; lv.y = ly;
                            *(__half2*)&Ol[grow * ldc + gcol] = lv;
                        }
                    }
                }
            }
        }
    }
}

// ======================= split conversions =======================
// ol may be null (hi only)
__global__ __launch_bounds__(256) void split_mat(
    const float* __restrict__ in, long ldIn,
    hf* __restrict__ oh, hf* __restrict__ ol, long ldOut,
    int cols4, long total4)
{
    long idx = (long)blockIdx.x * 256 + threadIdx.x;
    if (idx >= total4) return;
    long r = idx / cols4;
    int  c = (int)(idx - r * cols4);
    float4 v = *(const float4*)(in + r * ldIn + c * 4);
    hf h0, h1, h2, h3, l0, l1, l2, l3;
    split1(v.x, h0, l0); split1(v.y, h1, l1);
    split1(v.z, h2, l2); split1(v.w, h3, l3);
    __half2* ph = (__half2*)(oh + r * ldOut + c * 4);
    __half2 a; a.x = h0; a.y = h1; ph[0] = a;
    a.x = h2; a.y = h3; ph[1] = a;
    if (ol) {
        __half2* pl = (__half2*)(ol + r * ldOut + c * 4);
        a.x = l0; a.y = l1; pl[0] = a;
        a.x = l2; a.y = l3; pl[1] = a;
    }
}

// ======================= reductions =======================
__device__ __forceinline__ float blockSum(float val) {
    __shared__ float sh[32];
    int lane = threadIdx.x & 31, w = threadIdx.x >> 5;
    #pragma unroll
    for (int o = 16; o; o >>= 1) val += __shfl_xor_sync(0xffffffffu, val, o);
    __syncthreads();
    if (lane == 0) sh[w] = val;
    __syncthreads();
    val = (lane < 8) ? sh[lane] : 0.f;
    #pragma unroll
    for (int o = 4; o; o >>= 1) val += __shfl_xor_sync(0xffffffffu, val, o);
    return __shfl_sync(0xffffffffu, val, 0);
}
__device__ __forceinline__ float blockMax(float val) {
    __shared__ float sh[32];
    int lane = threadIdx.x & 31, w = threadIdx.x >> 5;
    #pragma unroll
    for (int o = 16; o; o >>= 1) val = fmaxf(val, __shfl_xor_sync(0xffffffffu, val, o));
    __syncthreads();
    if (lane == 0) sh[w] = val;
    __syncthreads();
    val = (lane < 8) ? sh[lane] : -3.4e38f;
    #pragma unroll
    for (int o = 4; o; o >>= 1) val = fmaxf(val, __shfl_xor_sync(0xffffffffu, val, o));
    return __shfl_sync(0xffffffffu, val, 0);
}

// ---------------- local windowed attention: fp32 qkv -> fp16 hi out ----------------
__global__ __launch_bounds__(256) void local_attn(
    const float* __restrict__ qkv, const int* __restrict__ mask,
    hf* __restrict__ outH)
{
    const int  bw   = blockIdx.x;
    const int  h    = blockIdx.y;
    const long tok0 = (long)bw * DW;
    const int  LD   = 3 * DD;
    const float* qb = qkv + tok0 * LD + h * DH_;
    const float* kb = qkv + tok0 * LD + DD + h * DH_;
    const float* vb = qkv + tok0 * LD + 2 * DD + h * DH_;

    __shared__ float s[DW][DW + 1];
    __shared__ float msk[DW];
    const int tid = threadIdx.x;
    if (tid < DW) msk[tid] = (mask[tok0 + tid] != 0) ? 0.f : -1e9f;

    #pragma unroll
    for (int p = tid; p < DW * DW; p += 256) {
        int i = p >> 5, j = p & 31;
        const float4* qp = (const float4*)(qb + (long)i * LD);
        const float4* kp = (const float4*)(kb + (long)j * LD);
        float acc = 0.f;
        #pragma unroll 8
        for (int d = 0; d < DH_ / 4; d++) {
            float4 a = qp[d], c = kp[d];
            acc += a.x * c.x + a.y * c.y + a.z * c.z + a.w * c.w;
        }
        s[i][j] = acc;
    }
    __syncthreads();

    if (tid < DW) {
        const int i = tid;
        const float mi = msk[i];
        float r[DW];
        float mx = -3.4e38f;
        #pragma unroll
        for (int j = 0; j < DW; j++) {
            float bias = (mi + msk[j] < -0.5f) ? -1e9f : 0.f;
            r[j] = s[i][j] * SCL + bias;
            mx = fmaxf(mx, r[j]);
        }
        float sum = 0.f;
        #pragma unroll
        for (int j = 0; j < DW; j++) { r[j] = expf(r[j] - mx); sum += r[j]; }
        const float inv = 1.f / sum;
        #pragma unroll
        for (int j = 0; j < DW; j++) s[i][j] = r[j] * inv;
    }
    __syncthreads();

    float2 acc[DW];
    #pragma unroll
    for (int i = 0; i < DW; i++) acc[i] = make_float2(0.f, 0.f);
    for (int j = 0; j < DW; j++) {
        float2 v2 = *(const float2*)(vb + (long)j * LD + tid * 2);
        #pragma unroll
        for (int i = 0; i < DW; i++) {
            float w = s[i][j];
            acc[i].x += w * v2.x;
            acc[i].y += w * v2.y;
        }
    }
    const long obase = tok0 * DD + h * DH_ + tid * 2;
    #pragma unroll
    for (int i = 0; i < DW; i++) {
        __half2 hv;
        hv.x = __float2half_rn(acc[i].x);
        hv.y = __float2half_rn(acc[i].y);
        *(__half2*)&outH[obase + (long)i * DD] = hv;
    }
}

// ---------------- LayerNorm over rows of 4096 -> fp16 out (Yl optional) ----------------
__global__ __launch_bounds__(256) void layernorm_bf(
    const float* __restrict__ X, const float* __restrict__ g,
    const float* __restrict__ b, hf* __restrict__ Yh, hf* __restrict__ Yl)
{
    const long row = blockIdx.x;
    const float* x = X + row * DD;
    float v[16];
    float s = 0.f;
    #pragma unroll
    for (int i = 0; i < 16; i++) { v[i] = x[threadIdx.x + i * 256]; s += v[i]; }
    const float mean = blockSum(s) * (1.f / DD);
    float d2 = 0.f;
    #pragma unroll
    for (int i = 0; i < 16; i++) { float d = v[i] - mean; d2 += d * d; }
    const float var = blockSum(d2) * (1.f / DD);
    const float rs = rsqrtf(var + 1e-5f);
    #pragma unroll
    for (int i = 0; i < 16; i++) {
        int c = threadIdx.x + i * 256;
        float o = (v[i] - mean) * rs * g[c] + b[c];
        hf h, l; split1(o, h, l);
        Yh[row * DD + c] = h;
        if (Yl) Yl[row * DD + c] = l;
    }
}

// ---------------- global softmax over S=2048 keys -> fp16 split out ----------------
__global__ __launch_bounds__(256) void softmax_bf(
    const float* __restrict__ sc, const int* __restrict__ mask,
    hf* __restrict__ oh, hf* __restrict__ ol)
{
    const long row = blockIdx.x;
    const int  b   = (int)(row >> 11);
    const float* x = sc + row * DS;
    const int* m = mask + (long)b * DS;
    float v[8];
    float mx = -3.4e38f;
    #pragma unroll
    for (int i = 0; i < 8; i++) {
        int c = threadIdx.x + i * 256;
        float t = x[c] + ((m[c] != 0) ? 0.f : -1e9f);
        v[i] = t;
        mx = fmaxf(mx, t);
    }
    mx = blockMax(mx);
    float s = 0.f;
    #pragma unroll
    for (int i = 0; i < 8; i++) { v[i] = expf(v[i] - mx); s += v[i]; }
    s = blockSum(s);
    const float inv = 1.f / s;
    #pragma unroll
    for (int i = 0; i < 8; i++) {
        int c = threadIdx.x + i * 256;
        hf h, l; split1(v[i] * inv, h, l);
        oh[row * DS + c] = h;
        ol[row * DS + c] = l;
    }
}

// ======================= launch =======================
static void split_full(const float* in, hf* oh, hf* ol, long rows, long cols) {
    long total4 = rows * (cols / 4);
    split_mat<<<(unsigned)((total4 + 255) / 256), 256>>>(in, cols, oh, ol, cols, (int)(cols / 4), total4);
}

extern "C" void kernel_launch(void* const* d_in, const int* in_sizes, int n_in,
                              void* d_out, int out_size)
{
    const float* vlm    = (const float*)d_in[0];
    const int*   mask   = (const int*)d_in[1];
    const float* l_in_w = (const float*)d_in[2];
    const float* l_in_b = (const float*)d_in[3];
    const float* l_out_w= (const float*)d_in[4];
    const float* l_out_b= (const float*)d_in[5];
    const float* l_ng   = (const float*)d_in[6];
    const float* l_nb   = (const float*)d_in[7];
    const float* l_pw   = (const float*)d_in[8];
    const float* l_pb   = (const float*)d_in[9];
    const float* g_in_w = (const float*)d_in[10];
    const float* g_in_b = (const float*)d_in[11];
    const float* g_out_w= (const float*)d_in[12];
    const float* g_out_b= (const float*)d_in[13];
    const float* g_ng   = (const float*)d_in[14];
    const float* g_nb   = (const float*)d_in[15];
    const float* qtok   = (const float*)d_in[16];
    const float* o_pw   = (const float*)d_in[17];
    const float* o_pb   = (const float*)d_in[18];
    float* out = (float*)d_out;

    cudaFuncSetAttribute(gemm_tc<0>, cudaFuncAttributeMaxDynamicSharedMemorySize, GSMEM);
    cudaFuncSetAttribute(gemm_tc<1>, cudaFuncAttributeMaxDynamicSharedMemorySize, GSMEM);

    float *p_qkv, *p_y, *p_sc, *p_yg;
    cudaGetSymbolAddress((void**)&p_qkv, g_qkv);
    cudaGetSymbolAddress((void**)&p_y,   g_y);
    cudaGetSymbolAddress((void**)&p_sc,  g_sc);
    cudaGetSymbolAddress((void**)&p_yg,  g_yg);

    hf *vlm_h,*liw_h,*low_h,*lpw_h,*giw_h,*gow_h,*opw_h,
       *attnl_h,*ln_h,*lf_h,*qtok_h,*qtok_l,
       *qg_h,*qg_l,*kvk_h,*vt_h,*sc_h,*sc_l,*ag_h,*ag_l,*lng_h,*lng_l;
    cudaGetSymbolAddress((void**)&vlm_h, b_vlm_h);
    cudaGetSymbolAddress((void**)&liw_h, b_liw_h);
    cudaGetSymbolAddress((void**)&low_h, b_low_h);
    cudaGetSymbolAddress((void**)&lpw_h, b_lpw_h);
    cudaGetSymbolAddress((void**)&giw_h, b_giw_h);
    cudaGetSymbolAddress((void**)&gow_h, b_gow_h);
    cudaGetSymbolAddress((void**)&opw_h, b_opw_h);
    cudaGetSymbolAddress((void**)&attnl_h, b_attnl_h);
    cudaGetSymbolAddress((void**)&ln_h,  b_ln_h);
    cudaGetSymbolAddress((void**)&lf_h,  b_lf_h);
    cudaGetSymbolAddress((void**)&qtok_h,b_qtok_h);  cudaGetSymbolAddress((void**)&qtok_l,b_qtok_l);
    cudaGetSymbolAddress((void**)&qg_h,  b_qg_h);    cudaGetSymbolAddress((void**)&qg_l,  b_qg_l);
    cudaGetSymbolAddress((void**)&kvk_h, b_kvk_h);
    cudaGetSymbolAddress((void**)&vt_h,  b_vt_h);
    cudaGetSymbolAddress((void**)&sc_h,  b_sc_h);    cudaGetSymbolAddress((void**)&sc_l,  b_sc_l);
    cudaGetSymbolAddress((void**)&ag_h,  b_ag_h);    cudaGetSymbolAddress((void**)&ag_l,  b_ag_l);
    cudaGetSymbolAddress((void**)&lng_h, b_lng_h);   cudaGetSymbolAddress((void**)&lng_l, b_lng_l);

    const dim3 T256(256);
    #define GEMM(UL,Ah,Al,lda,Bh,ldb,C,Oh,Ol,ldc,bias,res,resMod,resLd,K,scale,M,N,kvM,zTot,zInner,aIn,aOut,bIn,bOut,cIn,cOut) \
        gemm_tc<UL><<<dim3(((M)/128)*((N)/128), 1, zTot), T256, GSMEM>>>( \
            Ah, Al, lda, Bh, ldb, C, Oh, Ol, ldc, bias, res, resMod, resLd, \
            K, scale, (M)/128, (N)/128, kvM, zInner, aIn, aOut, bIn, bOut, cIn, cOut)
    #define NOF (const float*)nullptr
    #define NOC (float*)nullptr
    #define NOH (hf*)nullptr

    // input/weight splits (weights + vlm: hi only)
    split_full(vlm,     vlm_h,  NOH,    NTOK,   DD);
    split_full(l_in_w,  liw_h,  NOH,    3*DD,   DD);
    split_full(l_out_w, low_h,  NOH,    DD,     DD);
    split_full(l_pw,    lpw_h,  NOH,    DD,     DD);
    split_full(g_in_w,  giw_h,  NOH,    3*DD,   DD);
    split_full(g_out_w, gow_h,  NOH,    DD,     DD);
    split_full(o_pw,    opw_h,  NOH,    DD,     DD);
    split_full(qtok,    qtok_h, qtok_l, DT,     DD);

    // 1) local QKV (1-product), fp32 out (consumed by local_attn)
    GEMM(0, vlm_h, vlm_h, DD, liw_h, DD, p_qkv, NOH, NOH, 3*DD, l_in_b,
         NOF, 1, 1, DD, 1.f, NTOK, 3*DD, 0, 1, 1, 0,0,0,0,0,0);

    // 2) local windowed attention -> fp16 hi only (stage 3 is 1-product)
    local_attn<<<dim3(DB * (DS / DW), NH), T256>>>(p_qkv, mask, attnl_h);

    // 3) local out_proj + residual(vlm) [1-product], fp32 out (consumed by LN)
    GEMM(0, attnl_h, attnl_h, DD, low_h, DD, p_y, NOH, NOH, DD, l_out_b,
         vlm, NTOK, DD, DD, 1.f, NTOK, DD, 0, 1, 1, 0,0,0,0,0,0);

    // 4) LN local -> fp16 hi only (stage 5 is 1-product)
    layernorm_bf<<<NTOK, T256>>>(p_y, l_ng, l_nb, ln_h, NOH);

    // 5) local_proj -> local_features [1-product], hi-only out (stage 7 is 1-product)
    GEMM(0, ln_h, ln_h, DD, lpw_h, DD, NOC, lf_h, NOH, DD, l_pb,
         NOF, 1, 1, DD, 1.f, NTOK, DD, 0, 1, 1, 0,0,0,0,0,0);

    // 6) global q (batch-invariant) [2-product], fp16 split out
    GEMM(1, qtok_h, qtok_l, DD, giw_h, DD, NOC, qg_h, qg_l, DD, g_in_b,
         NOF, 1, 1, DD, 1.f, DT, DD, 0, 1, 1, 0,0,0,0,0,0);

    // 7) global k,v (1-product) — fused: K -> kvk_h, V -> vt_h transposed
    GEMM(0, lf_h, lf_h, DD, giw_h + (long)DD*DD, DD,
         NOC, kvk_h, vt_h, DD, g_in_b + DD,
         NOF, 1, 1, DD, 1.f, NTOK, 2*DD, 1, 1, 1, 0,0,0,0,0,0);

    // 8) scores (batched 32): (256 x 2048 x 512) [2-product], scaled, fp32 out
    GEMM(1, qg_h, qg_l, DD, kvk_h, DD, p_sc, NOH, NOH, DS,
         NOF, NOF, 1, 1,
         DH_, SCL, DT, DS, 0, DB*NH, NH,
         /*aIn*/DH_, /*aOut*/0,
         /*bIn*/DH_, /*bOut*/(long)DS * DD,
         /*cIn*/(long)DT * DS, /*cOut*/(long)NH * DT * DS);

    // 9) softmax over keys -> fp16 split directly
    softmax_bf<<<DB * NH * DT, T256>>>(p_sc, mask, sc_h, sc_l);

    // 10) AV (batched 32): (256 x 512 x 2048) [2-product], fp16 split out
    GEMM(1, sc_h, sc_l, DS, vt_h, DS, NOC, ag_h, ag_l, DD,
         NOF, NOF, 1, 1,
         DS, 1.f, DT, DH_, 0, DB*NH, NH,
         /*aIn*/(long)DT * DS, /*aOut*/(long)NH * DT * DS,
         /*bIn*/(long)DH_ * DS, /*bOut*/(long)DD * DS,
         /*cIn*/DH_, /*cOut*/(long)DT * DD);

    // 11) global out_proj + residual(query_tokens broadcast) [2-product], fp32 out
    GEMM(1, ag_h, ag_l, DD, gow_h, DD, p_yg, NOH, NOH, DD, g_out_b,
         qtok, DT, DD, DD, 1.f, NQ, DD, 0, 1, 1, 0,0,0,0,0,0);

    // 12) LN global -> fp16 split directly (stage 13 is 2-product)
    layernorm_bf<<<NQ, T256>>>(p_yg, g_ng, g_nb, lng_h, lng_l);

    // 13) output_proj -> d_out (fp32) [2-product]
    GEMM(1, lng_h, lng_l, DD, opw_h, DD, out, NOH, NOH, DD, o_pb,
         NOF, 1, 1, DD, 1.f, NQ, DD, 0, 1, 1, 0,0,0,0,0,0);
}

// round 13
// speedup vs baseline: 6.5391x; 1.0380x over previous
#include <cuda_runtime.h>
#include <cuda_fp16.h>
#include <cstdint>

// ---------------- problem constants ----------------
// B=4, S=2048, D=4096, T=256, W=32, H=8, DH=512
#define DB   4
#define DS   2048
#define DD   4096
#define DT   256
#define DW   32
#define DH_  512
#define NH   8
#define NTOK (DB*DS)            // 8192
#define NQ   (DB*DT)            // 1024
#define SCL  0.044194173824159216f  // 1/sqrt(512)

typedef __half hf;

// ---------------- device scratch (no allocations allowed) ----------------
__device__ float g_qkv  [ (long)NTOK * 3 * DD ];
__device__ float g_y    [ (long)NTOK * DD ];
__device__ float g_sc   [ (long)DB * NH * DT * DS ];
__device__ float g_yg   [ (long)NQ * DD ];
// fp16 split operands: hi for everything; lo only where consumed by 2-product GEMMs
__device__ __align__(16) hf b_vlm_h  [(long)NTOK*DD];
__device__ __align__(16) hf b_liw_h  [(long)3*DD*DD];
__device__ __align__(16) hf b_low_h  [(long)DD*DD];
__device__ __align__(16) hf b_lpw_h  [(long)DD*DD];
__device__ __align__(16) hf b_giw_h  [(long)3*DD*DD];
__device__ __align__(16) hf b_gow_h  [(long)DD*DD];
__device__ __align__(16) hf b_opw_h  [(long)DD*DD];
__device__ __align__(16) hf b_attnl_h[(long)NTOK*DD];
__device__ __align__(16) hf b_ln_h   [(long)NTOK*DD];
__device__ __align__(16) hf b_lf_h   [(long)NTOK*DD];
__device__ __align__(16) hf b_qtok_h [(long)DT*DD],        b_qtok_l [(long)DT*DD];
__device__ __align__(16) hf b_qg_h   [(long)DT*DD];
__device__ __align__(16) hf b_kvk_h  [(long)NTOK*DD];                    // B-role only
__device__ __align__(16) hf b_vt_h   [(long)DB*DD*DS];                   // B-role only
__device__ __align__(16) hf b_sc_h   [(long)DB*NH*DT*DS];
__device__ __align__(16) hf b_ag_h   [(long)NQ*DD];
__device__ __align__(16) hf b_lng_h  [(long)NQ*DD];

// ======================= helpers =======================
__device__ __forceinline__ uint32_t smem_u32(const void* p) {
    uint32_t a;
    asm("{ .reg .u64 t; cvta.to.shared.u64 t, %1; cvt.u32.u64 %0, t; }" : "=r"(a) : "l"(p));
    return a;
}
__device__ __forceinline__ void cp16(uint32_t dst, const void* src) {
    asm volatile("cp.async.cg.shared.global [%0], [%1], 16;" :: "r"(dst), "l"(src));
}
__device__ __forceinline__ void cp_commit() { asm volatile("cp.async.commit_group;" ::: "memory"); }
template <int N> __device__ __forceinline__ void cp_wait() {
    asm volatile("cp.async.wait_group %0;" :: "n"(N) : "memory");
}
__device__ __forceinline__ void ldsm4(uint32_t* r, uint32_t a) {
    asm volatile("ldmatrix.sync.aligned.m8n8.x4.shared.b16 {%0,%1,%2,%3}, [%4];"
        : "=r"(r[0]), "=r"(r[1]), "=r"(r[2]), "=r"(r[3]) : "r"(a));
}
// D += A*B  (m16n8k16, fp16 in, fp32 acc)
__device__ __forceinline__ void mma16816(float* d, const uint32_t* a, const uint32_t* b) {
    asm volatile(
        "mma.sync.aligned.m16n8k16.row.col.f32.f16.f16.f32 "
        "{%0,%1,%2,%3}, {%4,%5,%6,%7}, {%8,%9}, {%0,%1,%2,%3};"
        : "+f"(d[0]), "+f"(d[1]), "+f"(d[2]), "+f"(d[3])
        : "r"(a[0]), "r"(a[1]), "r"(a[2]), "r"(a[3]), "r"(b[0]), "r"(b[1]));
}
__device__ __forceinline__ void split1(float v, hf& h, hf& l) {
    h = __float2half_rn(v);
    l = __float2half_rn(v - __half2float(h));
}
// XOR swizzle: row pitch 64B, 16B unit c in 0..3; conflict-free 8-row ldmatrix groups
__device__ __forceinline__ uint32_t swz(int r, int c) {
    return (uint32_t)(r * 64 + ((c ^ ((r >> 1) & 3)) << 4));
}

// ======================= fp16 HMMA GEMM (1 or 2 products) =======================
// C(M,N) = scale * (Ah [+Al]) @ Bh^T + bias + res
// 128x128 tile, K-chunk 32, 4-stage cp.async, single __syncthreads/iter, 2 CTAs/SM.
// stage (24KB): Ah[128][32] Al Bh[128][32], pitch 64B, XOR-swizzled.
#define GSTG   24576
#define GSMEM  (4*GSTG)
#define OFF_AL 8192u
#define OFF_BH 16384u

template <int USELO>
__device__ __forceinline__ void load_chunk(
    uint32_t sb, int slot, long k0, int tid,
    const hf* __restrict__ Ah, const hf* __restrict__ Al, long lda, long bm,
    const hf* __restrict__ Bh, long ldb, long bn)
{
    uint32_t base = sb + (uint32_t)slot * GSTG;
    #pragma unroll
    for (int it = 0; it < 2; it++) {
        int u = tid + it * 256;            // 0..511
        int r = u >> 2, c = u & 3;         // row 0..127, 16B-col 0..3
        uint32_t off = swz(r, c);
        long srcA = (bm + r) * lda + k0 + c * 8;
        cp16(base + off, Ah + srcA);
        if (USELO) cp16(base + OFF_AL + off, Al + srcA);
        cp16(base + OFF_BH + off, Bh + (bn + r) * ldb + k0 + c * 8);
    }
    cp_commit();
}

template <int USELO>
__global__ __launch_bounds__(256, 2) void gemm_tc(
    const hf* __restrict__ Ah, const hf* __restrict__ Al, long lda,
    const hf* __restrict__ Bh, long ldb,
    float* __restrict__ C,
    hf* __restrict__ Oh, hf* __restrict__ Ol,
    long ldc,
    const float* __restrict__ bias,
    const float* __restrict__ res, int resMod, long resLd,
    int K, float scale, int nTm, int nTn, int kvMode,
    int zInner, long aIn, long aOut, long bIn, long bOut, long cIn, long cOut)
{
    extern __shared__ __align__(128) char smem[];
    const uint32_t sb = smem_u32(smem);
    const int tid = threadIdx.x;
    const int wid = tid >> 5;
    const int lane = tid & 31;

    const int z = blockIdx.z;
    const int zi = z % zInner, zo = z / zInner;
    Ah += (long)zi * aIn + (long)zo * aOut;  Al += (long)zi * aIn + (long)zo * aOut;
    Bh += (long)zi * bIn + (long)zo * bOut;
    const long coff = (long)zi * cIn + (long)zo * cOut;
    if (C)  C  += coff;
    if (Oh && !kvMode) { Oh += coff; if (Ol) Ol += coff; }

    // L2-friendly rasterization: bands of 8 N-tiles
    const int idx = blockIdx.x;
    const int per = nTm * 8;
    const int band = idx / per, rem = idx % per;
    const long bm = (long)(rem % nTm) * 128;
    const long bn = (long)(band * 8 + rem / nTm) * 128;

    // warp layout: 4(M) x 2(N); warp tile 32x64
    const int wm = wid & 3;
    const int wn = wid >> 2;

    const int aRow = wm * 32 + (lane & 15);           // + m*16
    const int aC0  = (lane >> 4);                      // + ks*2
    const int bRow = wn * 64 + (lane & 7) + ((lane >> 4) & 1) * 8;  // + p*16
    const int bC0  = ((lane >> 3) & 1);                // + ks*2

    float acc[2][8][4];
    #pragma unroll
    for (int i = 0; i < 2; i++)
        #pragma unroll
        for (int j = 0; j < 8; j++)
            #pragma unroll
            for (int q = 0; q < 4; q++) acc[i][j][q] = 0.f;

    const int nCh = K >> 5;        // K-chunk 32; all K here >= 512
    load_chunk<USELO>(sb, 0, 0,  tid, Ah, Al, lda, bm, Bh, ldb, bn);
    load_chunk<USELO>(sb, 1, 32, tid, Ah, Al, lda, bm, Bh, ldb, bn);
    load_chunk<USELO>(sb, 2, 64, tid, Ah, Al, lda, bm, Bh, ldb, bn);

    for (int i = 0; i < nCh; i++) {
        if (i + 2 < nCh)      cp_wait<2>();
        else if (i + 1 < nCh) cp_wait<1>();
        else                  cp_wait<0>();
        __syncthreads();
        if (i + 3 < nCh)
            load_chunk<USELO>(sb, (i + 3) & 3, (long)(i + 3) * 32, tid,
                              Ah, Al, lda, bm, Bh, ldb, bn);
        const uint32_t stg = sb + (uint32_t)(i & 3) * GSTG;
        #pragma unroll
        for (int ks = 0; ks < 2; ks++) {
            uint32_t ah[2][4], al[2][4];
            #pragma unroll
            for (int m = 0; m < 2; m++) {
                uint32_t a = stg + swz(aRow + m * 16, aC0 + ks * 2);
                ldsm4(ah[m], a);
                if (USELO) ldsm4(al[m], a + OFF_AL);
            }
            #pragma unroll
            for (int p = 0; p < 4; p++) {
                uint32_t bh[4];
                ldsm4(bh, stg + OFF_BH + swz(bRow + p * 16, bC0 + ks * 2));
                #pragma unroll
                for (int m = 0; m < 2; m++)
                    #pragma unroll
                    for (int s = 0; s < 2; s++) {
                        const int nt = p * 2 + s;
                        mma16816(acc[m][nt], ah[m], &bh[s * 2]);
                        if (USELO) mma16816(acc[m][nt], al[m], &bh[s * 2]);
                    }
            }
        }
    }

    // ---- epilogue: fused scale/bias/residual; fp32 / fp16-split / KV out ----
    const int r0 = lane >> 2;
    const int c0 = (lane & 3) * 2;
    const bool isV = kvMode && (bn >= DD);   // 128-wide tiles never straddle K/V halves
    #pragma unroll
    for (int m = 0; m < 2; m++) {
        #pragma unroll
        for (int half = 0; half < 2; half++) {
            const long grow = bm + wm * 32 + m * 16 + r0 + half * 8;
            const long rrow = (grow % resMod) * resLd;
            #pragma unroll
            for (int nt = 0; nt < 8; nt++) {
                const long gcol = bn + wn * 64 + nt * 8 + c0;
                float vx = acc[m][nt][half * 2]     * scale;
                float vy = acc[m][nt][half * 2 + 1] * scale;
                if (bias) {
                    float2 bb = *(const float2*)&bias[gcol];
                    vx += bb.x; vy += bb.y;
                }
                if (res) {
                    float2 rr = *(const float2*)&res[rrow + gcol];
                    vx += rr.x; vy += rr.y;
                }
                if (kvMode) {
                    if (!isV) {
                        // K half: kvk_h[grow*DD + gcol], hi only, coalesced half2
                        __half2 hv; hv.x = __float2half_rn(vx); hv.y = __float2half_rn(vy);
                        *(__half2*)&Oh[grow * DD + gcol] = hv;
                    } else {
                        // V half: transposed vt_h[((b*DD)+d)*DS + s], hi only
                        const int d = (int)(gcol - DD);
                        const long b = grow >> 11;        // grow / DS
                        const long s = grow & (DS - 1);
                        const long o = (b * DD + d) * DS + s;
                        Ol[o]      = __float2half_rn(vx);
                        Ol[o + DS] = __float2half_rn(vy);
                    }
                } else {
                    if (C) {
                        float2 v; v.x = vx; v.y = vy;
                        *(float2*)&C[grow * ldc + gcol] = v;
                    }
                    if (Oh) {
                        hf hx, lx, hy, ly;
                        split1(vx, hx, lx); split1(vy, hy, ly);
                        __half2 hv; hv.x = hx; hv.y = hy;
                        *(__half2*)&Oh[grow * ldc + gcol] = hv;
                        if (Ol) {
                            __half2 lv; lv.x = lx; lv.y = ly;
                            *(__half2*)&Ol[grow * ldc + gcol] = lv;
                        }
                    }
                }
            }
        }
    }
}

// ======================= split conversions =======================
// ol may be null (hi only)
__global__ __launch_bounds__(256) void split_mat(
    const float* __restrict__ in, long ldIn,
    hf* __restrict__ oh, hf* __restrict__ ol, long ldOut,
    int cols4, long total4)
{
    long idx = (long)blockIdx.x * 256 + threadIdx.x;
    if (idx >= total4) return;
    long r = idx / cols4;
    int  c = (int)(idx - r * cols4);
    float4 v = *(const float4*)(in + r * ldIn + c * 4);
    hf h0, h1, h2, h3, l0, l1, l2, l3;
    split1(v.x, h0, l0); split1(v.y, h1, l1);
    split1(v.z, h2, l2); split1(v.w, h3, l3);
    __half2* ph = (__half2*)(oh + r * ldOut + c * 4);
    __half2 a; a.x = h0; a.y = h1; ph[0] = a;
    a.x = h2; a.y = h3; ph[1] = a;
    if (ol) {
        __half2* pl = (__half2*)(ol + r * ldOut + c * 4);
        a.x = l0; a.y = l1; pl[0] = a;
        a.x = l2; a.y = l3; pl[1] = a;
    }
}

// ======================= reductions =======================
__device__ __forceinline__ float blockSum(float val) {
    __shared__ float sh[32];
    int lane = threadIdx.x & 31, w = threadIdx.x >> 5;
    #pragma unroll
    for (int o = 16; o; o >>= 1) val += __shfl_xor_sync(0xffffffffu, val, o);
    __syncthreads();
    if (lane == 0) sh[w] = val;
    __syncthreads();
    val = (lane < 8) ? sh[lane] : 0.f;
    #pragma unroll
    for (int o = 4; o; o >>= 1) val += __shfl_xor_sync(0xffffffffu, val, o);
    return __shfl_sync(0xffffffffu, val, 0);
}
__device__ __forceinline__ float blockMax(float val) {
    __shared__ float sh[32];
    int lane = threadIdx.x & 31, w = threadIdx.x >> 5;
    #pragma unroll
    for (int o = 16; o; o >>= 1) val = fmaxf(val, __shfl_xor_sync(0xffffffffu, val, o));
    __syncthreads();
    if (lane == 0) sh[w] = val;
    __syncthreads();
    val = (lane < 8) ? sh[lane] : -3.4e38f;
    #pragma unroll
    for (int o = 4; o; o >>= 1) val = fmaxf(val, __shfl_xor_sync(0xffffffffu, val, o));
    return __shfl_sync(0xffffffffu, val, 0);
}

// ---------------- local windowed attention: fp32 qkv -> fp16 hi out ----------------
__global__ __launch_bounds__(256) void local_attn(
    const float* __restrict__ qkv, const int* __restrict__ mask,
    hf* __restrict__ outH)
{
    const int  bw   = blockIdx.x;
    const int  h    = blockIdx.y;
    const long tok0 = (long)bw * DW;
    const int  LD   = 3 * DD;
    const float* qb = qkv + tok0 * LD + h * DH_;
    const float* kb = qkv + tok0 * LD + DD + h * DH_;
    const float* vb = qkv + tok0 * LD + 2 * DD + h * DH_;

    __shared__ float s[DW][DW + 1];
    __shared__ float msk[DW];
    const int tid = threadIdx.x;
    if (tid < DW) msk[tid] = (mask[tok0 + tid] != 0) ? 0.f : -1e9f;

    #pragma unroll
    for (int p = tid; p < DW * DW; p += 256) {
        int i = p >> 5, j = p & 31;
        const float4* qp = (const float4*)(qb + (long)i * LD);
        const float4* kp = (const float4*)(kb + (long)j * LD);
        float acc = 0.f;
        #pragma unroll 8
        for (int d = 0; d < DH_ / 4; d++) {
            float4 a = qp[d], c = kp[d];
            acc += a.x * c.x + a.y * c.y + a.z * c.z + a.w * c.w;
        }
        s[i][j] = acc;
    }
    __syncthreads();

    if (tid < DW) {
        const int i = tid;
        const float mi = msk[i];
        float r[DW];
        float mx = -3.4e38f;
        #pragma unroll
        for (int j = 0; j < DW; j++) {
            float bias = (mi + msk[j] < -0.5f) ? -1e9f : 0.f;
            r[j] = s[i][j] * SCL + bias;
            mx = fmaxf(mx, r[j]);
        }
        float sum = 0.f;
        #pragma unroll
        for (int j = 0; j < DW; j++) { r[j] = expf(r[j] - mx); sum += r[j]; }
        const float inv = 1.f / sum;
        #pragma unroll
        for (int j = 0; j < DW; j++) s[i][j] = r[j] * inv;
    }
    __syncthreads();

    float2 acc[DW];
    #pragma unroll
    for (int i = 0; i < DW; i++) acc[i] = make_float2(0.f, 0.f);
    for (int j = 0; j < DW; j++) {
        float2 v2 = *(const float2*)(vb + (long)j * LD + tid * 2);
        #pragma unroll
        for (int i = 0; i < DW; i++) {
            float w = s[i][j];
            acc[i].x += w * v2.x;
            acc[i].y += w * v2.y;
        }
    }
    const long obase = tok0 * DD + h * DH_ + tid * 2;
    #pragma unroll
    for (int i = 0; i < DW; i++) {
        __half2 hv;
        hv.x = __float2half_rn(acc[i].x);
        hv.y = __float2half_rn(acc[i].y);
        *(__half2*)&outH[obase + (long)i * DD] = hv;
    }
}

// ---------------- LayerNorm over rows of 4096 -> fp16 out (Yl optional) ----------------
__global__ __launch_bounds__(256) void layernorm_bf(
    const float* __restrict__ X, const float* __restrict__ g,
    const float* __restrict__ b, hf* __restrict__ Yh, hf* __restrict__ Yl)
{
    const long row = blockIdx.x;
    const float* x = X + row * DD;
    float v[16];
    float s = 0.f;
    #pragma unroll
    for (int i = 0; i < 16; i++) { v[i] = x[threadIdx.x + i * 256]; s += v[i]; }
    const float mean = blockSum(s) * (1.f / DD);
    float d2 = 0.f;
    #pragma unroll
    for (int i = 0; i < 16; i++) { float d = v[i] - mean; d2 += d * d; }
    const float var = blockSum(d2) * (1.f / DD);
    const float rs = rsqrtf(var + 1e-5f);
    #pragma unroll
    for (int i = 0; i < 16; i++) {
        int c = threadIdx.x + i * 256;
        float o = (v[i] - mean) * rs * g[c] + b[c];
        hf h, l; split1(o, h, l);
        Yh[row * DD + c] = h;
        if (Yl) Yl[row * DD + c] = l;
    }
}

// ---------------- global softmax over S=2048 keys -> fp16 hi out ----------------
__global__ __launch_bounds__(256) void softmax_bf(
    const float* __restrict__ sc, const int* __restrict__ mask,
    hf* __restrict__ oh)
{
    const long row = blockIdx.x;
    const int  b   = (int)(row >> 11);
    const float* x = sc + row * DS;
    const int* m = mask + (long)b * DS;
    float v[8];
    float mx = -3.4e38f;
    #pragma unroll
    for (int i = 0; i < 8; i++) {
        int c = threadIdx.x + i * 256;
        float t = x[c] + ((m[c] != 0) ? 0.f : -1e9f);
        v[i] = t;
        mx = fmaxf(mx, t);
    }
    mx = blockMax(mx);
    float s = 0.f;
    #pragma unroll
    for (int i = 0; i < 8; i++) { v[i] = expf(v[i] - mx); s += v[i]; }
    s = blockSum(s);
    const float inv = 1.f / s;
    #pragma unroll
    for (int i = 0; i < 8; i++) {
        int c = threadIdx.x + i * 256;
        oh[row * DS + c] = __float2half_rn(v[i] * inv);
    }
}

// ======================= launch =======================
static void split_full(const float* in, hf* oh, hf* ol, long rows, long cols) {
    long total4 = rows * (cols / 4);
    split_mat<<<(unsigned)((total4 + 255) / 256), 256>>>(in, cols, oh, ol, cols, (int)(cols / 4), total4);
}

extern "C" void kernel_launch(void* const* d_in, const int* in_sizes, int n_in,
                              void* d_out, int out_size)
{
    const float* vlm    = (const float*)d_in[0];
    const int*   mask   = (const int*)d_in[1];
    const float* l_in_w = (const float*)d_in[2];
    const float* l_in_b = (const float*)d_in[3];
    const float* l_out_w= (const float*)d_in[4];
    const float* l_out_b= (const float*)d_in[5];
    const float* l_ng   = (const float*)d_in[6];
    const float* l_nb   = (const float*)d_in[7];
    const float* l_pw   = (const float*)d_in[8];
    const float* l_pb   = (const float*)d_in[9];
    const float* g_in_w = (const float*)d_in[10];
    const float* g_in_b = (const float*)d_in[11];
    const float* g_out_w= (const float*)d_in[12];
    const float* g_out_b= (const float*)d_in[13];
    const float* g_ng   = (const float*)d_in[14];
    const float* g_nb   = (const float*)d_in[15];
    const float* qtok   = (const float*)d_in[16];
    const float* o_pw   = (const float*)d_in[17];
    const float* o_pb   = (const float*)d_in[18];
    float* out = (float*)d_out;

    cudaFuncSetAttribute(gemm_tc<0>, cudaFuncAttributeMaxDynamicSharedMemorySize, GSMEM);
    cudaFuncSetAttribute(gemm_tc<1>, cudaFuncAttributeMaxDynamicSharedMemorySize, GSMEM);

    float *p_qkv, *p_y, *p_sc, *p_yg;
    cudaGetSymbolAddress((void**)&p_qkv, g_qkv);
    cudaGetSymbolAddress((void**)&p_y,   g_y);
    cudaGetSymbolAddress((void**)&p_sc,  g_sc);
    cudaGetSymbolAddress((void**)&p_yg,  g_yg);

    hf *vlm_h,*liw_h,*low_h,*lpw_h,*giw_h,*gow_h,*opw_h,
       *attnl_h,*ln_h,*lf_h,*qtok_h,*qtok_l,
       *qg_h,*kvk_h,*vt_h,*sc_h,*ag_h,*lng_h;
    cudaGetSymbolAddress((void**)&vlm_h, b_vlm_h);
    cudaGetSymbolAddress((void**)&liw_h, b_liw_h);
    cudaGetSymbolAddress((void**)&low_h, b_low_h);
    cudaGetSymbolAddress((void**)&lpw_h, b_lpw_h);
    cudaGetSymbolAddress((void**)&giw_h, b_giw_h);
    cudaGetSymbolAddress((void**)&gow_h, b_gow_h);
    cudaGetSymbolAddress((void**)&opw_h, b_opw_h);
    cudaGetSymbolAddress((void**)&attnl_h, b_attnl_h);
    cudaGetSymbolAddress((void**)&ln_h,  b_ln_h);
    cudaGetSymbolAddress((void**)&lf_h,  b_lf_h);
    cudaGetSymbolAddress((void**)&qtok_h,b_qtok_h);  cudaGetSymbolAddress((void**)&qtok_l,b_qtok_l);
    cudaGetSymbolAddress((void**)&qg_h,  b_qg_h);
    cudaGetSymbolAddress((void**)&kvk_h, b_kvk_h);
    cudaGetSymbolAddress((void**)&vt_h,  b_vt_h);
    cudaGetSymbolAddress((void**)&sc_h,  b_sc_h);
    cudaGetSymbolAddress((void**)&ag_h,  b_ag_h);
    cudaGetSymbolAddress((void**)&lng_h, b_lng_h);

    const dim3 T256(256);
    #define GEMM(UL,Ah,Al,lda,Bh,ldb,C,Oh,Ol,ldc,bias,res,resMod,resLd,K,scale,M,N,kvM,zTot,zInner,aIn,aOut,bIn,bOut,cIn,cOut) \
        gemm_tc<UL><<<dim3(((M)/128)*((N)/128), 1, zTot), T256, GSMEM>>>( \
            Ah, Al, lda, Bh, ldb, C, Oh, Ol, ldc, bias, res, resMod, resLd, \
            K, scale, (M)/128, (N)/128, kvM, zInner, aIn, aOut, bIn, bOut, cIn, cOut)
    #define NOF (const float*)nullptr
    #define NOC (float*)nullptr
    #define NOH (hf*)nullptr

    // input/weight splits (weights + vlm: hi only)
    split_full(vlm,     vlm_h,  NOH,    NTOK,   DD);
    split_full(l_in_w,  liw_h,  NOH,    3*DD,   DD);
    split_full(l_out_w, low_h,  NOH,    DD,     DD);
    split_full(l_pw,    lpw_h,  NOH,    DD,     DD);
    split_full(g_in_w,  giw_h,  NOH,    3*DD,   DD);
    split_full(g_out_w, gow_h,  NOH,    DD,     DD);
    split_full(o_pw,    opw_h,  NOH,    DD,     DD);
    split_full(qtok,    qtok_h, qtok_l, DT,     DD);

    // 1) local QKV (1-product), fp32 out (consumed by local_attn)
    GEMM(0, vlm_h, vlm_h, DD, liw_h, DD, p_qkv, NOH, NOH, 3*DD, l_in_b,
         NOF, 1, 1, DD, 1.f, NTOK, 3*DD, 0, 1, 1, 0,0,0,0,0,0);

    // 2) local windowed attention -> fp16 hi only
    local_attn<<<dim3(DB * (DS / DW), NH), T256>>>(p_qkv, mask, attnl_h);

    // 3) local out_proj + residual(vlm) [1-product], fp32 out (consumed by LN)
    GEMM(0, attnl_h, attnl_h, DD, low_h, DD, p_y, NOH, NOH, DD, l_out_b,
         vlm, NTOK, DD, DD, 1.f, NTOK, DD, 0, 1, 1, 0,0,0,0,0,0);

    // 4) LN local -> fp16 hi only
    layernorm_bf<<<NTOK, T256>>>(p_y, l_ng, l_nb, ln_h, NOH);

    // 5) local_proj -> local_features [1-product], hi-only out
    GEMM(0, ln_h, ln_h, DD, lpw_h, DD, NOC, lf_h, NOH, DD, l_pb,
         NOF, 1, 1, DD, 1.f, NTOK, DD, 0, 1, 1, 0,0,0,0,0,0);

    // 6) global q (batch-invariant) [2-product], hi-only out (scores is 1-product)
    GEMM(1, qtok_h, qtok_l, DD, giw_h, DD, NOC, qg_h, NOH, DD, g_in_b,
         NOF, 1, 1, DD, 1.f, DT, DD, 0, 1, 1, 0,0,0,0,0,0);

    // 7) global k,v (1-product) — fused: K -> kvk_h, V -> vt_h transposed
    GEMM(0, lf_h, lf_h, DD, giw_h + (long)DD*DD, DD,
         NOC, kvk_h, vt_h, DD, g_in_b + DD,
         NOF, 1, 1, DD, 1.f, NTOK, 2*DD, 1, 1, 1, 0,0,0,0,0,0);

    // 8) scores (batched 32): (256 x 2048 x 512) [1-product], scaled, fp32 out
    GEMM(0, qg_h, qg_h, DD, kvk_h, DD, p_sc, NOH, NOH, DS,
         NOF, NOF, 1, 1,
         DH_, SCL, DT, DS, 0, DB*NH, NH,
         /*aIn*/DH_, /*aOut*/0,
         /*bIn*/DH_, /*bOut*/(long)DS * DD,
         /*cIn*/(long)DT * DS, /*cOut*/(long)NH * DT * DS);

    // 9) softmax over keys -> fp16 hi only
    softmax_bf<<<DB * NH * DT, T256>>>(p_sc, mask, sc_h);

    // 10) AV (batched 32): (256 x 512 x 2048) [1-product], hi-only out
    GEMM(0, sc_h, sc_h, DS, vt_h, DS, NOC, ag_h, NOH, DD,
         NOF, NOF, 1, 1,
         DS, 1.f, DT, DH_, 0, DB*NH, NH,
         /*aIn*/(long)DT * DS, /*aOut*/(long)NH * DT * DS,
         /*bIn*/(long)DH_ * DS, /*bOut*/(long)DD * DS,
         /*cIn*/DH_, /*cOut*/(long)DT * DD);

    // 11) global out_proj + residual(query_tokens broadcast) [1-product], fp32 out
    GEMM(0, ag_h, ag_h, DD, gow_h, DD, p_yg, NOH, NOH, DD, g_out_b,
         qtok, DT, DD, DD, 1.f, NQ, DD, 0, 1, 1, 0,0,0,0,0,0);

    // 12) LN global -> fp16 hi only (output_proj is 1-product)
    layernorm_bf<<<NQ, T256>>>(p_yg, g_ng, g_nb, lng_h, NOH);

    // 13) output_proj -> d_out (fp32) [1-product]
    GEMM(0, lng_h, lng_h, DD, opw_h, DD, out, NOH, NOH, DD, o_pb,
         NOF, 1, 1, DD, 1.f, NQ, DD, 0, 1, 1, 0,0,0,0,0,0);
}

// round 14
// speedup vs baseline: 7.1192x; 1.0887x over previous
#include <cuda_runtime.h>
#include <cuda_fp16.h>
#include <cstdint>

// ---------------- problem constants ----------------
// B=4, S=2048, D=4096, T=256, W=32, H=8, DH=512
#define DB   4
#define DS   2048
#define DD   4096
#define DT   256
#define DW   32
#define DH_  512
#define NH   8
#define NTOK (DB*DS)            // 8192
#define NQ   (DB*DT)            // 1024
#define SCL  0.044194173824159216f  // 1/sqrt(512)

typedef __half hf;

// ---------------- device scratch (no allocations allowed) ----------------
// fp16 intermediates (hi-only couriers between kernels)
__device__ __align__(16) hf b_qkv_h [(long)NTOK*3*DD];
__device__ __align__(16) hf b_y_h   [(long)NTOK*DD];
__device__ __align__(16) hf b_scr_h [(long)DB*NH*DT*DS];
__device__ __align__(16) hf b_yg_h  [(long)NQ*DD];
// fp16 split operands
__device__ __align__(16) hf b_vlm_h  [(long)NTOK*DD];
__device__ __align__(16) hf b_liw_h  [(long)3*DD*DD];
__device__ __align__(16) hf b_low_h  [(long)DD*DD];
__device__ __align__(16) hf b_lpw_h  [(long)DD*DD];
__device__ __align__(16) hf b_giw_h  [(long)3*DD*DD];
__device__ __align__(16) hf b_gow_h  [(long)DD*DD];
__device__ __align__(16) hf b_opw_h  [(long)DD*DD];
__device__ __align__(16) hf b_attnl_h[(long)NTOK*DD];
__device__ __align__(16) hf b_ln_h   [(long)NTOK*DD];
__device__ __align__(16) hf b_lf_h   [(long)NTOK*DD];
__device__ __align__(16) hf b_qtok_h [(long)DT*DD],        b_qtok_l [(long)DT*DD];
__device__ __align__(16) hf b_qg_h   [(long)DT*DD];
__device__ __align__(16) hf b_kvk_h  [(long)NTOK*DD];
__device__ __align__(16) hf b_vt_h   [(long)DB*DD*DS];
__device__ __align__(16) hf b_sc_h   [(long)DB*NH*DT*DS];
__device__ __align__(16) hf b_ag_h   [(long)NQ*DD];
__device__ __align__(16) hf b_lng_h  [(long)NQ*DD];

// ======================= helpers =======================
__device__ __forceinline__ uint32_t smem_u32(const void* p) {
    uint32_t a;
    asm("{ .reg .u64 t; cvta.to.shared.u64 t, %1; cvt.u32.u64 %0, t; }" : "=r"(a) : "l"(p));
    return a;
}
__device__ __forceinline__ void cp16(uint32_t dst, const void* src) {
    asm volatile("cp.async.cg.shared.global [%0], [%1], 16;" :: "r"(dst), "l"(src));
}
__device__ __forceinline__ void cp_commit() { asm volatile("cp.async.commit_group;" ::: "memory"); }
template <int N> __device__ __forceinline__ void cp_wait() {
    asm volatile("cp.async.wait_group %0;" :: "n"(N) : "memory");
}
__device__ __forceinline__ void ldsm4(uint32_t* r, uint32_t a) {
    asm volatile("ldmatrix.sync.aligned.m8n8.x4.shared.b16 {%0,%1,%2,%3}, [%4];"
        : "=r"(r[0]), "=r"(r[1]), "=r"(r[2]), "=r"(r[3]) : "r"(a));
}
// D += A*B  (m16n8k16, fp16 in, fp32 acc)
__device__ __forceinline__ void mma16816(float* d, const uint32_t* a, const uint32_t* b) {
    asm volatile(
        "mma.sync.aligned.m16n8k16.row.col.f32.f16.f16.f32 "
        "{%0,%1,%2,%3}, {%4,%5,%6,%7}, {%8,%9}, {%0,%1,%2,%3};"
        : "+f"(d[0]), "+f"(d[1]), "+f"(d[2]), "+f"(d[3])
        : "r"(a[0]), "r"(a[1]), "r"(a[2]), "r"(a[3]), "r"(b[0]), "r"(b[1]));
}
__device__ __forceinline__ void split1(float v, hf& h, hf& l) {
    h = __float2half_rn(v);
    l = __float2half_rn(v - __half2float(h));
}
// XOR swizzle: row pitch 64B, 16B unit c in 0..3; conflict-free 8-row ldmatrix groups
__device__ __forceinline__ uint32_t swz(int r, int c) {
    return (uint32_t)(r * 64 + ((c ^ ((r >> 1) & 3)) << 4));
}

// ======================= fp16 HMMA GEMM (1 or 2 products) =======================
// C(M,N) = scale * (Ah [+Al]) @ Bh^T + bias + res
// 128x128 tile, K-chunk 32, 4-stage cp.async, single __syncthreads/iter, 2 CTAs/SM.
#define GSTG   24576
#define GSMEM  (4*GSTG)
#define OFF_AL 8192u
#define OFF_BH 16384u

template <int USELO>
__device__ __forceinline__ void load_chunk(
    uint32_t sb, int slot, long k0, int tid,
    const hf* __restrict__ Ah, const hf* __restrict__ Al, long lda, long bm,
    const hf* __restrict__ Bh, long ldb, long bn)
{
    uint32_t base = sb + (uint32_t)slot * GSTG;
    #pragma unroll
    for (int it = 0; it < 2; it++) {
        int u = tid + it * 256;
        int r = u >> 2, c = u & 3;
        uint32_t off = swz(r, c);
        long srcA = (bm + r) * lda + k0 + c * 8;
        cp16(base + off, Ah + srcA);
        if (USELO) cp16(base + OFF_AL + off, Al + srcA);
        cp16(base + OFF_BH + off, Bh + (bn + r) * ldb + k0 + c * 8);
    }
    cp_commit();
}

template <int USELO>
__global__ __launch_bounds__(256, 2) void gemm_tc(
    const hf* __restrict__ Ah, const hf* __restrict__ Al, long lda,
    const hf* __restrict__ Bh, long ldb,
    float* __restrict__ C,
    hf* __restrict__ Oh, hf* __restrict__ Ol,
    long ldc,
    const float* __restrict__ bias,
    const float* __restrict__ res, int resMod, long resLd,
    int K, float scale, int nTm, int nTn, int kvMode,
    int zInner, long aIn, long aOut, long bIn, long bOut, long cIn, long cOut)
{
    extern __shared__ __align__(128) char smem[];
    const uint32_t sb = smem_u32(smem);
    const int tid = threadIdx.x;
    const int wid = tid >> 5;
    const int lane = tid & 31;

    const int z = blockIdx.z;
    const int zi = z % zInner, zo = z / zInner;
    Ah += (long)zi * aIn + (long)zo * aOut;  Al += (long)zi * aIn + (long)zo * aOut;
    Bh += (long)zi * bIn + (long)zo * bOut;
    const long coff = (long)zi * cIn + (long)zo * cOut;
    if (C)  C  += coff;
    if (Oh && !kvMode) { Oh += coff; if (Ol) Ol += coff; }

    const int idx = blockIdx.x;
    const int per = nTm * 8;
    const int band = idx / per, rem = idx % per;
    const long bm = (long)(rem % nTm) * 128;
    const long bn = (long)(band * 8 + rem / nTm) * 128;

    const int wm = wid & 3;
    const int wn = wid >> 2;

    const int aRow = wm * 32 + (lane & 15);
    const int aC0  = (lane >> 4);
    const int bRow = wn * 64 + (lane & 7) + ((lane >> 4) & 1) * 8;
    const int bC0  = ((lane >> 3) & 1);

    float acc[2][8][4];
    #pragma unroll
    for (int i = 0; i < 2; i++)
        #pragma unroll
        for (int j = 0; j < 8; j++)
            #pragma unroll
            for (int q = 0; q < 4; q++) acc[i][j][q] = 0.f;

    const int nCh = K >> 5;
    load_chunk<USELO>(sb, 0, 0,  tid, Ah, Al, lda, bm, Bh, ldb, bn);
    load_chunk<USELO>(sb, 1, 32, tid, Ah, Al, lda, bm, Bh, ldb, bn);
    load_chunk<USELO>(sb, 2, 64, tid, Ah, Al, lda, bm, Bh, ldb, bn);

    for (int i = 0; i < nCh; i++) {
        if (i + 2 < nCh)      cp_wait<2>();
        else if (i + 1 < nCh) cp_wait<1>();
        else                  cp_wait<0>();
        __syncthreads();
        if (i + 3 < nCh)
            load_chunk<USELO>(sb, (i + 3) & 3, (long)(i + 3) * 32, tid,
                              Ah, Al, lda, bm, Bh, ldb, bn);
        const uint32_t stg = sb + (uint32_t)(i & 3) * GSTG;
        #pragma unroll
        for (int ks = 0; ks < 2; ks++) {
            uint32_t ah[2][4], al[2][4];
            #pragma unroll
            for (int m = 0; m < 2; m++) {
                uint32_t a = stg + swz(aRow + m * 16, aC0 + ks * 2);
                ldsm4(ah[m], a);
                if (USELO) ldsm4(al[m], a + OFF_AL);
            }
            #pragma unroll
            for (int p = 0; p < 4; p++) {
                uint32_t bh[4];
                ldsm4(bh, stg + OFF_BH + swz(bRow + p * 16, bC0 + ks * 2));
                #pragma unroll
                for (int m = 0; m < 2; m++)
                    #pragma unroll
                    for (int s = 0; s < 2; s++) {
                        const int nt = p * 2 + s;
                        mma16816(acc[m][nt], ah[m], &bh[s * 2]);
                        if (USELO) mma16816(acc[m][nt], al[m], &bh[s * 2]);
                    }
            }
        }
    }

    // ---- epilogue ----
    const int r0 = lane >> 2;
    const int c0 = (lane & 3) * 2;
    const bool isV = kvMode && (bn >= DD);
    #pragma unroll
    for (int m = 0; m < 2; m++) {
        #pragma unroll
        for (int half = 0; half < 2; half++) {
            const long grow = bm + wm * 32 + m * 16 + r0 + half * 8;
            const long rrow = (grow % resMod) * resLd;
            #pragma unroll
            for (int nt = 0; nt < 8; nt++) {
                const long gcol = bn + wn * 64 + nt * 8 + c0;
                float vx = acc[m][nt][half * 2]     * scale;
                float vy = acc[m][nt][half * 2 + 1] * scale;
                if (bias) {
                    float2 bb = *(const float2*)&bias[gcol];
                    vx += bb.x; vy += bb.y;
                }
                if (res) {
                    float2 rr = *(const float2*)&res[rrow + gcol];
                    vx += rr.x; vy += rr.y;
                }
                if (kvMode) {
                    if (!isV) {
                        __half2 hv; hv.x = __float2half_rn(vx); hv.y = __float2half_rn(vy);
                        *(__half2*)&Oh[grow * DD + gcol] = hv;
                    } else {
                        const int d = (int)(gcol - DD);
                        const long b = grow >> 11;
                        const long s = grow & (DS - 1);
                        const long o = (b * DD + d) * DS + s;
                        Ol[o]      = __float2half_rn(vx);
                        Ol[o + DS] = __float2half_rn(vy);
                    }
                } else {
                    if (C) {
                        float2 v; v.x = vx; v.y = vy;
                        *(float2*)&C[grow * ldc + gcol] = v;
                    }
                    if (Oh) {
                        hf hx, lx, hy, ly;
                        split1(vx, hx, lx); split1(vy, hy, ly);
                        __half2 hv; hv.x = hx; hv.y = hy;
                        *(__half2*)&Oh[grow * ldc + gcol] = hv;
                        if (Ol) {
                            __half2 lv; lv.x = lx; lv.y = ly;
                            *(__half2*)&Ol[grow * ldc + gcol] = lv;
                        }
                    }
                }
            }
        }
    }
}

// ======================= split conversions =======================
__global__ __launch_bounds__(256) void split_mat(
    const float* __restrict__ in, long ldIn,
    hf* __restrict__ oh, hf* __restrict__ ol, long ldOut,
    int cols4, long total4)
{
    long idx = (long)blockIdx.x * 256 + threadIdx.x;
    if (idx >= total4) return;
    long r = idx / cols4;
    int  c = (int)(idx - r * cols4);
    float4 v = *(const float4*)(in + r * ldIn + c * 4);
    hf h0, h1, h2, h3, l0, l1, l2, l3;
    split1(v.x, h0, l0); split1(v.y, h1, l1);
    split1(v.z, h2, l2); split1(v.w, h3, l3);
    __half2* ph = (__half2*)(oh + r * ldOut + c * 4);
    __half2 a; a.x = h0; a.y = h1; ph[0] = a;
    a.x = h2; a.y = h3; ph[1] = a;
    if (ol) {
        __half2* pl = (__half2*)(ol + r * ldOut + c * 4);
        a.x = l0; a.y = l1; pl[0] = a;
        a.x = l2; a.y = l3; pl[1] = a;
    }
}

// ======================= reductions =======================
__device__ __forceinline__ float blockSum(float val) {
    __shared__ float sh[32];
    int lane = threadIdx.x & 31, w = threadIdx.x >> 5;
    #pragma unroll
    for (int o = 16; o; o >>= 1) val += __shfl_xor_sync(0xffffffffu, val, o);
    __syncthreads();
    if (lane == 0) sh[w] = val;
    __syncthreads();
    val = (lane < 8) ? sh[lane] : 0.f;
    #pragma unroll
    for (int o = 4; o; o >>= 1) val += __shfl_xor_sync(0xffffffffu, val, o);
    return __shfl_sync(0xffffffffu, val, 0);
}
__device__ __forceinline__ float blockMax(float val) {
    __shared__ float sh[32];
    int lane = threadIdx.x & 31, w = threadIdx.x >> 5;
    #pragma unroll
    for (int o = 16; o; o >>= 1) val = fmaxf(val, __shfl_xor_sync(0xffffffffu, val, o));
    __syncthreads();
    if (lane == 0) sh[w] = val;
    __syncthreads();
    val = (lane < 8) ? sh[lane] : -3.4e38f;
    #pragma unroll
    for (int o = 4; o; o >>= 1) val = fmaxf(val, __shfl_xor_sync(0xffffffffu, val, o));
    return __shfl_sync(0xffffffffu, val, 0);
}

// ---------------- local windowed attention: fp16 qkv -> fp16 hi out ----------------
__global__ __launch_bounds__(256) void local_attn(
    const hf* __restrict__ qkv, const int* __restrict__ mask,
    hf* __restrict__ outH)
{
    const int  bw   = blockIdx.x;
    const int  h    = blockIdx.y;
    const long tok0 = (long)bw * DW;
    const int  LD   = 3 * DD;
    const hf* qb = qkv + tok0 * LD + h * DH_;
    const hf* kb = qkv + tok0 * LD + DD + h * DH_;
    const hf* vb = qkv + tok0 * LD + 2 * DD + h * DH_;

    __shared__ float s[DW][DW + 1];
    __shared__ float msk[DW];
    const int tid = threadIdx.x;
    if (tid < DW) msk[tid] = (mask[tok0 + tid] != 0) ? 0.f : -1e9f;

    #pragma unroll
    for (int p = tid; p < DW * DW; p += 256) {
        int i = p >> 5, j = p & 31;
        const float4* qp = (const float4*)(qb + (long)i * LD);   // 8 halves / float4
        const float4* kp = (const float4*)(kb + (long)j * LD);
        float acc = 0.f;
        #pragma unroll 8
        for (int d = 0; d < DH_ / 8; d++) {
            float4 a4 = qp[d], c4 = kp[d];
            const __half2* ah = (const __half2*)&a4;
            const __half2* ch = (const __half2*)&c4;
            #pragma unroll
            for (int q = 0; q < 4; q++) {
                float2 av = __half22float2(ah[q]);
                float2 cv = __half22float2(ch[q]);
                acc += av.x * cv.x + av.y * cv.y;
            }
        }
        s[i][j] = acc;
    }
    __syncthreads();

    if (tid < DW) {
        const int i = tid;
        const float mi = msk[i];
        float r[DW];
        float mx = -3.4e38f;
        #pragma unroll
        for (int j = 0; j < DW; j++) {
            float bias = (mi + msk[j] < -0.5f) ? -1e9f : 0.f;
            r[j] = s[i][j] * SCL + bias;
            mx = fmaxf(mx, r[j]);
        }
        float sum = 0.f;
        #pragma unroll
        for (int j = 0; j < DW; j++) { r[j] = expf(r[j] - mx); sum += r[j]; }
        const float inv = 1.f / sum;
        #pragma unroll
        for (int j = 0; j < DW; j++) s[i][j] = r[j] * inv;
    }
    __syncthreads();

    float2 acc[DW];
    #pragma unroll
    for (int i = 0; i < DW; i++) acc[i] = make_float2(0.f, 0.f);
    for (int j = 0; j < DW; j++) {
        float2 v2 = __half22float2(*(const __half2*)(vb + (long)j * LD + tid * 2));
        #pragma unroll
        for (int i = 0; i < DW; i++) {
            float w = s[i][j];
            acc[i].x += w * v2.x;
            acc[i].y += w * v2.y;
        }
    }
    const long obase = tok0 * DD + h * DH_ + tid * 2;
    #pragma unroll
    for (int i = 0; i < DW; i++) {
        __half2 hv;
        hv.x = __float2half_rn(acc[i].x);
        hv.y = __float2half_rn(acc[i].y);
        *(__half2*)&outH[obase + (long)i * DD] = hv;
    }
}

// ---------------- LayerNorm over rows of 4096: fp16 in -> fp16 hi out ----------------
__global__ __launch_bounds__(256) void layernorm_hf(
    const hf* __restrict__ X, const float* __restrict__ g,
    const float* __restrict__ b, hf* __restrict__ Yh)
{
    const long row = blockIdx.x;
    const hf* x = X + row * DD;
    float v[16];
    float s = 0.f;
    #pragma unroll
    for (int i = 0; i < 16; i++) {
        v[i] = __half2float(x[threadIdx.x + i * 256]);
        s += v[i];
    }
    const float mean = blockSum(s) * (1.f / DD);
    float d2 = 0.f;
    #pragma unroll
    for (int i = 0; i < 16; i++) { float d = v[i] - mean; d2 += d * d; }
    const float var = blockSum(d2) * (1.f / DD);
    const float rs = rsqrtf(var + 1e-5f);
    #pragma unroll
    for (int i = 0; i < 16; i++) {
        int c = threadIdx.x + i * 256;
        Yh[row * DD + c] = __float2half_rn((v[i] - mean) * rs * g[c] + b[c]);
    }
}

// ---------------- global softmax over S=2048 keys: fp16 in -> fp16 hi out ----------------
__global__ __launch_bounds__(256) void softmax_hf(
    const hf* __restrict__ sc, const int* __restrict__ mask,
    hf* __restrict__ oh)
{
    const long row = blockIdx.x;
    const int  b   = (int)(row >> 11);
    const hf* x = sc + row * DS;
    const int* m = mask + (long)b * DS;
    float v[8];
    float mx = -3.4e38f;
    #pragma unroll
    for (int i = 0; i < 8; i++) {
        int c = threadIdx.x + i * 256;
        float t = __half2float(x[c]) + ((m[c] != 0) ? 0.f : -1e9f);
        v[i] = t;
        mx = fmaxf(mx, t);
    }
    mx = blockMax(mx);
    float s = 0.f;
    #pragma unroll
    for (int i = 0; i < 8; i++) { v[i] = expf(v[i] - mx); s += v[i]; }
    s = blockSum(s);
    const float inv = 1.f / s;
    #pragma unroll
    for (int i = 0; i < 8; i++) {
        int c = threadIdx.x + i * 256;
        oh[row * DS + c] = __float2half_rn(v[i] * inv);
    }
}

// ======================= launch =======================
static void split_full(const float* in, hf* oh, hf* ol, long rows, long cols) {
    long total4 = rows * (cols / 4);
    split_mat<<<(unsigned)((total4 + 255) / 256), 256>>>(in, cols, oh, ol, cols, (int)(cols / 4), total4);
}

extern "C" void kernel_launch(void* const* d_in, const int* in_sizes, int n_in,
                              void* d_out, int out_size)
{
    const float* vlm    = (const float*)d_in[0];
    const int*   mask   = (const int*)d_in[1];
    const float* l_in_w = (const float*)d_in[2];
    const float* l_in_b = (const float*)d_in[3];
    const float* l_out_w= (const float*)d_in[4];
    const float* l_out_b= (const float*)d_in[5];
    const float* l_ng   = (const float*)d_in[6];
    const float* l_nb   = (const float*)d_in[7];
    const float* l_pw   = (const float*)d_in[8];
    const float* l_pb   = (const float*)d_in[9];
    const float* g_in_w = (const float*)d_in[10];
    const float* g_in_b = (const float*)d_in[11];
    const float* g_out_w= (const float*)d_in[12];
    const float* g_out_b= (const float*)d_in[13];
    const float* g_ng   = (const float*)d_in[14];
    const float* g_nb   = (const float*)d_in[15];
    const float* qtok   = (const float*)d_in[16];
    const float* o_pw   = (const float*)d_in[17];
    const float* o_pb   = (const float*)d_in[18];
    float* out = (float*)d_out;

    cudaFuncSetAttribute(gemm_tc<0>, cudaFuncAttributeMaxDynamicSharedMemorySize, GSMEM);
    cudaFuncSetAttribute(gemm_tc<1>, cudaFuncAttributeMaxDynamicSharedMemorySize, GSMEM);

    hf *qkv_h,*y_h,*scr_h,*yg_h,
       *vlm_h,*liw_h,*low_h,*lpw_h,*giw_h,*gow_h,*opw_h,
       *attnl_h,*ln_h,*lf_h,*qtok_h,*qtok_l,
       *qg_h,*kvk_h,*vt_h,*sc_h,*ag_h,*lng_h;
    cudaGetSymbolAddress((void**)&qkv_h, b_qkv_h);
    cudaGetSymbolAddress((void**)&y_h,   b_y_h);
    cudaGetSymbolAddress((void**)&scr_h, b_scr_h);
    cudaGetSymbolAddress((void**)&yg_h,  b_yg_h);
    cudaGetSymbolAddress((void**)&vlm_h, b_vlm_h);
    cudaGetSymbolAddress((void**)&liw_h, b_liw_h);
    cudaGetSymbolAddress((void**)&low_h, b_low_h);
    cudaGetSymbolAddress((void**)&lpw_h, b_lpw_h);
    cudaGetSymbolAddress((void**)&giw_h, b_giw_h);
    cudaGetSymbolAddress((void**)&gow_h, b_gow_h);
    cudaGetSymbolAddress((void**)&opw_h, b_opw_h);
    cudaGetSymbolAddress((void**)&attnl_h, b_attnl_h);
    cudaGetSymbolAddress((void**)&ln_h,  b_ln_h);
    cudaGetSymbolAddress((void**)&lf_h,  b_lf_h);
    cudaGetSymbolAddress((void**)&qtok_h,b_qtok_h);  cudaGetSymbolAddress((void**)&qtok_l,b_qtok_l);
    cudaGetSymbolAddress((void**)&qg_h,  b_qg_h);
    cudaGetSymbolAddress((void**)&kvk_h, b_kvk_h);
    cudaGetSymbolAddress((void**)&vt_h,  b_vt_h);
    cudaGetSymbolAddress((void**)&sc_h,  b_sc_h);
    cudaGetSymbolAddress((void**)&ag_h,  b_ag_h);
    cudaGetSymbolAddress((void**)&lng_h, b_lng_h);

    const dim3 T256(256);
    #define GEMM(UL,Ah,Al,lda,Bh,ldb,C,Oh,Ol,ldc,bias,res,resMod,resLd,K,scale,M,N,kvM,zTot,zInner,aIn,aOut,bIn,bOut,cIn,cOut) \
        gemm_tc<UL><<<dim3(((M)/128)*((N)/128), 1, zTot), T256, GSMEM>>>( \
            Ah, Al, lda, Bh, ldb, C, Oh, Ol, ldc, bias, res, resMod, resLd, \
            K, scale, (M)/128, (N)/128, kvM, zInner, aIn, aOut, bIn, bOut, cIn, cOut)
    #define NOF (const float*)nullptr
    #define NOC (float*)nullptr
    #define NOH (hf*)nullptr

    // input/weight splits (weights + vlm: hi only)
    split_full(vlm,     vlm_h,  NOH,    NTOK,   DD);
    split_full(l_in_w,  liw_h,  NOH,    3*DD,   DD);
    split_full(l_out_w, low_h,  NOH,    DD,     DD);
    split_full(l_pw,    lpw_h,  NOH,    DD,     DD);
    split_full(g_in_w,  giw_h,  NOH,    3*DD,   DD);
    split_full(g_out_w, gow_h,  NOH,    DD,     DD);
    split_full(o_pw,    opw_h,  NOH,    DD,     DD);
    split_full(qtok,    qtok_h, qtok_l, DT,     DD);

    // 1) local QKV (1-product), fp16 hi out (consumed by local_attn)
    GEMM(0, vlm_h, vlm_h, DD, liw_h, DD, NOC, qkv_h, NOH, 3*DD, l_in_b,
         NOF, 1, 1, DD, 1.f, NTOK, 3*DD, 0, 1, 1, 0,0,0,0,0,0);

    // 2) local windowed attention (fp16 in) -> fp16 hi out
    local_attn<<<dim3(DB * (DS / DW), NH), T256>>>(qkv_h, mask, attnl_h);

    // 3) local out_proj + residual(vlm) [1-product], fp16 hi out (consumed by LN)
    GEMM(0, attnl_h, attnl_h, DD, low_h, DD, NOC, y_h, NOH, DD, l_out_b,
         vlm, NTOK, DD, DD, 1.f, NTOK, DD, 0, 1, 1, 0,0,0,0,0,0);

    // 4) LN local (fp16 in) -> fp16 hi out
    layernorm_hf<<<NTOK, T256>>>(y_h, l_ng, l_nb, ln_h);

    // 5) local_proj -> local_features [1-product], hi-only out
    GEMM(0, ln_h, ln_h, DD, lpw_h, DD, NOC, lf_h, NOH, DD, l_pb,
         NOF, 1, 1, DD, 1.f, NTOK, DD, 0, 1, 1, 0,0,0,0,0,0);

    // 6) global q (batch-invariant) [2-product], hi-only out
    GEMM(1, qtok_h, qtok_l, DD, giw_h, DD, NOC, qg_h, NOH, DD, g_in_b,
         NOF, 1, 1, DD, 1.f, DT, DD, 0, 1, 1, 0,0,0,0,0,0);

    // 7) global k,v (1-product) — fused: K -> kvk_h, V -> vt_h transposed
    GEMM(0, lf_h, lf_h, DD, giw_h + (long)DD*DD, DD,
         NOC, kvk_h, vt_h, DD, g_in_b + DD,
         NOF, 1, 1, DD, 1.f, NTOK, 2*DD, 1, 1, 1, 0,0,0,0,0,0);

    // 8) scores (batched 32) [1-product], scaled, fp16 hi out
    GEMM(0, qg_h, qg_h, DD, kvk_h, DD, NOC, scr_h, NOH, DS,
         NOF, NOF, 1, 1,
         DH_, SCL, DT, DS, 0, DB*NH, NH,
         /*aIn*/DH_, /*aOut*/0,
         /*bIn*/DH_, /*bOut*/(long)DS * DD,
         /*cIn*/(long)DT * DS, /*cOut*/(long)NH * DT * DS);

    // 9) softmax over keys (fp16 in) -> fp16 hi out
    softmax_hf<<<DB * NH * DT, T256>>>(scr_h, mask, sc_h);

    // 10) AV (batched 32) [1-product], hi-only out
    GEMM(0, sc_h, sc_h, DS, vt_h, DS, NOC, ag_h, NOH, DD,
         NOF, NOF, 1, 1,
         DS, 1.f, DT, DH_, 0, DB*NH, NH,
         /*aIn*/(long)DT * DS, /*aOut*/(long)NH * DT * DS,
         /*bIn*/(long)DH_ * DS, /*bOut*/(long)DD * DS,
         /*cIn*/DH_, /*cOut*/(long)DT * DD);

    // 11) global out_proj + residual(query_tokens broadcast) [1-product], fp16 hi out
    GEMM(0, ag_h, ag_h, DD, gow_h, DD, NOC, yg_h, NOH, DD, g_out_b,
         qtok, DT, DD, DD, 1.f, NQ, DD, 0, 1, 1, 0,0,0,0,0,0);

    // 12) LN global (fp16 in) -> fp16 hi out
    layernorm_hf<<<NQ, T256>>>(yg_h, g_ng, g_nb, lng_h);

    // 13) output_proj -> d_out (fp32) [1-product]
    GEMM(0, lng_h, lng_h, DD, opw_h, DD, out, NOH, NOH, DD, o_pb,
         NOF, 1, 1, DD, 1.f, NQ, DD, 0, 1, 1, 0,0,0,0,0,0);
}